// round 8
// baseline (speedup 1.0000x reference)
#include <cuda_runtime.h>
#include <cuda_bf16.h>
#include <cstdint>

// ---------------------------------------------------------------------------
// Problem constants
// ---------------------------------------------------------------------------
#define BB 4
#define CC 2048
#define EE 1024
#define HH 16
#define DD 64
#define MM (BB * CC)          // 8192 rows
#define FF (4 * EE)           // 4096 mlp hidden
#define KVS 2048              // fused K|V row stride

// ---------------------------------------------------------------------------
// Scratch
// ---------------------------------------------------------------------------
#define MB (1ull << 20)
__device__ __align__(256) unsigned char g_scratch[364 * MB];

#define OFF_NH    (0 * MB)
#define OFF_NL    (16 * MB)
#define OFF_HH    (32 * MB)
#define OFF_HL    (48 * MB)
#define OFF_QH    (64 * MB)
#define OFF_QL    (80 * MB)
#define OFF_KVH   (96 * MB)     // [MM, 2048] bf16  (K cols 0-1023, V 1024-2047)
#define OFF_KVL   (128 * MB)
#define OFF_OUTB  (160 * MB)
#define OFF_M1H   (192 * MB)
#define OFF_M1L   (256 * MB)
#define OFF_WQH   (320 * MB)
#define OFF_WQL   (322 * MB)
#define OFF_WKVH  (324 * MB)    // [2048, 1024] bf16
#define OFF_WKVL  (328 * MB)
#define OFF_W1H   (332 * MB)
#define OFF_W1L   (340 * MB)
#define OFF_W2H   (348 * MB)
#define OFF_W2L   (356 * MB)

// ---------------------------------------------------------------------------
// PTX helpers (baseline compute_103 only — no 'a' features)
// ---------------------------------------------------------------------------
__device__ __forceinline__ uint32_t smem_u32(const void* p) {
    uint32_t a;
    asm("{ .reg .u64 t; cvta.to.shared.u64 t, %1; cvt.u32.u64 %0, t; }"
        : "=r"(a) : "l"(p));
    return a;
}
__device__ __forceinline__ void cpa16(uint32_t d, const void* s) {
    asm volatile("cp.async.cg.shared.global [%0], [%1], 16;" :: "r"(d), "l"(s));
}
#define CP_COMMIT() asm volatile("cp.async.commit_group;" ::: "memory")

__device__ __forceinline__ void ldsm4(uint32_t* r, uint32_t addr) {
    asm volatile("ldmatrix.sync.aligned.m8n8.x4.shared.b16 {%0,%1,%2,%3}, [%4];"
                 : "=r"(r[0]), "=r"(r[1]), "=r"(r[2]), "=r"(r[3]) : "r"(addr));
}
__device__ __forceinline__ void ldsm4t(uint32_t* r, uint32_t addr) {
    asm volatile("ldmatrix.sync.aligned.m8n8.x4.trans.shared.b16 {%0,%1,%2,%3}, [%4];"
                 : "=r"(r[0]), "=r"(r[1]), "=r"(r[2]), "=r"(r[3]) : "r"(addr));
}
__device__ __forceinline__ void mma16816(float* c, const uint32_t* a,
                                         const uint32_t* b) {
    asm volatile(
        "mma.sync.aligned.m16n8k16.row.col.f32.bf16.bf16.f32 "
        "{%0,%1,%2,%3}, {%4,%5,%6,%7}, {%8,%9}, {%0,%1,%2,%3};"
        : "+f"(c[0]), "+f"(c[1]), "+f"(c[2]), "+f"(c[3])
        : "r"(a[0]), "r"(a[1]), "r"(a[2]), "r"(a[3]), "r"(b[0]), "r"(b[1]));
}

__device__ __forceinline__ void split2(float a, float b, uint32_t& hi, uint32_t& lo) {
    const __nv_bfloat16 ha = __float2bfloat16(a), hb = __float2bfloat16(b);
    __nv_bfloat162 th = __halves2bfloat162(ha, hb);
    hi = *reinterpret_cast<uint32_t*>(&th);
    const float ra = a - __bfloat162float(ha);
    const float rb = b - __bfloat162float(hb);
    __nv_bfloat162 tl = __halves2bfloat162(__float2bfloat16(ra), __float2bfloat16(rb));
    lo = *reinterpret_cast<uint32_t*>(&tl);
}

// ---------------------------------------------------------------------------
// Weight transpose + bf16 hi/lo split:  W[K,N] fp32  ->  Th/Tl [N,K] bf16
// ---------------------------------------------------------------------------
__global__ __launch_bounds__(256) void tsplit_kernel(
    const float* __restrict__ W, __nv_bfloat16* __restrict__ Th,
    __nv_bfloat16* __restrict__ Tl, int K, int N)
{
    __shared__ float t[32][33];
    const int n0 = blockIdx.x * 32, k0 = blockIdx.y * 32;
    const int tx = threadIdx.x & 31, ty = threadIdx.x >> 5;
    #pragma unroll
    for (int j = 0; j < 32; j += 8)
        t[ty + j][tx] = W[(size_t)(k0 + ty + j) * N + n0 + tx];
    __syncthreads();
    #pragma unroll
    for (int j = 0; j < 32; j += 8) {
        const float v = t[tx][ty + j];
        const __nv_bfloat16 h = __float2bfloat16(v);
        const __nv_bfloat16 l = __float2bfloat16(v - __bfloat162float(h));
        const size_t o = (size_t)(n0 + ty + j) * K + k0 + tx;
        Th[o] = h; Tl[o] = l;
    }
}

// ---------------------------------------------------------------------------
// LayerNorm -> bf16 hi/lo
// ---------------------------------------------------------------------------
__global__ __launch_bounds__(256) void ln_kernel(
    const float* __restrict__ x, const float* __restrict__ gamma,
    const float* __restrict__ beta, __nv_bfloat16* __restrict__ yh,
    __nv_bfloat16* __restrict__ yl)
{
    const int row = blockIdx.x;
    const int t = threadIdx.x;
    const float4 v = ((const float4*)(x + (size_t)row * EE))[t];
    float s  = v.x + v.y + v.z + v.w;
    float s2 = fmaf(v.x, v.x, fmaf(v.y, v.y, fmaf(v.z, v.z, v.w * v.w)));
    #pragma unroll
    for (int o = 16; o > 0; o >>= 1) {
        s  += __shfl_xor_sync(0xffffffffu, s, o);
        s2 += __shfl_xor_sync(0xffffffffu, s2, o);
    }
    __shared__ float rs[8], rs2[8];
    __shared__ float sstat[2];
    if ((t & 31) == 0) { rs[t >> 5] = s; rs2[t >> 5] = s2; }
    __syncthreads();
    if (t == 0) {
        float S = 0.f, S2 = 0.f;
        #pragma unroll
        for (int w = 0; w < 8; w++) { S += rs[w]; S2 += rs2[w]; }
        const float mean = S * (1.0f / EE);
        const float var  = S2 * (1.0f / EE) - mean * mean;
        sstat[0] = mean;
        sstat[1] = rsqrtf(var + 1e-5f);
    }
    __syncthreads();
    const float mean = sstat[0], rstd = sstat[1];
    const float4 gv = ((const float4*)gamma)[t];
    const float4 bv = ((const float4*)beta)[t];
    float o0 = (v.x - mean) * rstd * gv.x + bv.x;
    float o1 = (v.y - mean) * rstd * gv.y + bv.y;
    float o2 = (v.z - mean) * rstd * gv.z + bv.z;
    float o3 = (v.w - mean) * rstd * gv.w + bv.w;
    uint32_t h0, l0, h1, l1;
    split2(o0, o1, h0, l0);
    split2(o2, o3, h1, l1);
    uint32_t* ph = (uint32_t*)(yh + (size_t)row * EE + 4 * t);
    uint32_t* pl = (uint32_t*)(yl + (size_t)row * EE + 4 * t);
    ph[0] = h0; ph[1] = h1;
    pl[0] = l0; pl[1] = l1;
}

// ---------------------------------------------------------------------------
// mma.sync bf16x3 GEMM v2: CTA tile 128x64, warp tile 32x32 (8 warps, 4x2),
// K-chunk 32, 3-stage cp.async, single barrier per chunk, register
// double-buffered fragments, 2 CTAs/SM.
// ---------------------------------------------------------------------------
#define GROWB 80u
#define GMATA 10240u             // A: 128 rows * 80B
#define GMATB 5120u              // B: 64 rows * 80B
#define GSTG  30720u             // Ah | Al | Bh | Bl
#define GOFF_AL 10240u
#define GOFF_BH 20480u
#define GOFF_BL 25600u
#define GSM_BYTES (3 * 30720)    // 92160

__global__ __launch_bounds__(256, 2) void gemm_tc(
    const __nv_bfloat16* __restrict__ Ah, const __nv_bfloat16* __restrict__ Al,
    const __nv_bfloat16* __restrict__ Bh, const __nv_bfloat16* __restrict__ Bl,
    const float* __restrict__ bias, const float* __restrict__ bias2, int nsplit,
    const float* __restrict__ res,
    float* __restrict__ Cf, __nv_bfloat16* __restrict__ Ch,
    __nv_bfloat16* __restrict__ Cl, int M, int N, int K, int relu, float oscale)
{
    extern __shared__ unsigned char smem[];
    const uint32_t sbase = smem_u32(smem);
    const int tid = threadIdx.x;
    const int lane = tid & 31, wid = tid >> 5;
    const int wm = wid >> 1, wn = wid & 1;          // 4 x 2 warp grid
    const int row0 = blockIdx.y * 128, col0 = blockIdx.x * 64;

    const __nv_bfloat16* gAh = Ah + (size_t)row0 * K;
    const __nv_bfloat16* gAl = Al + (size_t)row0 * K;
    const __nv_bfloat16* gBh = Bh + (size_t)col0 * K;
    const __nv_bfloat16* gBl = Bl + (size_t)col0 * K;
    const int nch = K >> 5;

    float acc[2][4][4];
    #pragma unroll
    for (int a = 0; a < 2; a++)
        #pragma unroll
        for (int b = 0; b < 4; b++)
            #pragma unroll
            for (int c = 0; c < 4; c++) acc[a][b][c] = 0.f;

    // ldmatrix lane addressing (within matrix, before k-step/row-tile offsets)
    const uint32_t a_base = (uint32_t)(wm * 32 + (lane & 15)) * GROWB +
                            (((lane >> 4) << 3) << 1);
    const uint32_t b_base = (uint32_t)(wn * 32 + ((lane >> 4) << 3) + (lane & 7)) * GROWB +
                            ((((lane >> 3) & 1) << 3) << 1);

    // 6 cp.async per thread per chunk: A hi 2, A lo 2, B hi 1, B lo 1
    auto load_chunk = [&](int ch, int s) {
        const int k0 = ch << 5;
        const uint32_t st = sbase + (uint32_t)s * GSTG;
        #pragma unroll
        for (int i = 0; i < 2; i++) {
            const int idx = i * 256 + tid;
            const int r = idx >> 2, g = idx & 3;
            const uint32_t d = st + (uint32_t)r * GROWB + g * 16u;
            const size_t so = (size_t)r * K + k0 + g * 8;
            cpa16(d, gAh + so);
            cpa16(d + GOFF_AL, gAl + so);
        }
        {
            const int r = tid >> 2, g = tid & 3;
            const uint32_t d = st + (uint32_t)r * GROWB + g * 16u;
            const size_t so = (size_t)r * K + k0 + g * 8;
            cpa16(d + GOFF_BH, gBh + so);
            cpa16(d + GOFF_BL, gBl + so);
        }
    };

    // fragment buffers: [buf][tile][4]
    uint32_t aHf[2][2][4], aLf[2][2][4], bHf[2][2][4], bLf[2][2][4];

    auto ldfrags = [&](int buf, uint32_t st, int ks) {
        const uint32_t ao = a_base + (ks << 5);       // ks*32 bytes
        const uint32_t bo = b_base + (ks << 5);
        #pragma unroll
        for (int mi = 0; mi < 2; mi++) {
            ldsm4(aHf[buf][mi], st + ao + (uint32_t)mi * 16 * GROWB);
            ldsm4(aLf[buf][mi], st + GOFF_AL + ao + (uint32_t)mi * 16 * GROWB);
        }
        #pragma unroll
        for (int p = 0; p < 2; p++) {
            ldsm4(bHf[buf][p], st + GOFF_BH + bo + (uint32_t)p * 16 * GROWB);
            ldsm4(bLf[buf][p], st + GOFF_BL + bo + (uint32_t)p * 16 * GROWB);
        }
    };

    auto do_mmas = [&](int buf) {
        #pragma unroll
        for (int mi = 0; mi < 2; mi++)
            #pragma unroll
            for (int p = 0; p < 2; p++)
                #pragma unroll
                for (int h = 0; h < 2; h++)
                    mma16816(acc[mi][p * 2 + h], aHf[buf][mi], &bHf[buf][p][h * 2]);
        #pragma unroll
        for (int mi = 0; mi < 2; mi++)
            #pragma unroll
            for (int p = 0; p < 2; p++)
                #pragma unroll
                for (int h = 0; h < 2; h++)
                    mma16816(acc[mi][p * 2 + h], aHf[buf][mi], &bLf[buf][p][h * 2]);
        #pragma unroll
        for (int mi = 0; mi < 2; mi++)
            #pragma unroll
            for (int p = 0; p < 2; p++)
                #pragma unroll
                for (int h = 0; h < 2; h++)
                    mma16816(acc[mi][p * 2 + h], aLf[buf][mi], &bHf[buf][p][h * 2]);
    };

    // prologue: preload chunks 0 and 1
    load_chunk(0, 0); CP_COMMIT();
    if (nch > 1) { load_chunk(1, 1); CP_COMMIT(); }

    for (int ch = 0; ch < nch; ch++) {
        asm volatile("cp.async.wait_group 1;" ::: "memory");
        __syncthreads();
        // issue loads for ch+2 into the slot freed at iter ch-1, BEFORE compute
        if (ch + 2 < nch) {
            load_chunk(ch + 2, (ch + 2) % 3);
            CP_COMMIT();
        } else {
            CP_COMMIT();   // keep group accounting uniform
        }
        const uint32_t st = sbase + (uint32_t)(ch % 3) * GSTG;
        ldfrags(0, st, 0);
        ldfrags(1, st, 1);        // second ks buffered; ptxas interleaves w/ MMAs
        do_mmas(0);
        do_mmas(1);
    }
    asm volatile("cp.async.wait_group 0;" ::: "memory");

    // ---------------- epilogue ----------------
    const float* effb = (bias2 && col0 >= nsplit) ? (bias2 - nsplit) : bias;
    const int tr = lane >> 2, tc = (lane & 3) << 1;
    #pragma unroll
    for (int mi = 0; mi < 2; mi++) {
        #pragma unroll
        for (int ni = 0; ni < 4; ni++) {
            const int col = col0 + wn * 32 + ni * 8 + tc;
            const float2 bb = *(const float2*)&effb[col];
            #pragma unroll
            for (int hr = 0; hr < 2; hr++) {
                const int row = row0 + wm * 32 + mi * 16 + tr + hr * 8;
                float v0 = acc[mi][ni][hr * 2 + 0] + bb.x;
                float v1 = acc[mi][ni][hr * 2 + 1] + bb.y;
                if (relu) { v0 = fmaxf(v0, 0.f); v1 = fmaxf(v1, 0.f); }
                v0 *= oscale; v1 *= oscale;
                const size_t goff = (size_t)row * N + col;
                if (Cf) {
                    if (res) {
                        const float2 rv = *(const float2*)&res[goff];
                        v0 += rv.x; v1 += rv.y;
                    }
                    *(float2*)&Cf[goff] = make_float2(v0, v1);
                } else {
                    uint32_t hp, lp;
                    split2(v0, v1, hp, lp);
                    *(uint32_t*)&Ch[goff] = hp;
                    *(uint32_t*)&Cl[goff] = lp;
                }
            }
        }
    }
}

// ---------------------------------------------------------------------------
// Tensor-core flash attention (causal), bf16x3 precision.
// BM=128, BN=64, 256 threads (8 warps, warp tile 16x64). Q pre-scaled 1/8.
// ---------------------------------------------------------------------------
#define AR 144u                   // bytes per smem row (64 bf16 + 8 pad)
#define AQMAT 18432u              // 128 rows * 144B
#define AKMAT 9216u               // 64 rows * 144B
#define ASTG (4 * AKMAT)          // Kh,Kl,Vh,Vl per stage = 36864
#define ATTN_SMEM (2 * AQMAT + 2 * ASTG)   // 110592

__global__ __launch_bounds__(256) void attn_mma(
    const __nv_bfloat16* __restrict__ Qh, const __nv_bfloat16* __restrict__ Ql,
    const __nv_bfloat16* __restrict__ KVh, const __nv_bfloat16* __restrict__ KVl,
    const float* __restrict__ inp, float* __restrict__ Out)
{
    extern __shared__ unsigned char smem[];
    const uint32_t sbase = smem_u32(smem);
    const int tid = threadIdx.x, lane = tid & 31, w = tid >> 5;
    const int qt = blockIdx.x, h = blockIdx.y, b = blockIdx.z;
    const int q0 = qt * 128;
    const int nt = 2 * qt + 2;                 // kv tiles (64 rows each)

    // ---- load Q tile (128 rows, hi+lo) ----
    {
        const size_t ro = (size_t)(b * CC + q0) * EE + (size_t)h * 64;
        #pragma unroll
        for (int i = 0; i < 4; i++) {
            const int idx = i * 256 + tid;
            const int r = idx >> 3, g = idx & 7;
            const uint32_t d = sbase + (uint32_t)r * AR + g * 16u;
            const size_t so = ro + (size_t)r * EE + g * 8;
            cpa16(d, Qh + so);
            cpa16(d + AQMAT, Ql + so);
        }
    }
    CP_COMMIT();

    const size_t kvbase = (size_t)(b * CC) * KVS + (size_t)h * 64;
    auto load_kv = [&](int t, int s) {
        const uint32_t st = sbase + 2 * AQMAT + (uint32_t)s * ASTG;
        const size_t ro = kvbase + (size_t)(t * 64) * KVS;
        #pragma unroll
        for (int i = 0; i < 2; i++) {
            const int idx = i * 256 + tid;
            const int r = idx >> 3, g = idx & 7;
            const uint32_t d = st + (uint32_t)r * AR + g * 16u;
            const size_t so = ro + (size_t)r * KVS + g * 8;
            cpa16(d, KVh + so);
            cpa16(d + AKMAT, KVl + so);
            cpa16(d + 2 * AKMAT, KVh + so + 1024);
            cpa16(d + 3 * AKMAT, KVl + so + 1024);
        }
    };
    load_kv(0, 0); CP_COMMIT();

    float O[8][4];
    #pragma unroll
    for (int n = 0; n < 8; n++)
        #pragma unroll
        for (int j = 0; j < 4; j++) O[n][j] = 0.f;
    float m_lo = -1e30f, m_hi = -1e30f, l_lo = 0.f, l_hi = 0.f;
    uint32_t qHf[4][4], qLf[4][4];

    const int rowl = w * 16 + (lane >> 2);     // local q row (lo); hi = +8
    const int c0 = (lane & 3) << 1;

    for (int t = 0; t < nt; t++) {
        if (t + 1 < nt) load_kv(t + 1, (t + 1) & 1);
        CP_COMMIT();
        asm volatile("cp.async.wait_group 1;" ::: "memory");
        __syncthreads();

        const uint32_t sK = sbase + 2 * AQMAT + (uint32_t)(t & 1) * ASTG;
        const uint32_t sV = sK + 2 * AKMAT;

        if (t == 0) {
            const uint32_t qa = sbase + (uint32_t)(w * 16 + (lane & 15)) * AR +
                                (((lane >> 4) << 3) << 1);
            #pragma unroll
            for (int ks = 0; ks < 4; ks++) {
                ldsm4(qHf[ks], qa + ks * 32);
                ldsm4(qLf[ks], qa + AQMAT + ks * 32);
            }
        }

        // ---- S = Q @ K^T (3-pass, np-paired pass-outer) ----
        float S[8][4];
        #pragma unroll
        for (int n = 0; n < 8; n++)
            #pragma unroll
            for (int j = 0; j < 4; j++) S[n][j] = 0.f;

        #pragma unroll
        for (int ks = 0; ks < 4; ks++) {
            #pragma unroll
            for (int np = 0; np < 4; np += 2) {
                const uint32_t kb0 = sK +
                    (uint32_t)(np * 16 + ((lane >> 4) << 3) + (lane & 7)) * AR +
                    ((((lane >> 3) & 1) << 3) << 1) + ks * 32;
                const uint32_t kb1 = kb0 + 16 * AR;
                uint32_t bh0[4], bl0[4], bh1[4], bl1[4];
                ldsm4(bh0, kb0); ldsm4(bl0, kb0 + AKMAT);
                ldsm4(bh1, kb1); ldsm4(bl1, kb1 + AKMAT);
                #pragma unroll
                for (int h2 = 0; h2 < 2; h2++) {
                    mma16816(S[np * 2 + h2],       qHf[ks], &bh0[h2 * 2]);
                    mma16816(S[(np + 1) * 2 + h2], qHf[ks], &bh1[h2 * 2]);
                }
                #pragma unroll
                for (int h2 = 0; h2 < 2; h2++) {
                    mma16816(S[np * 2 + h2],       qHf[ks], &bl0[h2 * 2]);
                    mma16816(S[(np + 1) * 2 + h2], qHf[ks], &bl1[h2 * 2]);
                }
                #pragma unroll
                for (int h2 = 0; h2 < 2; h2++) {
                    mma16816(S[np * 2 + h2],       qLf[ks], &bh0[h2 * 2]);
                    mma16816(S[(np + 1) * 2 + h2], qLf[ks], &bh1[h2 * 2]);
                }
            }
        }

        // ---- causal mask (only tiles overlapping/above the diagonal) ----
        if (t >= 2 * qt) {
            const int colg0 = t * 64;
            const int rg_lo = q0 + rowl, rg_hi = rg_lo + 8;
            #pragma unroll
            for (int n = 0; n < 8; n++) {
                const int col = colg0 + n * 8 + c0;
                if (col > rg_lo)     S[n][0] = -1e30f;
                if (col + 1 > rg_lo) S[n][1] = -1e30f;
                if (col > rg_hi)     S[n][2] = -1e30f;
                if (col + 1 > rg_hi) S[n][3] = -1e30f;
            }
        }

        // ---- online softmax ----
        float mx0 = -1e30f, mx1 = -1e30f;
        #pragma unroll
        for (int n = 0; n < 8; n++) {
            mx0 = fmaxf(mx0, fmaxf(S[n][0], S[n][1]));
            mx1 = fmaxf(mx1, fmaxf(S[n][2], S[n][3]));
        }
        mx0 = fmaxf(mx0, __shfl_xor_sync(0xffffffffu, mx0, 1));
        mx0 = fmaxf(mx0, __shfl_xor_sync(0xffffffffu, mx0, 2));
        mx1 = fmaxf(mx1, __shfl_xor_sync(0xffffffffu, mx1, 1));
        mx1 = fmaxf(mx1, __shfl_xor_sync(0xffffffffu, mx1, 2));
        const float mn0 = fmaxf(m_lo, mx0), mn1 = fmaxf(m_hi, mx1);
        const float cr0 = __expf(m_lo - mn0), cr1 = __expf(m_hi - mn1);
        float s0 = 0.f, s1 = 0.f;
        #pragma unroll
        for (int n = 0; n < 8; n++) {
            S[n][0] = __expf(S[n][0] - mn0); s0 += S[n][0];
            S[n][1] = __expf(S[n][1] - mn0); s0 += S[n][1];
            S[n][2] = __expf(S[n][2] - mn1); s1 += S[n][2];
            S[n][3] = __expf(S[n][3] - mn1); s1 += S[n][3];
        }
        s0 += __shfl_xor_sync(0xffffffffu, s0, 1);
        s0 += __shfl_xor_sync(0xffffffffu, s0, 2);
        s1 += __shfl_xor_sync(0xffffffffu, s1, 1);
        s1 += __shfl_xor_sync(0xffffffffu, s1, 2);
        l_lo = l_lo * cr0 + s0; l_hi = l_hi * cr1 + s1;
        m_lo = mn0; m_hi = mn1;
        #pragma unroll
        for (int n = 0; n < 8; n++) {
            O[n][0] *= cr0; O[n][1] *= cr0;
            O[n][2] *= cr1; O[n][3] *= cr1;
        }

        // ---- P -> bf16 hi/lo A-fragments (C-frag reuse) ----
        uint32_t pH[4][4], pL[4][4];
        #pragma unroll
        for (int kk = 0; kk < 4; kk++) {
            split2(S[2 * kk][0],     S[2 * kk][1],     pH[kk][0], pL[kk][0]);
            split2(S[2 * kk][2],     S[2 * kk][3],     pH[kk][1], pL[kk][1]);
            split2(S[2 * kk + 1][0], S[2 * kk + 1][1], pH[kk][2], pL[kk][2]);
            split2(S[2 * kk + 1][2], S[2 * kk + 1][3], pH[kk][3], pL[kk][3]);
        }

        // ---- O += P @ V (3-pass, np-paired pass-outer, ldmatrix.trans) ----
        #pragma unroll
        for (int kk = 0; kk < 4; kk++) {
            #pragma unroll
            for (int np = 0; np < 4; np += 2) {
                const uint32_t va0 = sV +
                    (uint32_t)(kk * 16 + ((lane >> 3) & 1) * 8 + (lane & 7)) * AR +
                    ((np * 16 + ((lane >> 4) << 3)) << 1);
                const uint32_t va1 = va0 + 32;
                uint32_t vh0[4], vl0[4], vh1[4], vl1[4];
                ldsm4t(vh0, va0); ldsm4t(vl0, va0 + AKMAT);
                ldsm4t(vh1, va1); ldsm4t(vl1, va1 + AKMAT);
                #pragma unroll
                for (int h2 = 0; h2 < 2; h2++) {
                    mma16816(O[np * 2 + h2],       pH[kk], &vh0[h2 * 2]);
                    mma16816(O[(np + 1) * 2 + h2], pH[kk], &vh1[h2 * 2]);
                }
                #pragma unroll
                for (int h2 = 0; h2 < 2; h2++) {
                    mma16816(O[np * 2 + h2],       pH[kk], &vl0[h2 * 2]);
                    mma16816(O[(np + 1) * 2 + h2], pH[kk], &vl1[h2 * 2]);
                }
                #pragma unroll
                for (int h2 = 0; h2 < 2; h2++) {
                    mma16816(O[np * 2 + h2],       pL[kk], &vh0[h2 * 2]);
                    mma16816(O[(np + 1) * 2 + h2], pL[kk], &vh1[h2 * 2]);
                }
            }
        }
        __syncthreads();
    }

    // ---- finalize: /l, add residual, store fp32 ----
    const float inv0 = 1.0f / l_lo, inv1 = 1.0f / l_hi;
    const int gr0 = b * CC + q0 + rowl;
    #pragma unroll
    for (int n = 0; n < 8; n++) {
        const int col = h * 64 + n * 8 + c0;
        const size_t o0 = (size_t)gr0 * EE + col;
        const size_t o1 = o0 + (size_t)8 * EE;
        const float2 i0 = *(const float2*)&inp[o0];
        const float2 i1 = *(const float2*)&inp[o1];
        *(float2*)&Out[o0] = make_float2(i0.x + O[n][0] * inv0,
                                         i0.y + O[n][1] * inv0);
        *(float2*)&Out[o1] = make_float2(i1.x + O[n][2] * inv1,
                                         i1.y + O[n][3] * inv1);
    }
}

// ---------------------------------------------------------------------------
// kernel_launch
// ---------------------------------------------------------------------------
extern "C" void kernel_launch(void* const* d_in, const int* in_sizes, int n_in,
                              void* d_out, int out_size)
{
    const float* inputs = (const float*)d_in[0];
    const float* Wq     = (const float*)d_in[1];
    const float* bq     = (const float*)d_in[2];
    const float* Wk     = (const float*)d_in[3];
    const float* bk     = (const float*)d_in[4];
    const float* Wv     = (const float*)d_in[5];
    const float* bv     = (const float*)d_in[6];
    const float* g1     = (const float*)d_in[7];
    const float* beta1  = (const float*)d_in[8];
    const float* g2     = (const float*)d_in[9];
    const float* beta2  = (const float*)d_in[10];
    const float* W1     = (const float*)d_in[11];
    const float* bm1    = (const float*)d_in[12];
    const float* W2     = (const float*)d_in[13];
    const float* bm2    = (const float*)d_in[14];
    float* out = (float*)d_out;

    unsigned char* base = nullptr;
    cudaGetSymbolAddress((void**)&base, g_scratch);
    __nv_bfloat16* nh    = (__nv_bfloat16*)(base + OFF_NH);
    __nv_bfloat16* nl    = (__nv_bfloat16*)(base + OFF_NL);
    __nv_bfloat16* hh    = (__nv_bfloat16*)(base + OFF_HH);
    __nv_bfloat16* hl    = (__nv_bfloat16*)(base + OFF_HL);
    __nv_bfloat16* qh    = (__nv_bfloat16*)(base + OFF_QH);
    __nv_bfloat16* ql    = (__nv_bfloat16*)(base + OFF_QL);
    __nv_bfloat16* kvh   = (__nv_bfloat16*)(base + OFF_KVH);
    __nv_bfloat16* kvl   = (__nv_bfloat16*)(base + OFF_KVL);
    float* outbuf        = (float*)(base + OFF_OUTB);
    __nv_bfloat16* m1h   = (__nv_bfloat16*)(base + OFF_M1H);
    __nv_bfloat16* m1l   = (__nv_bfloat16*)(base + OFF_M1L);
    __nv_bfloat16* WqTh  = (__nv_bfloat16*)(base + OFF_WQH);
    __nv_bfloat16* WqTl  = (__nv_bfloat16*)(base + OFF_WQL);
    __nv_bfloat16* WkvTh = (__nv_bfloat16*)(base + OFF_WKVH);
    __nv_bfloat16* WkvTl = (__nv_bfloat16*)(base + OFF_WKVL);
    __nv_bfloat16* W1Th  = (__nv_bfloat16*)(base + OFF_W1H);
    __nv_bfloat16* W1Tl  = (__nv_bfloat16*)(base + OFF_W1L);
    __nv_bfloat16* W2Th  = (__nv_bfloat16*)(base + OFF_W2H);
    __nv_bfloat16* W2Tl  = (__nv_bfloat16*)(base + OFF_W2L);

    cudaFuncSetAttribute(gemm_tc, cudaFuncAttributeMaxDynamicSharedMemorySize,
                         GSM_BYTES);
    cudaFuncSetAttribute(attn_mma, cudaFuncAttributeMaxDynamicSharedMemorySize,
                         ATTN_SMEM);

    // Launch order keeps index 3 == gemm_tc (Q proj) for ncu capture.
    // 0: Wq prep
    tsplit_kernel<<<dim3(EE / 32, EE / 32), 256>>>(Wq, WqTh, WqTl, EE, EE);
    // 1: LN1 -> bf16 pair
    ln_kernel<<<MM, 256>>>(inputs, g1, beta1, nh, nl);
    // 2: Wk prep (rows 0..1023 of fused)
    tsplit_kernel<<<dim3(EE / 32, EE / 32), 256>>>(Wk, WkvTh, WkvTl, EE, EE);
    // 3: Q projection (profiled)
    gemm_tc<<<dim3(EE / 64, MM / 128), 256, GSM_BYTES>>>(
        nh, nl, WqTh, WqTl, bq, nullptr, 0, nullptr, nullptr,
        qh, ql, MM, EE, EE, 0, 0.125f);
    // 4: Wv prep (rows 1024..2047 of fused)
    tsplit_kernel<<<dim3(EE / 32, EE / 32), 256>>>(
        Wv, WkvTh + (size_t)1024 * EE, WkvTl + (size_t)1024 * EE, EE, EE);
    // 5: fused K|V projection (N=2048)
    gemm_tc<<<dim3(KVS / 64, MM / 128), 256, GSM_BYTES>>>(
        nh, nl, WkvTh, WkvTl, bk, bv, 1024, nullptr, nullptr,
        kvh, kvl, MM, KVS, EE, 0, 1.0f);
    // 6-7: MLP weight prep
    tsplit_kernel<<<dim3(FF / 32, EE / 32), 256>>>(W1, W1Th, W1Tl, EE, FF);
    tsplit_kernel<<<dim3(EE / 32, FF / 32), 256>>>(W2, W2Th, W2Tl, FF, EE);
    // 8: tensor-core causal attention + residual
    attn_mma<<<dim3(CC / 128, HH, BB), 256, ATTN_SMEM>>>(
        qh, ql, kvh, kvl, inputs, outbuf);
    // 9: LN2 -> bf16 pair
    ln_kernel<<<MM, 256>>>(outbuf, g2, beta2, hh, hl);
    // 10: MLP1 (relu) -> bf16 pair
    gemm_tc<<<dim3(FF / 64, MM / 128), 256, GSM_BYTES>>>(
        hh, hl, W1Th, W1Tl, bm1, nullptr, 0, nullptr, nullptr,
        m1h, m1l, MM, FF, EE, 1, 1.0f);
    // 11: MLP2 + residual -> out
    gemm_tc<<<dim3(EE / 64, MM / 128), 256, GSM_BYTES>>>(
        m1h, m1l, W2Th, W2Tl, bm2, nullptr, 0, outbuf, out,
        nullptr, nullptr, MM, EE, FF, 0, 1.0f);
}

// round 9
// speedup vs baseline: 1.3215x; 1.3215x over previous
#include <cuda_runtime.h>
#include <cuda_bf16.h>
#include <cuda_fp16.h>
#include <cstdint>

// ---------------------------------------------------------------------------
// Problem constants
// ---------------------------------------------------------------------------
#define BB 4
#define CC 2048
#define EE 1024
#define HH 16
#define DD 64
#define MM (BB * CC)          // 8192 rows
#define FF (4 * EE)           // 4096 mlp hidden
#define KVS 2048              // fused K|V row stride

// ---------------------------------------------------------------------------
// Scratch
// ---------------------------------------------------------------------------
#define MB (1ull << 20)
__device__ __align__(256) unsigned char g_scratch[364 * MB];

#define OFF_NH    (0 * MB)
#define OFF_NL    (16 * MB)
#define OFF_HH    (32 * MB)     // h as fp16 single [MM, EE] (16MB)
#define OFF_QH    (64 * MB)
#define OFF_QL    (80 * MB)
#define OFF_KVH   (96 * MB)     // [MM, 2048] bf16  (K cols 0-1023, V 1024-2047)
#define OFF_KVL   (128 * MB)
#define OFF_OUTB  (160 * MB)
#define OFF_M1H   (192 * MB)    // m1 as fp16 single [MM, FF] (64MB)
#define OFF_WQH   (320 * MB)
#define OFF_WQL   (322 * MB)
#define OFF_WKVH  (324 * MB)    // [2048, 1024] bf16
#define OFF_WKVL  (328 * MB)
#define OFF_W1H   (332 * MB)    // [4096,1024] fp16 (8MB)
#define OFF_W1L   (340 * MB)
#define OFF_W2H   (348 * MB)    // [1024,4096] fp16 (8MB)
#define OFF_W2L   (356 * MB)

// ---------------------------------------------------------------------------
// PTX helpers (baseline compute_103 only — no 'a' features)
// ---------------------------------------------------------------------------
__device__ __forceinline__ uint32_t smem_u32(const void* p) {
    uint32_t a;
    asm("{ .reg .u64 t; cvta.to.shared.u64 t, %1; cvt.u32.u64 %0, t; }"
        : "=r"(a) : "l"(p));
    return a;
}
__device__ __forceinline__ void cpa16(uint32_t d, const void* s) {
    asm volatile("cp.async.cg.shared.global [%0], [%1], 16;" :: "r"(d), "l"(s));
}
#define CP_COMMIT() asm volatile("cp.async.commit_group;" ::: "memory")

__device__ __forceinline__ void ldsm4(uint32_t* r, uint32_t addr) {
    asm volatile("ldmatrix.sync.aligned.m8n8.x4.shared.b16 {%0,%1,%2,%3}, [%4];"
                 : "=r"(r[0]), "=r"(r[1]), "=r"(r[2]), "=r"(r[3]) : "r"(addr));
}
__device__ __forceinline__ void ldsm4t(uint32_t* r, uint32_t addr) {
    asm volatile("ldmatrix.sync.aligned.m8n8.x4.trans.shared.b16 {%0,%1,%2,%3}, [%4];"
                 : "=r"(r[0]), "=r"(r[1]), "=r"(r[2]), "=r"(r[3]) : "r"(addr));
}
__device__ __forceinline__ void mma16816(float* c, const uint32_t* a,
                                         const uint32_t* b) {
    asm volatile(
        "mma.sync.aligned.m16n8k16.row.col.f32.bf16.bf16.f32 "
        "{%0,%1,%2,%3}, {%4,%5,%6,%7}, {%8,%9}, {%0,%1,%2,%3};"
        : "+f"(c[0]), "+f"(c[1]), "+f"(c[2]), "+f"(c[3])
        : "r"(a[0]), "r"(a[1]), "r"(a[2]), "r"(a[3]), "r"(b[0]), "r"(b[1]));
}
__device__ __forceinline__ void mma16816h(float* c, const uint32_t* a,
                                          const uint32_t* b) {
    asm volatile(
        "mma.sync.aligned.m16n8k16.row.col.f32.f16.f16.f32 "
        "{%0,%1,%2,%3}, {%4,%5,%6,%7}, {%8,%9}, {%0,%1,%2,%3};"
        : "+f"(c[0]), "+f"(c[1]), "+f"(c[2]), "+f"(c[3])
        : "r"(a[0]), "r"(a[1]), "r"(a[2]), "r"(a[3]), "r"(b[0]), "r"(b[1]));
}

__device__ __forceinline__ void split2(float a, float b, uint32_t& hi, uint32_t& lo) {
    const __nv_bfloat16 ha = __float2bfloat16(a), hb = __float2bfloat16(b);
    __nv_bfloat162 th = __halves2bfloat162(ha, hb);
    hi = *reinterpret_cast<uint32_t*>(&th);
    const float ra = a - __bfloat162float(ha);
    const float rb = b - __bfloat162float(hb);
    __nv_bfloat162 tl = __halves2bfloat162(__float2bfloat16(ra), __float2bfloat16(rb));
    lo = *reinterpret_cast<uint32_t*>(&tl);
}
__device__ __forceinline__ uint32_t pack_h2(float a, float b) {
    __half2 t = __floats2half2_rn(a, b);
    return *reinterpret_cast<uint32_t*>(&t);
}

// ---------------------------------------------------------------------------
// Weight transpose + bf16 hi/lo split:  W[K,N] fp32  ->  Th/Tl [N,K] bf16
// ---------------------------------------------------------------------------
__global__ __launch_bounds__(256) void tsplit_kernel(
    const float* __restrict__ W, __nv_bfloat16* __restrict__ Th,
    __nv_bfloat16* __restrict__ Tl, int K, int N)
{
    __shared__ float t[32][33];
    const int n0 = blockIdx.x * 32, k0 = blockIdx.y * 32;
    const int tx = threadIdx.x & 31, ty = threadIdx.x >> 5;
    #pragma unroll
    for (int j = 0; j < 32; j += 8)
        t[ty + j][tx] = W[(size_t)(k0 + ty + j) * N + n0 + tx];
    __syncthreads();
    #pragma unroll
    for (int j = 0; j < 32; j += 8) {
        const float v = t[tx][ty + j];
        const __nv_bfloat16 h = __float2bfloat16(v);
        const __nv_bfloat16 l = __float2bfloat16(v - __bfloat162float(h));
        const size_t o = (size_t)(n0 + ty + j) * K + k0 + tx;
        Th[o] = h; Tl[o] = l;
    }
}

// Transpose + fp16 hi/lo split
__global__ __launch_bounds__(256) void tsplit16_kernel(
    const float* __restrict__ W, __half* __restrict__ Th,
    __half* __restrict__ Tl, int K, int N)
{
    __shared__ float t[32][33];
    const int n0 = blockIdx.x * 32, k0 = blockIdx.y * 32;
    const int tx = threadIdx.x & 31, ty = threadIdx.x >> 5;
    #pragma unroll
    for (int j = 0; j < 32; j += 8)
        t[ty + j][tx] = W[(size_t)(k0 + ty + j) * N + n0 + tx];
    __syncthreads();
    #pragma unroll
    for (int j = 0; j < 32; j += 8) {
        const float v = t[tx][ty + j];
        const __half h = __float2half_rn(v);
        const __half l = __float2half_rn(v - __half2float(h));
        const size_t o = (size_t)(n0 + ty + j) * K + k0 + tx;
        Th[o] = h; Tl[o] = l;
    }
}

// ---------------------------------------------------------------------------
// LayerNorm -> bf16 hi/lo
// ---------------------------------------------------------------------------
__global__ __launch_bounds__(256) void ln_kernel(
    const float* __restrict__ x, const float* __restrict__ gamma,
    const float* __restrict__ beta, __nv_bfloat16* __restrict__ yh,
    __nv_bfloat16* __restrict__ yl)
{
    const int row = blockIdx.x;
    const int t = threadIdx.x;
    const float4 v = ((const float4*)(x + (size_t)row * EE))[t];
    float s  = v.x + v.y + v.z + v.w;
    float s2 = fmaf(v.x, v.x, fmaf(v.y, v.y, fmaf(v.z, v.z, v.w * v.w)));
    #pragma unroll
    for (int o = 16; o > 0; o >>= 1) {
        s  += __shfl_xor_sync(0xffffffffu, s, o);
        s2 += __shfl_xor_sync(0xffffffffu, s2, o);
    }
    __shared__ float rs[8], rs2[8];
    __shared__ float sstat[2];
    if ((t & 31) == 0) { rs[t >> 5] = s; rs2[t >> 5] = s2; }
    __syncthreads();
    if (t == 0) {
        float S = 0.f, S2 = 0.f;
        #pragma unroll
        for (int w = 0; w < 8; w++) { S += rs[w]; S2 += rs2[w]; }
        const float mean = S * (1.0f / EE);
        const float var  = S2 * (1.0f / EE) - mean * mean;
        sstat[0] = mean;
        sstat[1] = rsqrtf(var + 1e-5f);
    }
    __syncthreads();
    const float mean = sstat[0], rstd = sstat[1];
    const float4 gv = ((const float4*)gamma)[t];
    const float4 bv = ((const float4*)beta)[t];
    float o0 = (v.x - mean) * rstd * gv.x + bv.x;
    float o1 = (v.y - mean) * rstd * gv.y + bv.y;
    float o2 = (v.z - mean) * rstd * gv.z + bv.z;
    float o3 = (v.w - mean) * rstd * gv.w + bv.w;
    uint32_t h0, l0, h1, l1;
    split2(o0, o1, h0, l0);
    split2(o2, o3, h1, l1);
    uint32_t* ph = (uint32_t*)(yh + (size_t)row * EE + 4 * t);
    uint32_t* pl = (uint32_t*)(yl + (size_t)row * EE + 4 * t);
    ph[0] = h0; ph[1] = h1;
    pl[0] = l0; pl[1] = l1;
}

// LayerNorm -> fp16 single
__global__ __launch_bounds__(256) void ln16_kernel(
    const float* __restrict__ x, const float* __restrict__ gamma,
    const float* __restrict__ beta, __half* __restrict__ y)
{
    const int row = blockIdx.x;
    const int t = threadIdx.x;
    const float4 v = ((const float4*)(x + (size_t)row * EE))[t];
    float s  = v.x + v.y + v.z + v.w;
    float s2 = fmaf(v.x, v.x, fmaf(v.y, v.y, fmaf(v.z, v.z, v.w * v.w)));
    #pragma unroll
    for (int o = 16; o > 0; o >>= 1) {
        s  += __shfl_xor_sync(0xffffffffu, s, o);
        s2 += __shfl_xor_sync(0xffffffffu, s2, o);
    }
    __shared__ float rs[8], rs2[8];
    __shared__ float sstat[2];
    if ((t & 31) == 0) { rs[t >> 5] = s; rs2[t >> 5] = s2; }
    __syncthreads();
    if (t == 0) {
        float S = 0.f, S2 = 0.f;
        #pragma unroll
        for (int w = 0; w < 8; w++) { S += rs[w]; S2 += rs2[w]; }
        const float mean = S * (1.0f / EE);
        const float var  = S2 * (1.0f / EE) - mean * mean;
        sstat[0] = mean;
        sstat[1] = rsqrtf(var + 1e-5f);
    }
    __syncthreads();
    const float mean = sstat[0], rstd = sstat[1];
    const float4 gv = ((const float4*)gamma)[t];
    const float4 bv = ((const float4*)beta)[t];
    const float o0 = (v.x - mean) * rstd * gv.x + bv.x;
    const float o1 = (v.y - mean) * rstd * gv.y + bv.y;
    const float o2 = (v.z - mean) * rstd * gv.z + bv.z;
    const float o3 = (v.w - mean) * rstd * gv.w + bv.w;
    uint32_t* p = (uint32_t*)(y + (size_t)row * EE + 4 * t);
    p[0] = pack_h2(o0, o1);
    p[1] = pack_h2(o2, o3);
}

// ---------------------------------------------------------------------------
// mma.sync bf16x3 GEMM, 128x128 tile, 2-stage cp.async, 2 CTAs/SM.
// (R6/R7 proven configuration)
// ---------------------------------------------------------------------------
#define ROWB 80u
#define MATB 10240u
#define STGB 40960u
#define GSM_BYTES (2 * 40960)    // 81920

__global__ __launch_bounds__(256, 2) void gemm_tc(
    const __nv_bfloat16* __restrict__ Ah, const __nv_bfloat16* __restrict__ Al,
    const __nv_bfloat16* __restrict__ Bh, const __nv_bfloat16* __restrict__ Bl,
    const float* __restrict__ bias, const float* __restrict__ bias2, int nsplit,
    float* __restrict__ Cf, __nv_bfloat16* __restrict__ Ch,
    __nv_bfloat16* __restrict__ Cl, int M, int N, int K, float oscale)
{
    extern __shared__ unsigned char smem[];
    const uint32_t sbase = smem_u32(smem);
    const int tid = threadIdx.x;
    const int lane = tid & 31, wid = tid >> 5;
    const int wm = wid >> 2, wn = wid & 3;
    const int row0 = blockIdx.y * 128, col0 = blockIdx.x * 128;

    const __nv_bfloat16* gAh = Ah + (size_t)row0 * K;
    const __nv_bfloat16* gAl = Al + (size_t)row0 * K;
    const __nv_bfloat16* gBh = Bh + (size_t)col0 * K;
    const __nv_bfloat16* gBl = Bl + (size_t)col0 * K;
    const int nch = K >> 5;

    float acc[4][4][4];
    #pragma unroll
    for (int a = 0; a < 4; a++)
        #pragma unroll
        for (int b = 0; b < 4; b++)
            #pragma unroll
            for (int c = 0; c < 4; c++) acc[a][b][c] = 0.f;

    const uint32_t a_base = (uint32_t)(wm * 64 + (lane & 15)) * ROWB +
                            (((lane >> 4) << 3) << 1);
    const uint32_t b_base = (uint32_t)(wn * 32 + ((lane >> 4) << 3) + (lane & 7)) * ROWB +
                            ((((lane >> 3) & 1) << 3) << 1);

    auto load_chunk = [&](int ch, int s) {
        const int k0 = ch << 5;
        const uint32_t st = sbase + s * STGB;
        #pragma unroll
        for (int i = 0; i < 8; i++) {
            const __nv_bfloat16* src = (i < 2) ? gAh : (i < 4) ? gAl
                                     : (i < 6) ? gBh : gBl;
            const int rem = ((i & 1) << 8) + tid;
            const int r = rem >> 2, g = rem & 3;
            cpa16(st + (uint32_t)(i >> 1) * MATB + (uint32_t)r * ROWB + g * 16u,
                  src + (size_t)r * K + k0 + g * 8);
        }
    };

    auto compute_chunk = [&](int s) {
        const uint32_t st = sbase + s * STGB;
        #pragma unroll
        for (int ks = 0; ks < 32; ks += 16) {
            uint32_t aH[4][4], aL[4][4], bH[2][4], bL[2][4];
            const uint32_t ao = a_base + (ks << 1);
            #pragma unroll
            for (int mi = 0; mi < 4; mi++) {
                ldsm4(aH[mi], st + ao + (uint32_t)mi * 16 * ROWB);
                ldsm4(aL[mi], st + MATB + ao + (uint32_t)mi * 16 * ROWB);
            }
            const uint32_t bo = b_base + (ks << 1);
            #pragma unroll
            for (int p = 0; p < 2; p++) {
                ldsm4(bH[p], st + 2 * MATB + bo + (uint32_t)p * 16 * ROWB);
                ldsm4(bL[p], st + 3 * MATB + bo + (uint32_t)p * 16 * ROWB);
            }
            #pragma unroll
            for (int mi = 0; mi < 4; mi++)
                #pragma unroll
                for (int p = 0; p < 2; p++)
                    #pragma unroll
                    for (int h = 0; h < 2; h++) {
                        float* c = acc[mi][p * 2 + h];
                        mma16816(c, aH[mi], &bH[p][h * 2]);
                        mma16816(c, aH[mi], &bL[p][h * 2]);
                        mma16816(c, aL[mi], &bH[p][h * 2]);
                    }
        }
    };

    load_chunk(0, 0); CP_COMMIT();
    load_chunk(1, 1); CP_COMMIT();

    for (int ch = 0; ch < nch; ch++) {
        asm volatile("cp.async.wait_group 1;" ::: "memory");
        __syncthreads();
        compute_chunk(ch & 1);
        __syncthreads();
        if (ch + 2 < nch) load_chunk(ch + 2, ch & 1);
        CP_COMMIT();
    }
    asm volatile("cp.async.wait_group 0;" ::: "memory");

    // ---------------- epilogue ----------------
    const float* effb = (bias2 && col0 >= nsplit) ? (bias2 - nsplit) : bias;
    const int tr = lane >> 2, tc = (lane & 3) << 1;
    #pragma unroll
    for (int mi = 0; mi < 4; mi++) {
        #pragma unroll
        for (int ni = 0; ni < 4; ni++) {
            const int col = col0 + wn * 32 + ni * 8 + tc;
            const float2 bb = *(const float2*)&effb[col];
            #pragma unroll
            for (int hr = 0; hr < 2; hr++) {
                const int row = row0 + wm * 64 + mi * 16 + tr + hr * 8;
                float v0 = (acc[mi][ni][hr * 2 + 0] + bb.x) * oscale;
                float v1 = (acc[mi][ni][hr * 2 + 1] + bb.y) * oscale;
                const size_t goff = (size_t)row * N + col;
                if (Cf) {
                    *(float2*)&Cf[goff] = make_float2(v0, v1);
                } else {
                    uint32_t hp, lp;
                    split2(v0, v1, hp, lp);
                    *(uint32_t*)&Ch[goff] = hp;
                    *(uint32_t*)&Cl[goff] = lp;
                }
            }
        }
    }
}

// ---------------------------------------------------------------------------
// fp16 2-pass GEMM: D = A(fp16) @ [Bh + Bl]^T.  128x128 tile, 2-stage,
// 2 CTAs/SM.  Used for the MLP where activation rounding (2^-12) suffices.
// Epilogue: +bias, relu -> fp16 single out, OR +bias +res -> fp32 out.
// ---------------------------------------------------------------------------
#define H2STG 30720u              // A | Bh | Bl  (10240 each)
#define H2_BH 10240u
#define H2_BL 20480u
#define GSM2_BYTES (2 * 30720)    // 61440

__global__ __launch_bounds__(256, 2) void gemm_fp16_2p(
    const __half* __restrict__ A, const __half* __restrict__ Bh,
    const __half* __restrict__ Bl, const float* __restrict__ bias,
    const float* __restrict__ res, float* __restrict__ Cf,
    __half* __restrict__ Ch, int M, int N, int K, int relu)
{
    extern __shared__ unsigned char smem[];
    const uint32_t sbase = smem_u32(smem);
    const int tid = threadIdx.x;
    const int lane = tid & 31, wid = tid >> 5;
    const int wm = wid >> 2, wn = wid & 3;
    const int row0 = blockIdx.y * 128, col0 = blockIdx.x * 128;

    const __half* gA  = A  + (size_t)row0 * K;
    const __half* gBh = Bh + (size_t)col0 * K;
    const __half* gBl = Bl + (size_t)col0 * K;
    const int nch = K >> 5;

    float acc[4][4][4];
    #pragma unroll
    for (int a = 0; a < 4; a++)
        #pragma unroll
        for (int b = 0; b < 4; b++)
            #pragma unroll
            for (int c = 0; c < 4; c++) acc[a][b][c] = 0.f;

    const uint32_t a_base = (uint32_t)(wm * 64 + (lane & 15)) * ROWB +
                            (((lane >> 4) << 3) << 1);
    const uint32_t b_base = (uint32_t)(wn * 32 + ((lane >> 4) << 3) + (lane & 7)) * ROWB +
                            ((((lane >> 3) & 1) << 3) << 1);

    auto load_chunk = [&](int ch, int s) {
        const int k0 = ch << 5;
        const uint32_t st = sbase + s * H2STG;
        #pragma unroll
        for (int i = 0; i < 6; i++) {
            const __half* src = (i < 2) ? gA : (i < 4) ? gBh : gBl;
            const int rem = ((i & 1) << 8) + tid;
            const int r = rem >> 2, g = rem & 3;
            cpa16(st + (uint32_t)(i >> 1) * MATB + (uint32_t)r * ROWB + g * 16u,
                  src + (size_t)r * K + k0 + g * 8);
        }
    };

    auto compute_chunk = [&](int s) {
        const uint32_t st = sbase + s * H2STG;
        #pragma unroll
        for (int ks = 0; ks < 32; ks += 16) {
            uint32_t aF[4][4], bH[2][4], bL[2][4];
            const uint32_t ao = a_base + (ks << 1);
            #pragma unroll
            for (int mi = 0; mi < 4; mi++)
                ldsm4(aF[mi], st + ao + (uint32_t)mi * 16 * ROWB);
            const uint32_t bo = b_base + (ks << 1);
            #pragma unroll
            for (int p = 0; p < 2; p++) {
                ldsm4(bH[p], st + H2_BH + bo + (uint32_t)p * 16 * ROWB);
                ldsm4(bL[p], st + H2_BL + bo + (uint32_t)p * 16 * ROWB);
            }
            #pragma unroll
            for (int mi = 0; mi < 4; mi++)
                #pragma unroll
                for (int p = 0; p < 2; p++)
                    #pragma unroll
                    for (int h = 0; h < 2; h++) {
                        float* c = acc[mi][p * 2 + h];
                        mma16816h(c, aF[mi], &bH[p][h * 2]);
                        mma16816h(c, aF[mi], &bL[p][h * 2]);
                    }
        }
    };

    load_chunk(0, 0); CP_COMMIT();
    load_chunk(1, 1); CP_COMMIT();

    for (int ch = 0; ch < nch; ch++) {
        asm volatile("cp.async.wait_group 1;" ::: "memory");
        __syncthreads();
        compute_chunk(ch & 1);
        __syncthreads();
        if (ch + 2 < nch) load_chunk(ch + 2, ch & 1);
        CP_COMMIT();
    }
    asm volatile("cp.async.wait_group 0;" ::: "memory");

    // ---------------- epilogue ----------------
    const int tr = lane >> 2, tc = (lane & 3) << 1;
    #pragma unroll
    for (int mi = 0; mi < 4; mi++) {
        #pragma unroll
        for (int ni = 0; ni < 4; ni++) {
            const int col = col0 + wn * 32 + ni * 8 + tc;
            const float2 bb = *(const float2*)&bias[col];
            #pragma unroll
            for (int hr = 0; hr < 2; hr++) {
                const int row = row0 + wm * 64 + mi * 16 + tr + hr * 8;
                float v0 = acc[mi][ni][hr * 2 + 0] + bb.x;
                float v1 = acc[mi][ni][hr * 2 + 1] + bb.y;
                if (relu) { v0 = fmaxf(v0, 0.f); v1 = fmaxf(v1, 0.f); }
                const size_t goff = (size_t)row * N + col;
                if (Cf) {
                    if (res) {
                        const float2 rv = *(const float2*)&res[goff];
                        v0 += rv.x; v1 += rv.y;
                    }
                    *(float2*)&Cf[goff] = make_float2(v0, v1);
                } else {
                    *(uint32_t*)&Ch[goff] = pack_h2(v0, v1);
                }
            }
        }
    }
}

// ---------------------------------------------------------------------------
// Tensor-core flash attention (causal), bf16x3 precision.
// BM=128, BN=64, 256 threads (8 warps, warp tile 16x64). Q pre-scaled 1/8.
// ---------------------------------------------------------------------------
#define AR 144u                   // bytes per smem row (64 bf16 + 8 pad)
#define AQMAT 18432u              // 128 rows * 144B
#define AKMAT 9216u               // 64 rows * 144B
#define ASTG (4 * AKMAT)          // Kh,Kl,Vh,Vl per stage = 36864
#define ATTN_SMEM (2 * AQMAT + 2 * ASTG)   // 110592

__global__ __launch_bounds__(256) void attn_mma(
    const __nv_bfloat16* __restrict__ Qh, const __nv_bfloat16* __restrict__ Ql,
    const __nv_bfloat16* __restrict__ KVh, const __nv_bfloat16* __restrict__ KVl,
    const float* __restrict__ inp, float* __restrict__ Out)
{
    extern __shared__ unsigned char smem[];
    const uint32_t sbase = smem_u32(smem);
    const int tid = threadIdx.x, lane = tid & 31, w = tid >> 5;
    const int qt = blockIdx.x, h = blockIdx.y, b = blockIdx.z;
    const int q0 = qt * 128;
    const int nt = 2 * qt + 2;                 // kv tiles (64 rows each)

    {
        const size_t ro = (size_t)(b * CC + q0) * EE + (size_t)h * 64;
        #pragma unroll
        for (int i = 0; i < 4; i++) {
            const int idx = i * 256 + tid;
            const int r = idx >> 3, g = idx & 7;
            const uint32_t d = sbase + (uint32_t)r * AR + g * 16u;
            const size_t so = ro + (size_t)r * EE + g * 8;
            cpa16(d, Qh + so);
            cpa16(d + AQMAT, Ql + so);
        }
    }
    CP_COMMIT();

    const size_t kvbase = (size_t)(b * CC) * KVS + (size_t)h * 64;
    auto load_kv = [&](int t, int s) {
        const uint32_t st = sbase + 2 * AQMAT + (uint32_t)s * ASTG;
        const size_t ro = kvbase + (size_t)(t * 64) * KVS;
        #pragma unroll
        for (int i = 0; i < 2; i++) {
            const int idx = i * 256 + tid;
            const int r = idx >> 3, g = idx & 7;
            const uint32_t d = st + (uint32_t)r * AR + g * 16u;
            const size_t so = ro + (size_t)r * KVS + g * 8;
            cpa16(d, KVh + so);
            cpa16(d + AKMAT, KVl + so);
            cpa16(d + 2 * AKMAT, KVh + so + 1024);
            cpa16(d + 3 * AKMAT, KVl + so + 1024);
        }
    };
    load_kv(0, 0); CP_COMMIT();

    float O[8][4];
    #pragma unroll
    for (int n = 0; n < 8; n++)
        #pragma unroll
        for (int j = 0; j < 4; j++) O[n][j] = 0.f;
    float m_lo = -1e30f, m_hi = -1e30f, l_lo = 0.f, l_hi = 0.f;
    uint32_t qHf[4][4], qLf[4][4];

    const int rowl = w * 16 + (lane >> 2);
    const int c0 = (lane & 3) << 1;

    for (int t = 0; t < nt; t++) {
        if (t + 1 < nt) load_kv(t + 1, (t + 1) & 1);
        CP_COMMIT();
        asm volatile("cp.async.wait_group 1;" ::: "memory");
        __syncthreads();

        const uint32_t sK = sbase + 2 * AQMAT + (uint32_t)(t & 1) * ASTG;
        const uint32_t sV = sK + 2 * AKMAT;

        if (t == 0) {
            const uint32_t qa = sbase + (uint32_t)(w * 16 + (lane & 15)) * AR +
                                (((lane >> 4) << 3) << 1);
            #pragma unroll
            for (int ks = 0; ks < 4; ks++) {
                ldsm4(qHf[ks], qa + ks * 32);
                ldsm4(qLf[ks], qa + AQMAT + ks * 32);
            }
        }

        float S[8][4];
        #pragma unroll
        for (int n = 0; n < 8; n++)
            #pragma unroll
            for (int j = 0; j < 4; j++) S[n][j] = 0.f;

        #pragma unroll
        for (int ks = 0; ks < 4; ks++) {
            #pragma unroll
            for (int np = 0; np < 4; np += 2) {
                const uint32_t kb0 = sK +
                    (uint32_t)(np * 16 + ((lane >> 4) << 3) + (lane & 7)) * AR +
                    ((((lane >> 3) & 1) << 3) << 1) + ks * 32;
                const uint32_t kb1 = kb0 + 16 * AR;
                uint32_t bh0[4], bl0[4], bh1[4], bl1[4];
                ldsm4(bh0, kb0); ldsm4(bl0, kb0 + AKMAT);
                ldsm4(bh1, kb1); ldsm4(bl1, kb1 + AKMAT);
                #pragma unroll
                for (int h2 = 0; h2 < 2; h2++) {
                    mma16816(S[np * 2 + h2],       qHf[ks], &bh0[h2 * 2]);
                    mma16816(S[(np + 1) * 2 + h2], qHf[ks], &bh1[h2 * 2]);
                }
                #pragma unroll
                for (int h2 = 0; h2 < 2; h2++) {
                    mma16816(S[np * 2 + h2],       qHf[ks], &bl0[h2 * 2]);
                    mma16816(S[(np + 1) * 2 + h2], qHf[ks], &bl1[h2 * 2]);
                }
                #pragma unroll
                for (int h2 = 0; h2 < 2; h2++) {
                    mma16816(S[np * 2 + h2],       qLf[ks], &bh0[h2 * 2]);
                    mma16816(S[(np + 1) * 2 + h2], qLf[ks], &bh1[h2 * 2]);
                }
            }
        }

        if (t >= 2 * qt) {
            const int colg0 = t * 64;
            const int rg_lo = q0 + rowl, rg_hi = rg_lo + 8;
            #pragma unroll
            for (int n = 0; n < 8; n++) {
                const int col = colg0 + n * 8 + c0;
                if (col > rg_lo)     S[n][0] = -1e30f;
                if (col + 1 > rg_lo) S[n][1] = -1e30f;
                if (col > rg_hi)     S[n][2] = -1e30f;
                if (col + 1 > rg_hi) S[n][3] = -1e30f;
            }
        }

        float mx0 = -1e30f, mx1 = -1e30f;
        #pragma unroll
        for (int n = 0; n < 8; n++) {
            mx0 = fmaxf(mx0, fmaxf(S[n][0], S[n][1]));
            mx1 = fmaxf(mx1, fmaxf(S[n][2], S[n][3]));
        }
        mx0 = fmaxf(mx0, __shfl_xor_sync(0xffffffffu, mx0, 1));
        mx0 = fmaxf(mx0, __shfl_xor_sync(0xffffffffu, mx0, 2));
        mx1 = fmaxf(mx1, __shfl_xor_sync(0xffffffffu, mx1, 1));
        mx1 = fmaxf(mx1, __shfl_xor_sync(0xffffffffu, mx1, 2));
        const float mn0 = fmaxf(m_lo, mx0), mn1 = fmaxf(m_hi, mx1);
        const float cr0 = __expf(m_lo - mn0), cr1 = __expf(m_hi - mn1);
        float s0 = 0.f, s1 = 0.f;
        #pragma unroll
        for (int n = 0; n < 8; n++) {
            S[n][0] = __expf(S[n][0] - mn0); s0 += S[n][0];
            S[n][1] = __expf(S[n][1] - mn0); s0 += S[n][1];
            S[n][2] = __expf(S[n][2] - mn1); s1 += S[n][2];
            S[n][3] = __expf(S[n][3] - mn1); s1 += S[n][3];
        }
        s0 += __shfl_xor_sync(0xffffffffu, s0, 1);
        s0 += __shfl_xor_sync(0xffffffffu, s0, 2);
        s1 += __shfl_xor_sync(0xffffffffu, s1, 1);
        s1 += __shfl_xor_sync(0xffffffffu, s1, 2);
        l_lo = l_lo * cr0 + s0; l_hi = l_hi * cr1 + s1;
        m_lo = mn0; m_hi = mn1;
        #pragma unroll
        for (int n = 0; n < 8; n++) {
            O[n][0] *= cr0; O[n][1] *= cr0;
            O[n][2] *= cr1; O[n][3] *= cr1;
        }

        uint32_t pH[4][4], pL[4][4];
        #pragma unroll
        for (int kk = 0; kk < 4; kk++) {
            split2(S[2 * kk][0],     S[2 * kk][1],     pH[kk][0], pL[kk][0]);
            split2(S[2 * kk][2],     S[2 * kk][3],     pH[kk][1], pL[kk][1]);
            split2(S[2 * kk + 1][0], S[2 * kk + 1][1], pH[kk][2], pL[kk][2]);
            split2(S[2 * kk + 1][2], S[2 * kk + 1][3], pH[kk][3], pL[kk][3]);
        }

        #pragma unroll
        for (int kk = 0; kk < 4; kk++) {
            #pragma unroll
            for (int np = 0; np < 4; np += 2) {
                const uint32_t va0 = sV +
                    (uint32_t)(kk * 16 + ((lane >> 3) & 1) * 8 + (lane & 7)) * AR +
                    ((np * 16 + ((lane >> 4) << 3)) << 1);
                const uint32_t va1 = va0 + 32;
                uint32_t vh0[4], vl0[4], vh1[4], vl1[4];
                ldsm4t(vh0, va0); ldsm4t(vl0, va0 + AKMAT);
                ldsm4t(vh1, va1); ldsm4t(vl1, va1 + AKMAT);
                #pragma unroll
                for (int h2 = 0; h2 < 2; h2++) {
                    mma16816(O[np * 2 + h2],       pH[kk], &vh0[h2 * 2]);
                    mma16816(O[(np + 1) * 2 + h2], pH[kk], &vh1[h2 * 2]);
                }
                #pragma unroll
                for (int h2 = 0; h2 < 2; h2++) {
                    mma16816(O[np * 2 + h2],       pH[kk], &vl0[h2 * 2]);
                    mma16816(O[(np + 1) * 2 + h2], pH[kk], &vl1[h2 * 2]);
                }
                #pragma unroll
                for (int h2 = 0; h2 < 2; h2++) {
                    mma16816(O[np * 2 + h2],       pL[kk], &vh0[h2 * 2]);
                    mma16816(O[(np + 1) * 2 + h2], pL[kk], &vh1[h2 * 2]);
                }
            }
        }
        __syncthreads();
    }

    const float inv0 = 1.0f / l_lo, inv1 = 1.0f / l_hi;
    const int gr0 = b * CC + q0 + rowl;
    #pragma unroll
    for (int n = 0; n < 8; n++) {
        const int col = h * 64 + n * 8 + c0;
        const size_t o0 = (size_t)gr0 * EE + col;
        const size_t o1 = o0 + (size_t)8 * EE;
        const float2 i0 = *(const float2*)&inp[o0];
        const float2 i1 = *(const float2*)&inp[o1];
        *(float2*)&Out[o0] = make_float2(i0.x + O[n][0] * inv0,
                                         i0.y + O[n][1] * inv0);
        *(float2*)&Out[o1] = make_float2(i1.x + O[n][2] * inv1,
                                         i1.y + O[n][3] * inv1);
    }
}

// ---------------------------------------------------------------------------
// kernel_launch
// ---------------------------------------------------------------------------
extern "C" void kernel_launch(void* const* d_in, const int* in_sizes, int n_in,
                              void* d_out, int out_size)
{
    const float* inputs = (const float*)d_in[0];
    const float* Wq     = (const float*)d_in[1];
    const float* bq     = (const float*)d_in[2];
    const float* Wk     = (const float*)d_in[3];
    const float* bk     = (const float*)d_in[4];
    const float* Wv     = (const float*)d_in[5];
    const float* bv     = (const float*)d_in[6];
    const float* g1     = (const float*)d_in[7];
    const float* beta1  = (const float*)d_in[8];
    const float* g2     = (const float*)d_in[9];
    const float* beta2  = (const float*)d_in[10];
    const float* W1     = (const float*)d_in[11];
    const float* bm1    = (const float*)d_in[12];
    const float* W2     = (const float*)d_in[13];
    const float* bm2    = (const float*)d_in[14];
    float* out = (float*)d_out;

    unsigned char* base = nullptr;
    cudaGetSymbolAddress((void**)&base, g_scratch);
    __nv_bfloat16* nh    = (__nv_bfloat16*)(base + OFF_NH);
    __nv_bfloat16* nl    = (__nv_bfloat16*)(base + OFF_NL);
    __half* hh           = (__half*)(base + OFF_HH);
    __nv_bfloat16* qh    = (__nv_bfloat16*)(base + OFF_QH);
    __nv_bfloat16* ql    = (__nv_bfloat16*)(base + OFF_QL);
    __nv_bfloat16* kvh   = (__nv_bfloat16*)(base + OFF_KVH);
    __nv_bfloat16* kvl   = (__nv_bfloat16*)(base + OFF_KVL);
    float* outbuf        = (float*)(base + OFF_OUTB);
    __half* m1           = (__half*)(base + OFF_M1H);
    __nv_bfloat16* WqTh  = (__nv_bfloat16*)(base + OFF_WQH);
    __nv_bfloat16* WqTl  = (__nv_bfloat16*)(base + OFF_WQL);
    __nv_bfloat16* WkvTh = (__nv_bfloat16*)(base + OFF_WKVH);
    __nv_bfloat16* WkvTl = (__nv_bfloat16*)(base + OFF_WKVL);
    __half* W1Th         = (__half*)(base + OFF_W1H);
    __half* W1Tl         = (__half*)(base + OFF_W1L);
    __half* W2Th         = (__half*)(base + OFF_W2H);
    __half* W2Tl         = (__half*)(base + OFF_W2L);

    cudaFuncSetAttribute(gemm_tc, cudaFuncAttributeMaxDynamicSharedMemorySize,
                         GSM_BYTES);
    cudaFuncSetAttribute(gemm_fp16_2p, cudaFuncAttributeMaxDynamicSharedMemorySize,
                         GSM2_BYTES);
    cudaFuncSetAttribute(attn_mma, cudaFuncAttributeMaxDynamicSharedMemorySize,
                         ATTN_SMEM);

    // Launch order keeps index 3 == gemm_tc (Q proj) for ncu capture.
    // 0: Wq prep
    tsplit_kernel<<<dim3(EE / 32, EE / 32), 256>>>(Wq, WqTh, WqTl, EE, EE);
    // 1: LN1 -> bf16 pair
    ln_kernel<<<MM, 256>>>(inputs, g1, beta1, nh, nl);
    // 2: Wk prep (rows 0..1023 of fused)
    tsplit_kernel<<<dim3(EE / 32, EE / 32), 256>>>(Wk, WkvTh, WkvTl, EE, EE);
    // 3: Q projection (profiled)
    gemm_tc<<<dim3(EE / 128, MM / 128), 256, GSM_BYTES>>>(
        nh, nl, WqTh, WqTl, bq, nullptr, 0, nullptr,
        qh, ql, MM, EE, EE, 0.125f);
    // 4: Wv prep (rows 1024..2047 of fused)
    tsplit_kernel<<<dim3(EE / 32, EE / 32), 256>>>(
        Wv, WkvTh + (size_t)1024 * EE, WkvTl + (size_t)1024 * EE, EE, EE);
    // 5: fused K|V projection (N=2048)
    gemm_tc<<<dim3(KVS / 128, MM / 128), 256, GSM_BYTES>>>(
        nh, nl, WkvTh, WkvTl, bk, bv, 1024, nullptr,
        kvh, kvl, MM, KVS, EE, 1.0f);
    // 6-7: MLP weight prep (fp16 hi/lo)
    tsplit16_kernel<<<dim3(FF / 32, EE / 32), 256>>>(W1, W1Th, W1Tl, EE, FF);
    tsplit16_kernel<<<dim3(EE / 32, FF / 32), 256>>>(W2, W2Th, W2Tl, FF, EE);
    // 8: tensor-core causal attention + residual
    attn_mma<<<dim3(CC / 128, HH, BB), 256, ATTN_SMEM>>>(
        qh, ql, kvh, kvl, inputs, outbuf);
    // 9: LN2 -> fp16 single
    ln16_kernel<<<MM, 256>>>(outbuf, g2, beta2, hh);
    // 10: MLP1 (relu) -> fp16 single, 2-pass fp16
    gemm_fp16_2p<<<dim3(FF / 128, MM / 128), 256, GSM2_BYTES>>>(
        hh, W1Th, W1Tl, bm1, nullptr, nullptr, m1, MM, FF, EE, 1);
    // 11: MLP2 + residual -> out, 2-pass fp16
    gemm_fp16_2p<<<dim3(EE / 128, MM / 128), 256, GSM2_BYTES>>>(
        m1, W2Th, W2Tl, bm2, outbuf, out, nullptr, MM, EE, FF, 0);
}

// round 10
// speedup vs baseline: 1.6395x; 1.2406x over previous
#include <cuda_runtime.h>
#include <cuda_bf16.h>
#include <cuda_fp16.h>
#include <cstdint>

// ---------------------------------------------------------------------------
// Problem constants
// ---------------------------------------------------------------------------
#define BB 4
#define CC 2048
#define EE 1024
#define HH 16
#define DD 64
#define MM (BB * CC)          // 8192 rows
#define FF (4 * EE)           // 4096 mlp hidden
#define KVS 2048              // fused K|V row stride

// ---------------------------------------------------------------------------
// Scratch
// ---------------------------------------------------------------------------
#define MB (1ull << 20)
__device__ __align__(256) unsigned char g_scratch[364 * MB];

#define OFF_NH    (0 * MB)
#define OFF_NL    (16 * MB)
#define OFF_HH    (32 * MB)     // h as fp16 single [MM, EE] (16MB)
#define OFF_QH    (64 * MB)
#define OFF_QL    (80 * MB)
#define OFF_KVH   (96 * MB)     // [MM, 2048] bf16  (K cols 0-1023, V 1024-2047)
#define OFF_KVL   (128 * MB)
#define OFF_OUTB  (160 * MB)
#define OFF_M1H   (192 * MB)    // m1 as fp16 single [MM, FF] (64MB)
#define OFF_WQH   (320 * MB)
#define OFF_WQL   (322 * MB)
#define OFF_WKVH  (324 * MB)    // [2048, 1024] bf16
#define OFF_WKVL  (328 * MB)
#define OFF_W1H   (332 * MB)    // [4096,1024] fp16 (8MB)
#define OFF_W2H   (348 * MB)    // [1024,4096] fp16 (8MB)

// ---------------------------------------------------------------------------
// PTX helpers (baseline compute_103 only — no 'a' features)
// ---------------------------------------------------------------------------
__device__ __forceinline__ uint32_t smem_u32(const void* p) {
    uint32_t a;
    asm("{ .reg .u64 t; cvta.to.shared.u64 t, %1; cvt.u32.u64 %0, t; }"
        : "=r"(a) : "l"(p));
    return a;
}
__device__ __forceinline__ void cpa16(uint32_t d, const void* s) {
    asm volatile("cp.async.cg.shared.global [%0], [%1], 16;" :: "r"(d), "l"(s));
}
#define CP_COMMIT() asm volatile("cp.async.commit_group;" ::: "memory")

__device__ __forceinline__ void ldsm4(uint32_t* r, uint32_t addr) {
    asm volatile("ldmatrix.sync.aligned.m8n8.x4.shared.b16 {%0,%1,%2,%3}, [%4];"
                 : "=r"(r[0]), "=r"(r[1]), "=r"(r[2]), "=r"(r[3]) : "r"(addr));
}
__device__ __forceinline__ void ldsm4t(uint32_t* r, uint32_t addr) {
    asm volatile("ldmatrix.sync.aligned.m8n8.x4.trans.shared.b16 {%0,%1,%2,%3}, [%4];"
                 : "=r"(r[0]), "=r"(r[1]), "=r"(r[2]), "=r"(r[3]) : "r"(addr));
}
__device__ __forceinline__ void mma16816(float* c, const uint32_t* a,
                                         const uint32_t* b) {
    asm volatile(
        "mma.sync.aligned.m16n8k16.row.col.f32.bf16.bf16.f32 "
        "{%0,%1,%2,%3}, {%4,%5,%6,%7}, {%8,%9}, {%0,%1,%2,%3};"
        : "+f"(c[0]), "+f"(c[1]), "+f"(c[2]), "+f"(c[3])
        : "r"(a[0]), "r"(a[1]), "r"(a[2]), "r"(a[3]), "r"(b[0]), "r"(b[1]));
}
__device__ __forceinline__ void mma16816h(float* c, const uint32_t* a,
                                          const uint32_t* b) {
    asm volatile(
        "mma.sync.aligned.m16n8k16.row.col.f32.f16.f16.f32 "
        "{%0,%1,%2,%3}, {%4,%5,%6,%7}, {%8,%9}, {%0,%1,%2,%3};"
        : "+f"(c[0]), "+f"(c[1]), "+f"(c[2]), "+f"(c[3])
        : "r"(a[0]), "r"(a[1]), "r"(a[2]), "r"(a[3]), "r"(b[0]), "r"(b[1]));
}

__device__ __forceinline__ void split2(float a, float b, uint32_t& hi, uint32_t& lo) {
    const __nv_bfloat16 ha = __float2bfloat16(a), hb = __float2bfloat16(b);
    __nv_bfloat162 th = __halves2bfloat162(ha, hb);
    hi = *reinterpret_cast<uint32_t*>(&th);
    const float ra = a - __bfloat162float(ha);
    const float rb = b - __bfloat162float(hb);
    __nv_bfloat162 tl = __halves2bfloat162(__float2bfloat16(ra), __float2bfloat16(rb));
    lo = *reinterpret_cast<uint32_t*>(&tl);
}
__device__ __forceinline__ uint32_t pack_h2(float a, float b) {
    __half2 t = __floats2half2_rn(a, b);
    return *reinterpret_cast<uint32_t*>(&t);
}

// ---------------------------------------------------------------------------
// Weight transpose + bf16 hi/lo split:  W[K,N] fp32  ->  Th/Tl [N,K] bf16
// ---------------------------------------------------------------------------
__global__ __launch_bounds__(256) void tsplit_kernel(
    const float* __restrict__ W, __nv_bfloat16* __restrict__ Th,
    __nv_bfloat16* __restrict__ Tl, int K, int N)
{
    __shared__ float t[32][33];
    const int n0 = blockIdx.x * 32, k0 = blockIdx.y * 32;
    const int tx = threadIdx.x & 31, ty = threadIdx.x >> 5;
    #pragma unroll
    for (int j = 0; j < 32; j += 8)
        t[ty + j][tx] = W[(size_t)(k0 + ty + j) * N + n0 + tx];
    __syncthreads();
    #pragma unroll
    for (int j = 0; j < 32; j += 8) {
        const float v = t[tx][ty + j];
        const __nv_bfloat16 h = __float2bfloat16(v);
        const __nv_bfloat16 l = __float2bfloat16(v - __bfloat162float(h));
        const size_t o = (size_t)(n0 + ty + j) * K + k0 + tx;
        Th[o] = h; Tl[o] = l;
    }
}

// Transpose + fp16 single
__global__ __launch_bounds__(256) void t16_kernel(
    const float* __restrict__ W, __half* __restrict__ Th, int K, int N)
{
    __shared__ float t[32][33];
    const int n0 = blockIdx.x * 32, k0 = blockIdx.y * 32;
    const int tx = threadIdx.x & 31, ty = threadIdx.x >> 5;
    #pragma unroll
    for (int j = 0; j < 32; j += 8)
        t[ty + j][tx] = W[(size_t)(k0 + ty + j) * N + n0 + tx];
    __syncthreads();
    #pragma unroll
    for (int j = 0; j < 32; j += 8) {
        const float v = t[tx][ty + j];
        Th[(size_t)(n0 + ty + j) * K + k0 + tx] = __float2half_rn(v);
    }
}

// ---------------------------------------------------------------------------
// LayerNorm -> bf16 hi/lo
// ---------------------------------------------------------------------------
__global__ __launch_bounds__(256) void ln_kernel(
    const float* __restrict__ x, const float* __restrict__ gamma,
    const float* __restrict__ beta, __nv_bfloat16* __restrict__ yh,
    __nv_bfloat16* __restrict__ yl)
{
    const int row = blockIdx.x;
    const int t = threadIdx.x;
    const float4 v = ((const float4*)(x + (size_t)row * EE))[t];
    float s  = v.x + v.y + v.z + v.w;
    float s2 = fmaf(v.x, v.x, fmaf(v.y, v.y, fmaf(v.z, v.z, v.w * v.w)));
    #pragma unroll
    for (int o = 16; o > 0; o >>= 1) {
        s  += __shfl_xor_sync(0xffffffffu, s, o);
        s2 += __shfl_xor_sync(0xffffffffu, s2, o);
    }
    __shared__ float rs[8], rs2[8];
    __shared__ float sstat[2];
    if ((t & 31) == 0) { rs[t >> 5] = s; rs2[t >> 5] = s2; }
    __syncthreads();
    if (t == 0) {
        float S = 0.f, S2 = 0.f;
        #pragma unroll
        for (int w = 0; w < 8; w++) { S += rs[w]; S2 += rs2[w]; }
        const float mean = S * (1.0f / EE);
        const float var  = S2 * (1.0f / EE) - mean * mean;
        sstat[0] = mean;
        sstat[1] = rsqrtf(var + 1e-5f);
    }
    __syncthreads();
    const float mean = sstat[0], rstd = sstat[1];
    const float4 gv = ((const float4*)gamma)[t];
    const float4 bv = ((const float4*)beta)[t];
    float o0 = (v.x - mean) * rstd * gv.x + bv.x;
    float o1 = (v.y - mean) * rstd * gv.y + bv.y;
    float o2 = (v.z - mean) * rstd * gv.z + bv.z;
    float o3 = (v.w - mean) * rstd * gv.w + bv.w;
    uint32_t h0, l0, h1, l1;
    split2(o0, o1, h0, l0);
    split2(o2, o3, h1, l1);
    uint32_t* ph = (uint32_t*)(yh + (size_t)row * EE + 4 * t);
    uint32_t* pl = (uint32_t*)(yl + (size_t)row * EE + 4 * t);
    ph[0] = h0; ph[1] = h1;
    pl[0] = l0; pl[1] = l1;
}

// LayerNorm -> fp16 single
__global__ __launch_bounds__(256) void ln16_kernel(
    const float* __restrict__ x, const float* __restrict__ gamma,
    const float* __restrict__ beta, __half* __restrict__ y)
{
    const int row = blockIdx.x;
    const int t = threadIdx.x;
    const float4 v = ((const float4*)(x + (size_t)row * EE))[t];
    float s  = v.x + v.y + v.z + v.w;
    float s2 = fmaf(v.x, v.x, fmaf(v.y, v.y, fmaf(v.z, v.z, v.w * v.w)));
    #pragma unroll
    for (int o = 16; o > 0; o >>= 1) {
        s  += __shfl_xor_sync(0xffffffffu, s, o);
        s2 += __shfl_xor_sync(0xffffffffu, s2, o);
    }
    __shared__ float rs[8], rs2[8];
    __shared__ float sstat[2];
    if ((t & 31) == 0) { rs[t >> 5] = s; rs2[t >> 5] = s2; }
    __syncthreads();
    if (t == 0) {
        float S = 0.f, S2 = 0.f;
        #pragma unroll
        for (int w = 0; w < 8; w++) { S += rs[w]; S2 += rs2[w]; }
        const float mean = S * (1.0f / EE);
        const float var  = S2 * (1.0f / EE) - mean * mean;
        sstat[0] = mean;
        sstat[1] = rsqrtf(var + 1e-5f);
    }
    __syncthreads();
    const float mean = sstat[0], rstd = sstat[1];
    const float4 gv = ((const float4*)gamma)[t];
    const float4 bv = ((const float4*)beta)[t];
    const float o0 = (v.x - mean) * rstd * gv.x + bv.x;
    const float o1 = (v.y - mean) * rstd * gv.y + bv.y;
    const float o2 = (v.z - mean) * rstd * gv.z + bv.z;
    const float o3 = (v.w - mean) * rstd * gv.w + bv.w;
    uint32_t* p = (uint32_t*)(y + (size_t)row * EE + 4 * t);
    p[0] = pack_h2(o0, o1);
    p[1] = pack_h2(o2, o3);
}

// ---------------------------------------------------------------------------
// mma.sync bf16x3 GEMM, 128x128 tile, 2-stage cp.async, 2 CTAs/SM.
// ---------------------------------------------------------------------------
#define ROWB 80u
#define MATB 10240u
#define STGB 40960u
#define GSM_BYTES (2 * 40960)    // 81920

__global__ __launch_bounds__(256, 2) void gemm_tc(
    const __nv_bfloat16* __restrict__ Ah, const __nv_bfloat16* __restrict__ Al,
    const __nv_bfloat16* __restrict__ Bh, const __nv_bfloat16* __restrict__ Bl,
    const float* __restrict__ bias, const float* __restrict__ bias2, int nsplit,
    float* __restrict__ Cf, __nv_bfloat16* __restrict__ Ch,
    __nv_bfloat16* __restrict__ Cl, int M, int N, int K, float oscale)
{
    extern __shared__ unsigned char smem[];
    const uint32_t sbase = smem_u32(smem);
    const int tid = threadIdx.x;
    const int lane = tid & 31, wid = tid >> 5;
    const int wm = wid >> 2, wn = wid & 3;
    const int row0 = blockIdx.y * 128, col0 = blockIdx.x * 128;

    const __nv_bfloat16* gAh = Ah + (size_t)row0 * K;
    const __nv_bfloat16* gAl = Al + (size_t)row0 * K;
    const __nv_bfloat16* gBh = Bh + (size_t)col0 * K;
    const __nv_bfloat16* gBl = Bl + (size_t)col0 * K;
    const int nch = K >> 5;

    float acc[4][4][4];
    #pragma unroll
    for (int a = 0; a < 4; a++)
        #pragma unroll
        for (int b = 0; b < 4; b++)
            #pragma unroll
            for (int c = 0; c < 4; c++) acc[a][b][c] = 0.f;

    const uint32_t a_base = (uint32_t)(wm * 64 + (lane & 15)) * ROWB +
                            (((lane >> 4) << 3) << 1);
    const uint32_t b_base = (uint32_t)(wn * 32 + ((lane >> 4) << 3) + (lane & 7)) * ROWB +
                            ((((lane >> 3) & 1) << 3) << 1);

    auto load_chunk = [&](int ch, int s) {
        const int k0 = ch << 5;
        const uint32_t st = sbase + s * STGB;
        #pragma unroll
        for (int i = 0; i < 8; i++) {
            const __nv_bfloat16* src = (i < 2) ? gAh : (i < 4) ? gAl
                                     : (i < 6) ? gBh : gBl;
            const int rem = ((i & 1) << 8) + tid;
            const int r = rem >> 2, g = rem & 3;
            cpa16(st + (uint32_t)(i >> 1) * MATB + (uint32_t)r * ROWB + g * 16u,
                  src + (size_t)r * K + k0 + g * 8);
        }
    };

    auto compute_chunk = [&](int s) {
        const uint32_t st = sbase + s * STGB;
        #pragma unroll
        for (int ks = 0; ks < 32; ks += 16) {
            uint32_t aH[4][4], aL[4][4], bH[2][4], bL[2][4];
            const uint32_t ao = a_base + (ks << 1);
            #pragma unroll
            for (int mi = 0; mi < 4; mi++) {
                ldsm4(aH[mi], st + ao + (uint32_t)mi * 16 * ROWB);
                ldsm4(aL[mi], st + MATB + ao + (uint32_t)mi * 16 * ROWB);
            }
            const uint32_t bo = b_base + (ks << 1);
            #pragma unroll
            for (int p = 0; p < 2; p++) {
                ldsm4(bH[p], st + 2 * MATB + bo + (uint32_t)p * 16 * ROWB);
                ldsm4(bL[p], st + 3 * MATB + bo + (uint32_t)p * 16 * ROWB);
            }
            #pragma unroll
            for (int mi = 0; mi < 4; mi++)
                #pragma unroll
                for (int p = 0; p < 2; p++)
                    #pragma unroll
                    for (int h = 0; h < 2; h++) {
                        float* c = acc[mi][p * 2 + h];
                        mma16816(c, aH[mi], &bH[p][h * 2]);
                        mma16816(c, aH[mi], &bL[p][h * 2]);
                        mma16816(c, aL[mi], &bH[p][h * 2]);
                    }
        }
    };

    load_chunk(0, 0); CP_COMMIT();
    load_chunk(1, 1); CP_COMMIT();

    for (int ch = 0; ch < nch; ch++) {
        asm volatile("cp.async.wait_group 1;" ::: "memory");
        __syncthreads();
        compute_chunk(ch & 1);
        __syncthreads();
        if (ch + 2 < nch) load_chunk(ch + 2, ch & 1);
        CP_COMMIT();
    }
    asm volatile("cp.async.wait_group 0;" ::: "memory");

    // ---------------- epilogue ----------------
    const float* effb = (bias2 && col0 >= nsplit) ? (bias2 - nsplit) : bias;
    const int tr = lane >> 2, tc = (lane & 3) << 1;
    #pragma unroll
    for (int mi = 0; mi < 4; mi++) {
        #pragma unroll
        for (int ni = 0; ni < 4; ni++) {
            const int col = col0 + wn * 32 + ni * 8 + tc;
            const float2 bb = *(const float2*)&effb[col];
            #pragma unroll
            for (int hr = 0; hr < 2; hr++) {
                const int row = row0 + wm * 64 + mi * 16 + tr + hr * 8;
                float v0 = (acc[mi][ni][hr * 2 + 0] + bb.x) * oscale;
                float v1 = (acc[mi][ni][hr * 2 + 1] + bb.y) * oscale;
                const size_t goff = (size_t)row * N + col;
                if (Cf) {
                    *(float2*)&Cf[goff] = make_float2(v0, v1);
                } else {
                    uint32_t hp, lp;
                    split2(v0, v1, hp, lp);
                    *(uint32_t*)&Ch[goff] = hp;
                    *(uint32_t*)&Cl[goff] = lp;
                }
            }
        }
    }
}

// ---------------------------------------------------------------------------
// fp16 single-pass GEMM: D = A(fp16) @ B(fp16)^T.  128x128 tile, 2-stage,
// 2 CTAs/SM.  MLP only (weight+activation rounding ~1e-4 rel each).
// ---------------------------------------------------------------------------
#define H1STG 20480u              // A | B  (10240 each)
#define H1_B  10240u
#define GSM1_BYTES (2 * 20480)    // 40960

__global__ __launch_bounds__(256, 2) void gemm_fp16_1p(
    const __half* __restrict__ A, const __half* __restrict__ B,
    const float* __restrict__ bias, const float* __restrict__ res,
    float* __restrict__ Cf, __half* __restrict__ Ch,
    int M, int N, int K, int relu)
{
    extern __shared__ unsigned char smem[];
    const uint32_t sbase = smem_u32(smem);
    const int tid = threadIdx.x;
    const int lane = tid & 31, wid = tid >> 5;
    const int wm = wid >> 2, wn = wid & 3;
    const int row0 = blockIdx.y * 128, col0 = blockIdx.x * 128;

    const __half* gA = A + (size_t)row0 * K;
    const __half* gB = B + (size_t)col0 * K;
    const int nch = K >> 5;

    float acc[4][4][4];
    #pragma unroll
    for (int a = 0; a < 4; a++)
        #pragma unroll
        for (int b = 0; b < 4; b++)
            #pragma unroll
            for (int c = 0; c < 4; c++) acc[a][b][c] = 0.f;

    const uint32_t a_base = (uint32_t)(wm * 64 + (lane & 15)) * ROWB +
                            (((lane >> 4) << 3) << 1);
    const uint32_t b_base = (uint32_t)(wn * 32 + ((lane >> 4) << 3) + (lane & 7)) * ROWB +
                            ((((lane >> 3) & 1) << 3) << 1);

    auto load_chunk = [&](int ch, int s) {
        const int k0 = ch << 5;
        const uint32_t st = sbase + s * H1STG;
        #pragma unroll
        for (int i = 0; i < 4; i++) {
            const __half* src = (i < 2) ? gA : gB;
            const int rem = ((i & 1) << 8) + tid;
            const int r = rem >> 2, g = rem & 3;
            cpa16(st + (uint32_t)(i >> 1) * MATB + (uint32_t)r * ROWB + g * 16u,
                  src + (size_t)r * K + k0 + g * 8);
        }
    };

    auto compute_chunk = [&](int s) {
        const uint32_t st = sbase + s * H1STG;
        #pragma unroll
        for (int ks = 0; ks < 32; ks += 16) {
            uint32_t aF[4][4], bF[2][4];
            const uint32_t ao = a_base + (ks << 1);
            #pragma unroll
            for (int mi = 0; mi < 4; mi++)
                ldsm4(aF[mi], st + ao + (uint32_t)mi * 16 * ROWB);
            const uint32_t bo = b_base + (ks << 1);
            #pragma unroll
            for (int p = 0; p < 2; p++)
                ldsm4(bF[p], st + H1_B + bo + (uint32_t)p * 16 * ROWB);
            #pragma unroll
            for (int mi = 0; mi < 4; mi++)
                #pragma unroll
                for (int p = 0; p < 2; p++)
                    #pragma unroll
                    for (int h = 0; h < 2; h++)
                        mma16816h(acc[mi][p * 2 + h], aF[mi], &bF[p][h * 2]);
        }
    };

    load_chunk(0, 0); CP_COMMIT();
    load_chunk(1, 1); CP_COMMIT();

    for (int ch = 0; ch < nch; ch++) {
        asm volatile("cp.async.wait_group 1;" ::: "memory");
        __syncthreads();
        compute_chunk(ch & 1);
        __syncthreads();
        if (ch + 2 < nch) load_chunk(ch + 2, ch & 1);
        CP_COMMIT();
    }
    asm volatile("cp.async.wait_group 0;" ::: "memory");

    // ---------------- epilogue ----------------
    const int tr = lane >> 2, tc = (lane & 3) << 1;
    #pragma unroll
    for (int mi = 0; mi < 4; mi++) {
        #pragma unroll
        for (int ni = 0; ni < 4; ni++) {
            const int col = col0 + wn * 32 + ni * 8 + tc;
            const float2 bb = *(const float2*)&bias[col];
            #pragma unroll
            for (int hr = 0; hr < 2; hr++) {
                const int row = row0 + wm * 64 + mi * 16 + tr + hr * 8;
                float v0 = acc[mi][ni][hr * 2 + 0] + bb.x;
                float v1 = acc[mi][ni][hr * 2 + 1] + bb.y;
                if (relu) { v0 = fmaxf(v0, 0.f); v1 = fmaxf(v1, 0.f); }
                const size_t goff = (size_t)row * N + col;
                if (Cf) {
                    if (res) {
                        const float2 rv = *(const float2*)&res[goff];
                        v0 += rv.x; v1 += rv.y;
                    }
                    *(float2*)&Cf[goff] = make_float2(v0, v1);
                } else {
                    *(uint32_t*)&Ch[goff] = pack_h2(v0, v1);
                }
            }
        }
    }
}

// ---------------------------------------------------------------------------
// Tensor-core flash attention (causal), bf16x3 precision.
// BM=128, BN=64, 256 threads (8 warps, warp tile 16x64). Q pre-scaled 1/8.
// ---------------------------------------------------------------------------
#define AR 144u                   // bytes per smem row (64 bf16 + 8 pad)
#define AQMAT 18432u              // 128 rows * 144B
#define AKMAT 9216u               // 64 rows * 144B
#define ASTG (4 * AKMAT)          // Kh,Kl,Vh,Vl per stage = 36864
#define ATTN_SMEM (2 * AQMAT + 2 * ASTG)   // 110592

__global__ __launch_bounds__(256) void attn_mma(
    const __nv_bfloat16* __restrict__ Qh, const __nv_bfloat16* __restrict__ Ql,
    const __nv_bfloat16* __restrict__ KVh, const __nv_bfloat16* __restrict__ KVl,
    const float* __restrict__ inp, float* __restrict__ Out)
{
    extern __shared__ unsigned char smem[];
    const uint32_t sbase = smem_u32(smem);
    const int tid = threadIdx.x, lane = tid & 31, w = tid >> 5;
    const int qt = blockIdx.x, h = blockIdx.y, b = blockIdx.z;
    const int q0 = qt * 128;
    const int nt = 2 * qt + 2;                 // kv tiles (64 rows each)

    {
        const size_t ro = (size_t)(b * CC + q0) * EE + (size_t)h * 64;
        #pragma unroll
        for (int i = 0; i < 4; i++) {
            const int idx = i * 256 + tid;
            const int r = idx >> 3, g = idx & 7;
            const uint32_t d = sbase + (uint32_t)r * AR + g * 16u;
            const size_t so = ro + (size_t)r * EE + g * 8;
            cpa16(d, Qh + so);
            cpa16(d + AQMAT, Ql + so);
        }
    }
    CP_COMMIT();

    const size_t kvbase = (size_t)(b * CC) * KVS + (size_t)h * 64;
    auto load_kv = [&](int t, int s) {
        const uint32_t st = sbase + 2 * AQMAT + (uint32_t)s * ASTG;
        const size_t ro = kvbase + (size_t)(t * 64) * KVS;
        #pragma unroll
        for (int i = 0; i < 2; i++) {
            const int idx = i * 256 + tid;
            const int r = idx >> 3, g = idx & 7;
            const uint32_t d = st + (uint32_t)r * AR + g * 16u;
            const size_t so = ro + (size_t)r * KVS + g * 8;
            cpa16(d, KVh + so);
            cpa16(d + AKMAT, KVl + so);
            cpa16(d + 2 * AKMAT, KVh + so + 1024);
            cpa16(d + 3 * AKMAT, KVl + so + 1024);
        }
    };
    load_kv(0, 0); CP_COMMIT();

    float O[8][4];
    #pragma unroll
    for (int n = 0; n < 8; n++)
        #pragma unroll
        for (int j = 0; j < 4; j++) O[n][j] = 0.f;
    float m_lo = -1e30f, m_hi = -1e30f, l_lo = 0.f, l_hi = 0.f;
    uint32_t qHf[4][4], qLf[4][4];

    const int rowl = w * 16 + (lane >> 2);
    const int c0 = (lane & 3) << 1;

    for (int t = 0; t < nt; t++) {
        if (t + 1 < nt) load_kv(t + 1, (t + 1) & 1);
        CP_COMMIT();
        asm volatile("cp.async.wait_group 1;" ::: "memory");
        __syncthreads();

        const uint32_t sK = sbase + 2 * AQMAT + (uint32_t)(t & 1) * ASTG;
        const uint32_t sV = sK + 2 * AKMAT;

        if (t == 0) {
            const uint32_t qa = sbase + (uint32_t)(w * 16 + (lane & 15)) * AR +
                                (((lane >> 4) << 3) << 1);
            #pragma unroll
            for (int ks = 0; ks < 4; ks++) {
                ldsm4(qHf[ks], qa + ks * 32);
                ldsm4(qLf[ks], qa + AQMAT + ks * 32);
            }
        }

        float S[8][4];
        #pragma unroll
        for (int n = 0; n < 8; n++)
            #pragma unroll
            for (int j = 0; j < 4; j++) S[n][j] = 0.f;

        #pragma unroll
        for (int ks = 0; ks < 4; ks++) {
            #pragma unroll
            for (int np = 0; np < 4; np += 2) {
                const uint32_t kb0 = sK +
                    (uint32_t)(np * 16 + ((lane >> 4) << 3) + (lane & 7)) * AR +
                    ((((lane >> 3) & 1) << 3) << 1) + ks * 32;
                const uint32_t kb1 = kb0 + 16 * AR;
                uint32_t bh0[4], bl0[4], bh1[4], bl1[4];
                ldsm4(bh0, kb0); ldsm4(bl0, kb0 + AKMAT);
                ldsm4(bh1, kb1); ldsm4(bl1, kb1 + AKMAT);
                #pragma unroll
                for (int h2 = 0; h2 < 2; h2++) {
                    mma16816(S[np * 2 + h2],       qHf[ks], &bh0[h2 * 2]);
                    mma16816(S[(np + 1) * 2 + h2], qHf[ks], &bh1[h2 * 2]);
                }
                #pragma unroll
                for (int h2 = 0; h2 < 2; h2++) {
                    mma16816(S[np * 2 + h2],       qHf[ks], &bl0[h2 * 2]);
                    mma16816(S[(np + 1) * 2 + h2], qHf[ks], &bl1[h2 * 2]);
                }
                #pragma unroll
                for (int h2 = 0; h2 < 2; h2++) {
                    mma16816(S[np * 2 + h2],       qLf[ks], &bh0[h2 * 2]);
                    mma16816(S[(np + 1) * 2 + h2], qLf[ks], &bh1[h2 * 2]);
                }
            }
        }

        if (t >= 2 * qt) {
            const int colg0 = t * 64;
            const int rg_lo = q0 + rowl, rg_hi = rg_lo + 8;
            #pragma unroll
            for (int n = 0; n < 8; n++) {
                const int col = colg0 + n * 8 + c0;
                if (col > rg_lo)     S[n][0] = -1e30f;
                if (col + 1 > rg_lo) S[n][1] = -1e30f;
                if (col > rg_hi)     S[n][2] = -1e30f;
                if (col + 1 > rg_hi) S[n][3] = -1e30f;
            }
        }

        float mx0 = -1e30f, mx1 = -1e30f;
        #pragma unroll
        for (int n = 0; n < 8; n++) {
            mx0 = fmaxf(mx0, fmaxf(S[n][0], S[n][1]));
            mx1 = fmaxf(mx1, fmaxf(S[n][2], S[n][3]));
        }
        mx0 = fmaxf(mx0, __shfl_xor_sync(0xffffffffu, mx0, 1));
        mx0 = fmaxf(mx0, __shfl_xor_sync(0xffffffffu, mx0, 2));
        mx1 = fmaxf(mx1, __shfl_xor_sync(0xffffffffu, mx1, 1));
        mx1 = fmaxf(mx1, __shfl_xor_sync(0xffffffffu, mx1, 2));
        const float mn0 = fmaxf(m_lo, mx0), mn1 = fmaxf(m_hi, mx1);
        const float cr0 = __expf(m_lo - mn0), cr1 = __expf(m_hi - mn1);
        float s0 = 0.f, s1 = 0.f;
        #pragma unroll
        for (int n = 0; n < 8; n++) {
            S[n][0] = __expf(S[n][0] - mn0); s0 += S[n][0];
            S[n][1] = __expf(S[n][1] - mn0); s0 += S[n][1];
            S[n][2] = __expf(S[n][2] - mn1); s1 += S[n][2];
            S[n][3] = __expf(S[n][3] - mn1); s1 += S[n][3];
        }
        s0 += __shfl_xor_sync(0xffffffffu, s0, 1);
        s0 += __shfl_xor_sync(0xffffffffu, s0, 2);
        s1 += __shfl_xor_sync(0xffffffffu, s1, 1);
        s1 += __shfl_xor_sync(0xffffffffu, s1, 2);
        l_lo = l_lo * cr0 + s0; l_hi = l_hi * cr1 + s1;
        m_lo = mn0; m_hi = mn1;
        #pragma unroll
        for (int n = 0; n < 8; n++) {
            O[n][0] *= cr0; O[n][1] *= cr0;
            O[n][2] *= cr1; O[n][3] *= cr1;
        }

        uint32_t pH[4][4], pL[4][4];
        #pragma unroll
        for (int kk = 0; kk < 4; kk++) {
            split2(S[2 * kk][0],     S[2 * kk][1],     pH[kk][0], pL[kk][0]);
            split2(S[2 * kk][2],     S[2 * kk][3],     pH[kk][1], pL[kk][1]);
            split2(S[2 * kk + 1][0], S[2 * kk + 1][1], pH[kk][2], pL[kk][2]);
            split2(S[2 * kk + 1][2], S[2 * kk + 1][3], pH[kk][3], pL[kk][3]);
        }

        #pragma unroll
        for (int kk = 0; kk < 4; kk++) {
            #pragma unroll
            for (int np = 0; np < 4; np += 2) {
                const uint32_t va0 = sV +
                    (uint32_t)(kk * 16 + ((lane >> 3) & 1) * 8 + (lane & 7)) * AR +
                    ((np * 16 + ((lane >> 4) << 3)) << 1);
                const uint32_t va1 = va0 + 32;
                uint32_t vh0[4], vl0[4], vh1[4], vl1[4];
                ldsm4t(vh0, va0); ldsm4t(vl0, va0 + AKMAT);
                ldsm4t(vh1, va1); ldsm4t(vl1, va1 + AKMAT);
                #pragma unroll
                for (int h2 = 0; h2 < 2; h2++) {
                    mma16816(O[np * 2 + h2],       pH[kk], &vh0[h2 * 2]);
                    mma16816(O[(np + 1) * 2 + h2], pH[kk], &vh1[h2 * 2]);
                }
                #pragma unroll
                for (int h2 = 0; h2 < 2; h2++) {
                    mma16816(O[np * 2 + h2],       pH[kk], &vl0[h2 * 2]);
                    mma16816(O[(np + 1) * 2 + h2], pH[kk], &vl1[h2 * 2]);
                }
                #pragma unroll
                for (int h2 = 0; h2 < 2; h2++) {
                    mma16816(O[np * 2 + h2],       pL[kk], &vh0[h2 * 2]);
                    mma16816(O[(np + 1) * 2 + h2], pL[kk], &vh1[h2 * 2]);
                }
            }
        }
        __syncthreads();
    }

    const float inv0 = 1.0f / l_lo, inv1 = 1.0f / l_hi;
    const int gr0 = b * CC + q0 + rowl;
    #pragma unroll
    for (int n = 0; n < 8; n++) {
        const int col = h * 64 + n * 8 + c0;
        const size_t o0 = (size_t)gr0 * EE + col;
        const size_t o1 = o0 + (size_t)8 * EE;
        const float2 i0 = *(const float2*)&inp[o0];
        const float2 i1 = *(const float2*)&inp[o1];
        *(float2*)&Out[o0] = make_float2(i0.x + O[n][0] * inv0,
                                         i0.y + O[n][1] * inv0);
        *(float2*)&Out[o1] = make_float2(i1.x + O[n][2] * inv1,
                                         i1.y + O[n][3] * inv1);
    }
}

// ---------------------------------------------------------------------------
// kernel_launch
// ---------------------------------------------------------------------------
extern "C" void kernel_launch(void* const* d_in, const int* in_sizes, int n_in,
                              void* d_out, int out_size)
{
    const float* inputs = (const float*)d_in[0];
    const float* Wq     = (const float*)d_in[1];
    const float* bq     = (const float*)d_in[2];
    const float* Wk     = (const float*)d_in[3];
    const float* bk     = (const float*)d_in[4];
    const float* Wv     = (const float*)d_in[5];
    const float* bv     = (const float*)d_in[6];
    const float* g1     = (const float*)d_in[7];
    const float* beta1  = (const float*)d_in[8];
    const float* g2     = (const float*)d_in[9];
    const float* beta2  = (const float*)d_in[10];
    const float* W1     = (const float*)d_in[11];
    const float* bm1    = (const float*)d_in[12];
    const float* W2     = (const float*)d_in[13];
    const float* bm2    = (const float*)d_in[14];
    float* out = (float*)d_out;

    unsigned char* base = nullptr;
    cudaGetSymbolAddress((void**)&base, g_scratch);
    __nv_bfloat16* nh    = (__nv_bfloat16*)(base + OFF_NH);
    __nv_bfloat16* nl    = (__nv_bfloat16*)(base + OFF_NL);
    __half* hh           = (__half*)(base + OFF_HH);
    __nv_bfloat16* qh    = (__nv_bfloat16*)(base + OFF_QH);
    __nv_bfloat16* ql    = (__nv_bfloat16*)(base + OFF_QL);
    __nv_bfloat16* kvh   = (__nv_bfloat16*)(base + OFF_KVH);
    __nv_bfloat16* kvl   = (__nv_bfloat16*)(base + OFF_KVL);
    float* outbuf        = (float*)(base + OFF_OUTB);
    __half* m1           = (__half*)(base + OFF_M1H);
    __nv_bfloat16* WqTh  = (__nv_bfloat16*)(base + OFF_WQH);
    __nv_bfloat16* WqTl  = (__nv_bfloat16*)(base + OFF_WQL);
    __nv_bfloat16* WkvTh = (__nv_bfloat16*)(base + OFF_WKVH);
    __nv_bfloat16* WkvTl = (__nv_bfloat16*)(base + OFF_WKVL);
    __half* W1Th         = (__half*)(base + OFF_W1H);
    __half* W2Th         = (__half*)(base + OFF_W2H);

    cudaFuncSetAttribute(gemm_tc, cudaFuncAttributeMaxDynamicSharedMemorySize,
                         GSM_BYTES);
    cudaFuncSetAttribute(gemm_fp16_1p, cudaFuncAttributeMaxDynamicSharedMemorySize,
                         GSM1_BYTES);
    cudaFuncSetAttribute(attn_mma, cudaFuncAttributeMaxDynamicSharedMemorySize,
                         ATTN_SMEM);

    // Launch order keeps index 3 == gemm_tc (Q proj) for ncu capture.
    // 0: Wq prep
    tsplit_kernel<<<dim3(EE / 32, EE / 32), 256>>>(Wq, WqTh, WqTl, EE, EE);
    // 1: LN1 -> bf16 pair
    ln_kernel<<<MM, 256>>>(inputs, g1, beta1, nh, nl);
    // 2: Wk prep (rows 0..1023 of fused)
    tsplit_kernel<<<dim3(EE / 32, EE / 32), 256>>>(Wk, WkvTh, WkvTl, EE, EE);
    // 3: Q projection (profiled)
    gemm_tc<<<dim3(EE / 128, MM / 128), 256, GSM_BYTES>>>(
        nh, nl, WqTh, WqTl, bq, nullptr, 0, nullptr,
        qh, ql, MM, EE, EE, 0.125f);
    // 4: Wv prep (rows 1024..2047 of fused)
    tsplit_kernel<<<dim3(EE / 32, EE / 32), 256>>>(
        Wv, WkvTh + (size_t)1024 * EE, WkvTl + (size_t)1024 * EE, EE, EE);
    // 5: fused K|V projection (N=2048)
    gemm_tc<<<dim3(KVS / 128, MM / 128), 256, GSM_BYTES>>>(
        nh, nl, WkvTh, WkvTl, bk, bv, 1024, nullptr,
        kvh, kvl, MM, KVS, EE, 1.0f);
    // 6-7: MLP weight prep (fp16 single)
    t16_kernel<<<dim3(FF / 32, EE / 32), 256>>>(W1, W1Th, EE, FF);
    t16_kernel<<<dim3(EE / 32, FF / 32), 256>>>(W2, W2Th, FF, EE);
    // 8: tensor-core causal attention + residual
    attn_mma<<<dim3(CC / 128, HH, BB), 256, ATTN_SMEM>>>(
        qh, ql, kvh, kvl, inputs, outbuf);
    // 9: LN2 -> fp16 single
    ln16_kernel<<<MM, 256>>>(outbuf, g2, beta2, hh);
    // 10: MLP1 (relu) -> fp16 single, pure fp16 GEMM
    gemm_fp16_1p<<<dim3(FF / 128, MM / 128), 256, GSM1_BYTES>>>(
        hh, W1Th, bm1, nullptr, nullptr, m1, MM, FF, EE, 1);
    // 11: MLP2 + residual -> out, pure fp16 GEMM
    gemm_fp16_1p<<<dim3(EE / 128, MM / 128), 256, GSM1_BYTES>>>(
        m1, W2Th, bm2, outbuf, out, nullptr, MM, EE, FF, 0);
}

// round 12
// speedup vs baseline: 2.7070x; 1.6511x over previous
#include <cuda_runtime.h>
#include <cuda_bf16.h>
#include <cuda_fp16.h>
#include <cstdint>

// ---------------------------------------------------------------------------
// Problem constants
// ---------------------------------------------------------------------------
#define BB 4
#define CC 2048
#define EE 1024
#define HH 16
#define DD 64
#define MM (BB * CC)          // 8192 rows
#define FF (4 * EE)           // 4096 mlp hidden
#define KVS 2048              // fused K|V row stride

// ---------------------------------------------------------------------------
// Scratch
// ---------------------------------------------------------------------------
#define MB (1ull << 20)
__device__ __align__(256) unsigned char g_scratch[364 * MB];

#define OFF_N     (0 * MB)      // normed fp16 [MM, EE] (16MB)
#define OFF_H     (32 * MB)     // h fp16 [MM, EE] (16MB)
#define OFF_Q     (64 * MB)     // q fp16 [MM, EE] (16MB)
#define OFF_KV    (96 * MB)     // [MM, 2048] fp16 (32MB): K cols 0-1023, V 1024-2047
#define OFF_OUTB  (160 * MB)
#define OFF_M1    (192 * MB)    // m1 fp16 [MM, FF] (64MB)
#define OFF_WQ    (320 * MB)    // [1024,1024] fp16 (2MB)
#define OFF_WKV   (324 * MB)    // [2048,1024] fp16 (4MB)
#define OFF_W1    (332 * MB)    // [4096,1024] fp16 (8MB)
#define OFF_W2    (348 * MB)    // [1024,4096] fp16 (8MB)

// ---------------------------------------------------------------------------
// PTX helpers (baseline compute_103 only — no 'a' features)
// ---------------------------------------------------------------------------
__device__ __forceinline__ uint32_t smem_u32(const void* p) {
    uint32_t a;
    asm("{ .reg .u64 t; cvta.to.shared.u64 t, %1; cvt.u32.u64 %0, t; }"
        : "=r"(a) : "l"(p));
    return a;
}
__device__ __forceinline__ void cpa16(uint32_t d, const void* s) {
    asm volatile("cp.async.cg.shared.global [%0], [%1], 16;" :: "r"(d), "l"(s));
}
#define CP_COMMIT() asm volatile("cp.async.commit_group;" ::: "memory")

__device__ __forceinline__ void ldsm4(uint32_t* r, uint32_t addr) {
    asm volatile("ldmatrix.sync.aligned.m8n8.x4.shared.b16 {%0,%1,%2,%3}, [%4];"
                 : "=r"(r[0]), "=r"(r[1]), "=r"(r[2]), "=r"(r[3]) : "r"(addr));
}
__device__ __forceinline__ void ldsm4t(uint32_t* r, uint32_t addr) {
    asm volatile("ldmatrix.sync.aligned.m8n8.x4.trans.shared.b16 {%0,%1,%2,%3}, [%4];"
                 : "=r"(r[0]), "=r"(r[1]), "=r"(r[2]), "=r"(r[3]) : "r"(addr));
}
__device__ __forceinline__ void mma16816h(float* c, const uint32_t* a,
                                          const uint32_t* b) {
    asm volatile(
        "mma.sync.aligned.m16n8k16.row.col.f32.f16.f16.f32 "
        "{%0,%1,%2,%3}, {%4,%5,%6,%7}, {%8,%9}, {%0,%1,%2,%3};"
        : "+f"(c[0]), "+f"(c[1]), "+f"(c[2]), "+f"(c[3])
        : "r"(a[0]), "r"(a[1]), "r"(a[2]), "r"(a[3]), "r"(b[0]), "r"(b[1]));
}
__device__ __forceinline__ uint32_t pack_h2(float a, float b) {
    __half2 t = __floats2half2_rn(a, b);
    return *reinterpret_cast<uint32_t*>(&t);
}

// ---------------------------------------------------------------------------
// Weight transpose -> fp16:  W[K,N] fp32 -> T[N,K] fp16
// ---------------------------------------------------------------------------
__global__ __launch_bounds__(256) void t16_kernel(
    const float* __restrict__ W, __half* __restrict__ Th, int K, int N)
{
    __shared__ float t[32][33];
    const int n0 = blockIdx.x * 32, k0 = blockIdx.y * 32;
    const int tx = threadIdx.x & 31, ty = threadIdx.x >> 5;
    #pragma unroll
    for (int j = 0; j < 32; j += 8)
        t[ty + j][tx] = W[(size_t)(k0 + ty + j) * N + n0 + tx];
    __syncthreads();
    #pragma unroll
    for (int j = 0; j < 32; j += 8) {
        const float v = t[tx][ty + j];
        Th[(size_t)(n0 + ty + j) * K + k0 + tx] = __float2half_rn(v);
    }
}

// ---------------------------------------------------------------------------
// LayerNorm -> fp16 single
// ---------------------------------------------------------------------------
__global__ __launch_bounds__(256) void ln16_kernel(
    const float* __restrict__ x, const float* __restrict__ gamma,
    const float* __restrict__ beta, __half* __restrict__ y)
{
    const int row = blockIdx.x;
    const int t = threadIdx.x;
    const float4 v = ((const float4*)(x + (size_t)row * EE))[t];
    float s  = v.x + v.y + v.z + v.w;
    float s2 = fmaf(v.x, v.x, fmaf(v.y, v.y, fmaf(v.z, v.z, v.w * v.w)));
    #pragma unroll
    for (int o = 16; o > 0; o >>= 1) {
        s  += __shfl_xor_sync(0xffffffffu, s, o);
        s2 += __shfl_xor_sync(0xffffffffu, s2, o);
    }
    __shared__ float rs[8], rs2[8];
    __shared__ float sstat[2];
    if ((t & 31) == 0) { rs[t >> 5] = s; rs2[t >> 5] = s2; }
    __syncthreads();
    if (t == 0) {
        float S = 0.f, S2 = 0.f;
        #pragma unroll
        for (int w = 0; w < 8; w++) { S += rs[w]; S2 += rs2[w]; }
        const float mean = S * (1.0f / EE);
        const float var  = S2 * (1.0f / EE) - mean * mean;
        sstat[0] = mean;
        sstat[1] = rsqrtf(var + 1e-5f);
    }
    __syncthreads();
    const float mean = sstat[0], rstd = sstat[1];
    const float4 gv = ((const float4*)gamma)[t];
    const float4 bv = ((const float4*)beta)[t];
    const float o0 = (v.x - mean) * rstd * gv.x + bv.x;
    const float o1 = (v.y - mean) * rstd * gv.y + bv.y;
    const float o2 = (v.z - mean) * rstd * gv.z + bv.z;
    const float o3 = (v.w - mean) * rstd * gv.w + bv.w;
    uint32_t* p = (uint32_t*)(y + (size_t)row * EE + 4 * t);
    p[0] = pack_h2(o0, o1);
    p[1] = pack_h2(o2, o3);
}

// ---------------------------------------------------------------------------
// fp16 single-pass GEMM: D = A(fp16) @ B(fp16)^T.  128x128 tile, 2-stage,
// 2 CTAs/SM.  bias2/nsplit for fused KV; oscale for Q; fp16 or fp32 out.
// ---------------------------------------------------------------------------
#define ROWB 80u
#define MATB 10240u
#define H1STG 20480u              // A | B  (10240 each)
#define H1_B  10240u
#define GSM1_BYTES (2 * 20480)    // 40960

__global__ __launch_bounds__(256, 2) void gemm_fp16_1p(
    const __half* __restrict__ A, const __half* __restrict__ B,
    const float* __restrict__ bias, const float* __restrict__ bias2, int nsplit,
    const float* __restrict__ res, float* __restrict__ Cf,
    __half* __restrict__ Ch, int M, int N, int K, int relu, float oscale)
{
    extern __shared__ unsigned char smem[];
    const uint32_t sbase = smem_u32(smem);
    const int tid = threadIdx.x;
    const int lane = tid & 31, wid = tid >> 5;
    const int wm = wid >> 2, wn = wid & 3;
    const int row0 = blockIdx.y * 128, col0 = blockIdx.x * 128;

    const __half* gA = A + (size_t)row0 * K;
    const __half* gB = B + (size_t)col0 * K;
    const int nch = K >> 5;

    float acc[4][4][4];
    #pragma unroll
    for (int a = 0; a < 4; a++)
        #pragma unroll
        for (int b = 0; b < 4; b++)
            #pragma unroll
            for (int c = 0; c < 4; c++) acc[a][b][c] = 0.f;

    const uint32_t a_base = (uint32_t)(wm * 64 + (lane & 15)) * ROWB +
                            (((lane >> 4) << 3) << 1);
    const uint32_t b_base = (uint32_t)(wn * 32 + ((lane >> 4) << 3) + (lane & 7)) * ROWB +
                            ((((lane >> 3) & 1) << 3) << 1);

    auto load_chunk = [&](int ch, int s) {
        const int k0 = ch << 5;
        const uint32_t st = sbase + s * H1STG;
        #pragma unroll
        for (int i = 0; i < 4; i++) {
            const __half* src = (i < 2) ? gA : gB;
            const int rem = ((i & 1) << 8) + tid;
            const int r = rem >> 2, g = rem & 3;
            cpa16(st + (uint32_t)(i >> 1) * MATB + (uint32_t)r * ROWB + g * 16u,
                  src + (size_t)r * K + k0 + g * 8);
        }
    };

    auto compute_chunk = [&](int s) {
        const uint32_t st = sbase + s * H1STG;
        #pragma unroll
        for (int ks = 0; ks < 32; ks += 16) {
            uint32_t aF[4][4], bF[2][4];
            const uint32_t ao = a_base + (ks << 1);
            #pragma unroll
            for (int mi = 0; mi < 4; mi++)
                ldsm4(aF[mi], st + ao + (uint32_t)mi * 16 * ROWB);
            const uint32_t bo = b_base + (ks << 1);
            #pragma unroll
            for (int p = 0; p < 2; p++)
                ldsm4(bF[p], st + H1_B + bo + (uint32_t)p * 16 * ROWB);
            #pragma unroll
            for (int mi = 0; mi < 4; mi++)
                #pragma unroll
                for (int p = 0; p < 2; p++)
                    #pragma unroll
                    for (int h = 0; h < 2; h++)
                        mma16816h(acc[mi][p * 2 + h], aF[mi], &bF[p][h * 2]);
        }
    };

    load_chunk(0, 0); CP_COMMIT();
    load_chunk(1, 1); CP_COMMIT();

    for (int ch = 0; ch < nch; ch++) {
        asm volatile("cp.async.wait_group 1;" ::: "memory");
        __syncthreads();
        compute_chunk(ch & 1);
        __syncthreads();
        if (ch + 2 < nch) load_chunk(ch + 2, ch & 1);
        CP_COMMIT();
    }
    asm volatile("cp.async.wait_group 0;" ::: "memory");

    // ---------------- epilogue ----------------
    const float* effb = (bias2 && col0 >= nsplit) ? (bias2 - nsplit) : bias;
    const int tr = lane >> 2, tc = (lane & 3) << 1;
    #pragma unroll
    for (int mi = 0; mi < 4; mi++) {
        #pragma unroll
        for (int ni = 0; ni < 4; ni++) {
            const int col = col0 + wn * 32 + ni * 8 + tc;
            const float2 bb = *(const float2*)&effb[col];
            #pragma unroll
            for (int hr = 0; hr < 2; hr++) {
                const int row = row0 + wm * 64 + mi * 16 + tr + hr * 8;
                float v0 = (acc[mi][ni][hr * 2 + 0] + bb.x) * oscale;
                float v1 = (acc[mi][ni][hr * 2 + 1] + bb.y) * oscale;
                if (relu) { v0 = fmaxf(v0, 0.f); v1 = fmaxf(v1, 0.f); }
                const size_t goff = (size_t)row * N + col;
                if (Cf) {
                    if (res) {
                        const float2 rv = *(const float2*)&res[goff];
                        v0 += rv.x; v1 += rv.y;
                    }
                    *(float2*)&Cf[goff] = make_float2(v0, v1);
                } else {
                    *(uint32_t*)&Ch[goff] = pack_h2(v0, v1);
                }
            }
        }
    }
}

// ---------------------------------------------------------------------------
// Tensor-core flash attention (causal), fp16 single-pass.
// BM=128, BN=64, 256 threads (8 warps, warp tile 16x64). Q pre-scaled 1/8.
// Q fp16 [M][EE] head h at cols h*64. K/V fused fp16 [M][2048].
// Out = inp + softmax(QK^T)V (fp32).
// ---------------------------------------------------------------------------
#define AR 144u                   // bytes per smem row (64 fp16 + 16 pad)
#define AQMAT 18432u              // 128 rows * 144B
#define AKMAT 9216u               // 64 rows * 144B
#define ASTG (2 * AKMAT)          // K, V per stage = 18432
#define ATTN_SMEM (AQMAT + 2 * ASTG)   // 55296

__global__ __launch_bounds__(256) void attn_mma(
    const __half* __restrict__ Q, const __half* __restrict__ KV,
    const float* __restrict__ inp, float* __restrict__ Out)
{
    extern __shared__ unsigned char smem[];
    const uint32_t sbase = smem_u32(smem);
    const int tid = threadIdx.x, lane = tid & 31, w = tid >> 5;
    const int qt = blockIdx.x, h = blockIdx.y, b = blockIdx.z;
    const int q0 = qt * 128;
    const int nt = 2 * qt + 2;                 // kv tiles (64 rows each)

    // ---- load Q tile (128 rows) ----
    {
        const size_t ro = (size_t)(b * CC + q0) * EE + (size_t)h * 64;
        #pragma unroll
        for (int i = 0; i < 4; i++) {
            const int idx = i * 256 + tid;
            const int r = idx >> 3, g = idx & 7;
            cpa16(sbase + (uint32_t)r * AR + g * 16u,
                  Q + ro + (size_t)r * EE + g * 8);
        }
    }
    CP_COMMIT();

    const size_t kvbase = (size_t)(b * CC) * KVS + (size_t)h * 64;
    auto load_kv = [&](int t, int s) {
        const uint32_t st = sbase + AQMAT + (uint32_t)s * ASTG;
        const size_t ro = kvbase + (size_t)(t * 64) * KVS;
        #pragma unroll
        for (int i = 0; i < 2; i++) {
            const int idx = i * 256 + tid;
            const int r = idx >> 3, g = idx & 7;
            const uint32_t d = st + (uint32_t)r * AR + g * 16u;
            const size_t so = ro + (size_t)r * KVS + g * 8;
            cpa16(d, KV + so);
            cpa16(d + AKMAT, KV + so + 1024);
        }
    };
    load_kv(0, 0); CP_COMMIT();

    float O[8][4];
    #pragma unroll
    for (int n = 0; n < 8; n++)
        #pragma unroll
        for (int j = 0; j < 4; j++) O[n][j] = 0.f;
    float m_lo = -1e30f, m_hi = -1e30f, l_lo = 0.f, l_hi = 0.f;
    uint32_t qF[4][4];

    const int rowl = w * 16 + (lane >> 2);     // local q row (lo); hi = +8
    const int c0 = (lane & 3) << 1;

    for (int t = 0; t < nt; t++) {
        if (t + 1 < nt) load_kv(t + 1, (t + 1) & 1);
        CP_COMMIT();
        asm volatile("cp.async.wait_group 1;" ::: "memory");
        __syncthreads();

        const uint32_t sK = sbase + AQMAT + (uint32_t)(t & 1) * ASTG;
        const uint32_t sV = sK + AKMAT;

        if (t == 0) {
            const uint32_t qa = sbase + (uint32_t)(w * 16 + (lane & 15)) * AR +
                                (((lane >> 4) << 3) << 1);
            #pragma unroll
            for (int ks = 0; ks < 4; ks++)
                ldsm4(qF[ks], qa + ks * 32);
        }

        // ---- S = Q @ K^T (single pass fp16) ----
        float S[8][4];
        #pragma unroll
        for (int n = 0; n < 8; n++)
            #pragma unroll
            for (int j = 0; j < 4; j++) S[n][j] = 0.f;

        #pragma unroll
        for (int ks = 0; ks < 4; ks++) {
            #pragma unroll
            for (int np = 0; np < 4; np += 2) {
                const uint32_t kb0 = sK +
                    (uint32_t)(np * 16 + ((lane >> 4) << 3) + (lane & 7)) * AR +
                    ((((lane >> 3) & 1) << 3) << 1) + ks * 32;
                const uint32_t kb1 = kb0 + 16 * AR;
                uint32_t bh0[4], bh1[4];
                ldsm4(bh0, kb0);
                ldsm4(bh1, kb1);
                #pragma unroll
                for (int h2 = 0; h2 < 2; h2++) {
                    mma16816h(S[np * 2 + h2],       qF[ks], &bh0[h2 * 2]);
                    mma16816h(S[(np + 1) * 2 + h2], qF[ks], &bh1[h2 * 2]);
                }
            }
        }

        // ---- causal mask (only tiles overlapping/above the diagonal) ----
        if (t >= 2 * qt) {
            const int colg0 = t * 64;
            const int rg_lo = q0 + rowl, rg_hi = rg_lo + 8;
            #pragma unroll
            for (int n = 0; n < 8; n++) {
                const int col = colg0 + n * 8 + c0;
                if (col > rg_lo)     S[n][0] = -1e30f;
                if (col + 1 > rg_lo) S[n][1] = -1e30f;
                if (col > rg_hi)     S[n][2] = -1e30f;
                if (col + 1 > rg_hi) S[n][3] = -1e30f;
            }
        }

        // ---- online softmax ----
        float mx0 = -1e30f, mx1 = -1e30f;
        #pragma unroll
        for (int n = 0; n < 8; n++) {
            mx0 = fmaxf(mx0, fmaxf(S[n][0], S[n][1]));
            mx1 = fmaxf(mx1, fmaxf(S[n][2], S[n][3]));
        }
        mx0 = fmaxf(mx0, __shfl_xor_sync(0xffffffffu, mx0, 1));
        mx0 = fmaxf(mx0, __shfl_xor_sync(0xffffffffu, mx0, 2));
        mx1 = fmaxf(mx1, __shfl_xor_sync(0xffffffffu, mx1, 1));
        mx1 = fmaxf(mx1, __shfl_xor_sync(0xffffffffu, mx1, 2));
        const float mn0 = fmaxf(m_lo, mx0), mn1 = fmaxf(m_hi, mx1);
        const float cr0 = __expf(m_lo - mn0), cr1 = __expf(m_hi - mn1);
        float s0 = 0.f, s1 = 0.f;
        #pragma unroll
        for (int n = 0; n < 8; n++) {
            S[n][0] = __expf(S[n][0] - mn0); s0 += S[n][0];
            S[n][1] = __expf(S[n][1] - mn0); s0 += S[n][1];
            S[n][2] = __expf(S[n][2] - mn1); s1 += S[n][2];
            S[n][3] = __expf(S[n][3] - mn1); s1 += S[n][3];
        }
        s0 += __shfl_xor_sync(0xffffffffu, s0, 1);
        s0 += __shfl_xor_sync(0xffffffffu, s0, 2);
        s1 += __shfl_xor_sync(0xffffffffu, s1, 1);
        s1 += __shfl_xor_sync(0xffffffffu, s1, 2);
        l_lo = l_lo * cr0 + s0; l_hi = l_hi * cr1 + s1;
        m_lo = mn0; m_hi = mn1;
        #pragma unroll
        for (int n = 0; n < 8; n++) {
            O[n][0] *= cr0; O[n][1] *= cr0;
            O[n][2] *= cr1; O[n][3] *= cr1;
        }

        // ---- P -> fp16 A-fragments (C-frag reuse) ----
        uint32_t pF[4][4];
        #pragma unroll
        for (int kk = 0; kk < 4; kk++) {
            pF[kk][0] = pack_h2(S[2 * kk][0],     S[2 * kk][1]);
            pF[kk][1] = pack_h2(S[2 * kk][2],     S[2 * kk][3]);
            pF[kk][2] = pack_h2(S[2 * kk + 1][0], S[2 * kk + 1][1]);
            pF[kk][3] = pack_h2(S[2 * kk + 1][2], S[2 * kk + 1][3]);
        }

        // ---- O += P @ V (single pass fp16, ldmatrix.trans for V) ----
        #pragma unroll
        for (int kk = 0; kk < 4; kk++) {
            #pragma unroll
            for (int np = 0; np < 4; np += 2) {
                const uint32_t va0 = sV +
                    (uint32_t)(kk * 16 + ((lane >> 3) & 1) * 8 + (lane & 7)) * AR +
                    ((np * 16 + ((lane >> 4) << 3)) << 1);
                const uint32_t va1 = va0 + 32;
                uint32_t vh0[4], vh1[4];
                ldsm4t(vh0, va0);
                ldsm4t(vh1, va1);
                #pragma unroll
                for (int h2 = 0; h2 < 2; h2++) {
                    mma16816h(O[np * 2 + h2],       pF[kk], &vh0[h2 * 2]);
                    mma16816h(O[(np + 1) * 2 + h2], pF[kk], &vh1[h2 * 2]);
                }
            }
        }
        __syncthreads();
    }

    // ---- finalize: /l, add residual, store fp32 ----
    const float inv0 = 1.0f / l_lo, inv1 = 1.0f / l_hi;
    const int gr0 = b * CC + q0 + rowl;
    #pragma unroll
    for (int n = 0; n < 8; n++) {
        const int col = h * 64 + n * 8 + c0;
        const size_t o0 = (size_t)gr0 * EE + col;
        const size_t o1 = o0 + (size_t)8 * EE;
        const float2 i0 = *(const float2*)&inp[o0];
        const float2 i1 = *(const float2*)&inp[o1];
        *(float2*)&Out[o0] = make_float2(i0.x + O[n][0] * inv0,
                                         i0.y + O[n][1] * inv0);
        *(float2*)&Out[o1] = make_float2(i1.x + O[n][2] * inv1,
                                         i1.y + O[n][3] * inv1);
    }
}

// ---------------------------------------------------------------------------
// kernel_launch
// ---------------------------------------------------------------------------
extern "C" void kernel_launch(void* const* d_in, const int* in_sizes, int n_in,
                              void* d_out, int out_size)
{
    const float* inputs = (const float*)d_in[0];
    const float* Wq     = (const float*)d_in[1];
    const float* bq     = (const float*)d_in[2];
    const float* Wk     = (const float*)d_in[3];
    const float* bk     = (const float*)d_in[4];
    const float* Wv     = (const float*)d_in[5];
    const float* bv     = (const float*)d_in[6];
    const float* g1     = (const float*)d_in[7];
    const float* beta1  = (const float*)d_in[8];
    const float* g2     = (const float*)d_in[9];
    const float* beta2  = (const float*)d_in[10];
    const float* W1     = (const float*)d_in[11];
    const float* bm1    = (const float*)d_in[12];
    const float* W2     = (const float*)d_in[13];
    const float* bm2    = (const float*)d_in[14];
    float* out = (float*)d_out;

    unsigned char* base = nullptr;
    cudaGetSymbolAddress((void**)&base, g_scratch);
    __half* nf     = (__half*)(base + OFF_N);
    __half* hf     = (__half*)(base + OFF_H);
    __half* qf     = (__half*)(base + OFF_Q);
    __half* kvf    = (__half*)(base + OFF_KV);
    float* outbuf  = (float*)(base + OFF_OUTB);
    __half* m1     = (__half*)(base + OFF_M1);
    __half* WqT    = (__half*)(base + OFF_WQ);
    __half* WkvT   = (__half*)(base + OFF_WKV);
    __half* W1T    = (__half*)(base + OFF_W1);
    __half* W2T    = (__half*)(base + OFF_W2);

    cudaFuncSetAttribute(gemm_fp16_1p, cudaFuncAttributeMaxDynamicSharedMemorySize,
                         GSM1_BYTES);
    cudaFuncSetAttribute(attn_mma, cudaFuncAttributeMaxDynamicSharedMemorySize,
                         ATTN_SMEM);

    // Launch order keeps index 3 == gemm_fp16_1p (Q proj) for ncu capture.
    // 0: Wq prep
    t16_kernel<<<dim3(EE / 32, EE / 32), 256>>>(Wq, WqT, EE, EE);
    // 1: LN1 -> fp16
    ln16_kernel<<<MM, 256>>>(inputs, g1, beta1, nf);
    // 2: Wk prep (rows 0..1023 of fused)
    t16_kernel<<<dim3(EE / 32, EE / 32), 256>>>(Wk, WkvT, EE, EE);
    // 3: Q projection, oscale=1/8 (profiled)
    gemm_fp16_1p<<<dim3(EE / 128, MM / 128), 256, GSM1_BYTES>>>(
        nf, WqT, bq, nullptr, 0, nullptr, nullptr, qf, MM, EE, EE, 0, 0.125f);
    // 4: Wv prep (rows 1024..2047 of fused)
    t16_kernel<<<dim3(EE / 32, EE / 32), 256>>>(
        Wv, WkvT + (size_t)1024 * EE, EE, EE);
    // 5: fused K|V projection (N=2048)
    gemm_fp16_1p<<<dim3(KVS / 128, MM / 128), 256, GSM1_BYTES>>>(
        nf, WkvT, bk, bv, 1024, nullptr, nullptr, kvf, MM, KVS, EE, 0, 1.0f);
    // 6-7: MLP weight prep
    t16_kernel<<<dim3(FF / 32, EE / 32), 256>>>(W1, W1T, EE, FF);
    t16_kernel<<<dim3(EE / 32, FF / 32), 256>>>(W2, W2T, FF, EE);
    // 8: fp16 causal attention + residual
    attn_mma<<<dim3(CC / 128, HH, BB), 256, ATTN_SMEM>>>(
        qf, kvf, inputs, outbuf);
    // 9: LN2 -> fp16
    ln16_kernel<<<MM, 256>>>(outbuf, g2, beta2, hf);
    // 10: MLP1 (relu) -> fp16
    gemm_fp16_1p<<<dim3(FF / 128, MM / 128), 256, GSM1_BYTES>>>(
        hf, W1T, bm1, nullptr, 0, nullptr, nullptr, m1, MM, FF, EE, 1, 1.0f);
    // 11: MLP2 + residual -> out
    gemm_fp16_1p<<<dim3(EE / 128, MM / 128), 256, GSM1_BYTES>>>(
        m1, W2T, bm2, nullptr, 0, outbuf, out, nullptr, MM, EE, FF, 0, 1.0f);
}

// round 13
// speedup vs baseline: 2.7864x; 1.0293x over previous
#include <cuda_runtime.h>
#include <cuda_bf16.h>
#include <cuda_fp16.h>
#include <cstdint>

// ---------------------------------------------------------------------------
// Problem constants
// ---------------------------------------------------------------------------
#define BB 4
#define CC 2048
#define EE 1024
#define HH 16
#define DD 64
#define MM (BB * CC)          // 8192 rows
#define FF (4 * EE)           // 4096 mlp hidden
#define KVS 2048              // fused K|V row stride

// ---------------------------------------------------------------------------
// Scratch
// ---------------------------------------------------------------------------
#define MB (1ull << 20)
__device__ __align__(256) unsigned char g_scratch[364 * MB];

#define OFF_N     (0 * MB)      // normed fp16 [MM, EE]
#define OFF_H     (32 * MB)     // h fp16 [MM, EE]
#define OFF_Q     (64 * MB)     // q fp16 [MM, EE]
#define OFF_KV    (96 * MB)     // [MM, 2048] fp16: K cols 0-1023, V 1024-2047
#define OFF_OUTB  (160 * MB)
#define OFF_M1    (192 * MB)    // m1 fp16 [MM, FF]
#define OFF_WQ    (320 * MB)
#define OFF_WKV   (324 * MB)
#define OFF_W1    (332 * MB)
#define OFF_W2    (348 * MB)

// ---------------------------------------------------------------------------
// PTX helpers (baseline compute_103 only — no 'a' features)
// ---------------------------------------------------------------------------
__device__ __forceinline__ uint32_t smem_u32(const void* p) {
    uint32_t a;
    asm("{ .reg .u64 t; cvta.to.shared.u64 t, %1; cvt.u32.u64 %0, t; }"
        : "=r"(a) : "l"(p));
    return a;
}
__device__ __forceinline__ void cpa16(uint32_t d, const void* s) {
    asm volatile("cp.async.cg.shared.global [%0], [%1], 16;" :: "r"(d), "l"(s));
}
#define CP_COMMIT() asm volatile("cp.async.commit_group;" ::: "memory")

__device__ __forceinline__ void ldsm4(uint32_t* r, uint32_t addr) {
    asm volatile("ldmatrix.sync.aligned.m8n8.x4.shared.b16 {%0,%1,%2,%3}, [%4];"
                 : "=r"(r[0]), "=r"(r[1]), "=r"(r[2]), "=r"(r[3]) : "r"(addr));
}
__device__ __forceinline__ void ldsm4t(uint32_t* r, uint32_t addr) {
    asm volatile("ldmatrix.sync.aligned.m8n8.x4.trans.shared.b16 {%0,%1,%2,%3}, [%4];"
                 : "=r"(r[0]), "=r"(r[1]), "=r"(r[2]), "=r"(r[3]) : "r"(addr));
}
__device__ __forceinline__ void mma16816h(float* c, const uint32_t* a,
                                          const uint32_t* b) {
    asm volatile(
        "mma.sync.aligned.m16n8k16.row.col.f32.f16.f16.f32 "
        "{%0,%1,%2,%3}, {%4,%5,%6,%7}, {%8,%9}, {%0,%1,%2,%3};"
        : "+f"(c[0]), "+f"(c[1]), "+f"(c[2]), "+f"(c[3])
        : "r"(a[0]), "r"(a[1]), "r"(a[2]), "r"(a[3]), "r"(b[0]), "r"(b[1]));
}
__device__ __forceinline__ uint32_t pack_h2(float a, float b) {
    __half2 t = __floats2half2_rn(a, b);
    return *reinterpret_cast<uint32_t*>(&t);
}

// ---------------------------------------------------------------------------
// Weight transpose -> fp16:  W[K,N] fp32 -> T[N,K] fp16
// ---------------------------------------------------------------------------
__global__ __launch_bounds__(256) void t16_kernel(
    const float* __restrict__ W, __half* __restrict__ Th, int K, int N)
{
    __shared__ float t[32][33];
    const int n0 = blockIdx.x * 32, k0 = blockIdx.y * 32;
    const int tx = threadIdx.x & 31, ty = threadIdx.x >> 5;
    #pragma unroll
    for (int j = 0; j < 32; j += 8)
        t[ty + j][tx] = W[(size_t)(k0 + ty + j) * N + n0 + tx];
    __syncthreads();
    #pragma unroll
    for (int j = 0; j < 32; j += 8) {
        const float v = t[tx][ty + j];
        Th[(size_t)(n0 + ty + j) * K + k0 + tx] = __float2half_rn(v);
    }
}

// ---------------------------------------------------------------------------
// LayerNorm -> fp16 single
// ---------------------------------------------------------------------------
__global__ __launch_bounds__(256) void ln16_kernel(
    const float* __restrict__ x, const float* __restrict__ gamma,
    const float* __restrict__ beta, __half* __restrict__ y)
{
    const int row = blockIdx.x;
    const int t = threadIdx.x;
    const float4 v = ((const float4*)(x + (size_t)row * EE))[t];
    float s  = v.x + v.y + v.z + v.w;
    float s2 = fmaf(v.x, v.x, fmaf(v.y, v.y, fmaf(v.z, v.z, v.w * v.w)));
    #pragma unroll
    for (int o = 16; o > 0; o >>= 1) {
        s  += __shfl_xor_sync(0xffffffffu, s, o);
        s2 += __shfl_xor_sync(0xffffffffu, s2, o);
    }
    __shared__ float rs[8], rs2[8];
    __shared__ float sstat[2];
    if ((t & 31) == 0) { rs[t >> 5] = s; rs2[t >> 5] = s2; }
    __syncthreads();
    if (t == 0) {
        float S = 0.f, S2 = 0.f;
        #pragma unroll
        for (int w = 0; w < 8; w++) { S += rs[w]; S2 += rs2[w]; }
        const float mean = S * (1.0f / EE);
        const float var  = S2 * (1.0f / EE) - mean * mean;
        sstat[0] = mean;
        sstat[1] = rsqrtf(var + 1e-5f);
    }
    __syncthreads();
    const float mean = sstat[0], rstd = sstat[1];
    const float4 gv = ((const float4*)gamma)[t];
    const float4 bv = ((const float4*)beta)[t];
    const float o0 = (v.x - mean) * rstd * gv.x + bv.x;
    const float o1 = (v.y - mean) * rstd * gv.y + bv.y;
    const float o2 = (v.z - mean) * rstd * gv.z + bv.z;
    const float o3 = (v.w - mean) * rstd * gv.w + bv.w;
    uint32_t* p = (uint32_t*)(y + (size_t)row * EE + 4 * t);
    p[0] = pack_h2(o0, o1);
    p[1] = pack_h2(o2, o3);
}

// ---------------------------------------------------------------------------
// fp16 single-pass GEMM: D = A(fp16) @ B(fp16)^T.  128x128 tile,
// K-chunk 64, 3-stage cp.async, single __syncthreads per chunk, 2 CTAs/SM.
// ---------------------------------------------------------------------------
#define G64ROWB 144u               // 64 halfs + 8 pad = 144B per row
#define G64MAT  18432u             // 128 rows * 144B
#define G64STG  36864u             // A | B
#define GSM1_BYTES (3 * 36864)     // 110592

__global__ __launch_bounds__(256, 2) void gemm_fp16_1p(
    const __half* __restrict__ A, const __half* __restrict__ B,
    const float* __restrict__ bias, const float* __restrict__ bias2, int nsplit,
    const float* __restrict__ res, float* __restrict__ Cf,
    __half* __restrict__ Ch, int M, int N, int K, int relu, float oscale)
{
    extern __shared__ unsigned char smem[];
    const uint32_t sbase = smem_u32(smem);
    const int tid = threadIdx.x;
    const int lane = tid & 31, wid = tid >> 5;
    const int wm = wid >> 2, wn = wid & 3;
    const int row0 = blockIdx.y * 128, col0 = blockIdx.x * 128;

    const __half* gA = A + (size_t)row0 * K;
    const __half* gB = B + (size_t)col0 * K;
    const int nch = K >> 6;              // K-chunk 64

    float acc[4][4][4];
    #pragma unroll
    for (int a = 0; a < 4; a++)
        #pragma unroll
        for (int b = 0; b < 4; b++)
            #pragma unroll
            for (int c = 0; c < 4; c++) acc[a][b][c] = 0.f;

    const uint32_t a_base = (uint32_t)(wm * 64 + (lane & 15)) * G64ROWB +
                            (((lane >> 4) << 3) << 1);
    const uint32_t b_base = (uint32_t)(wn * 32 + ((lane >> 4) << 3) + (lane & 7)) * G64ROWB +
                            ((((lane >> 3) & 1) << 3) << 1);

    // 8 cp.async per thread per chunk: 4 for A (128 rows x 8 groups), 4 for B
    auto load_chunk = [&](int ch, int s) {
        const int k0 = ch << 6;
        const uint32_t st = sbase + (uint32_t)s * G64STG;
        #pragma unroll
        for (int i = 0; i < 4; i++) {
            const int idx = i * 256 + tid;
            const int r = idx >> 3, g = idx & 7;
            const uint32_t d = (uint32_t)r * G64ROWB + g * 16u;
            const size_t so = (size_t)r * K + k0 + g * 8;
            cpa16(st + d, gA + so);
            cpa16(st + G64MAT + d, gB + so);
        }
    };

    auto compute_chunk = [&](int s) {
        const uint32_t st = sbase + (uint32_t)s * G64STG;
        #pragma unroll
        for (int ks = 0; ks < 4; ks++) {            // 4 x k16 per chunk
            uint32_t aF[4][4], bF[2][4];
            const uint32_t ao = a_base + (ks << 5);  // ks * 32 bytes
            #pragma unroll
            for (int mi = 0; mi < 4; mi++)
                ldsm4(aF[mi], st + ao + (uint32_t)mi * 16 * G64ROWB);
            const uint32_t bo = b_base + (ks << 5);
            #pragma unroll
            for (int p = 0; p < 2; p++)
                ldsm4(bF[p], st + G64MAT + bo + (uint32_t)p * 16 * G64ROWB);
            #pragma unroll
            for (int mi = 0; mi < 4; mi++)
                #pragma unroll
                for (int p = 0; p < 2; p++)
                    #pragma unroll
                    for (int h = 0; h < 2; h++)
                        mma16816h(acc[mi][p * 2 + h], aF[mi], &bF[p][h * 2]);
        }
    };

    // prologue: chunks 0 and 1 in flight
    load_chunk(0, 0); CP_COMMIT();
    load_chunk(1, 1); CP_COMMIT();

    for (int ch = 0; ch < nch; ch++) {
        asm volatile("cp.async.wait_group 1;" ::: "memory");
        __syncthreads();
        // issue next-next chunk into the stage freed at iter ch-1
        if (ch + 2 < nch) {
            load_chunk(ch + 2, (ch + 2) % 3);
            CP_COMMIT();
        } else {
            CP_COMMIT();
        }
        compute_chunk(ch % 3);
    }
    asm volatile("cp.async.wait_group 0;" ::: "memory");

    // ---------------- epilogue ----------------
    const float* effb = (bias2 && col0 >= nsplit) ? (bias2 - nsplit) : bias;
    const int tr = lane >> 2, tc = (lane & 3) << 1;
    #pragma unroll
    for (int mi = 0; mi < 4; mi++) {
        #pragma unroll
        for (int ni = 0; ni < 4; ni++) {
            const int col = col0 + wn * 32 + ni * 8 + tc;
            const float2 bb = *(const float2*)&effb[col];
            #pragma unroll
            for (int hr = 0; hr < 2; hr++) {
                const int row = row0 + wm * 64 + mi * 16 + tr + hr * 8;
                float v0 = (acc[mi][ni][hr * 2 + 0] + bb.x) * oscale;
                float v1 = (acc[mi][ni][hr * 2 + 1] + bb.y) * oscale;
                if (relu) { v0 = fmaxf(v0, 0.f); v1 = fmaxf(v1, 0.f); }
                const size_t goff = (size_t)row * N + col;
                if (Cf) {
                    if (res) {
                        const float2 rv = *(const float2*)&res[goff];
                        v0 += rv.x; v1 += rv.y;
                    }
                    *(float2*)&Cf[goff] = make_float2(v0, v1);
                } else {
                    *(uint32_t*)&Ch[goff] = pack_h2(v0, v1);
                }
            }
        }
    }
}

// ---------------------------------------------------------------------------
// Tensor-core flash attention (causal), fp16 single-pass.
// BM=128, BN=64, 256 threads (8 warps, warp tile 16x64). Q pre-scaled 1/8.
// ---------------------------------------------------------------------------
#define AR 144u                   // bytes per smem row (64 fp16 + pad)
#define AQMAT 18432u              // 128 rows * 144B
#define AKMAT 9216u               // 64 rows * 144B
#define ASTG (2 * AKMAT)          // K, V per stage = 18432
#define ATTN_SMEM (AQMAT + 2 * ASTG)   // 55296

__global__ __launch_bounds__(256) void attn_mma(
    const __half* __restrict__ Q, const __half* __restrict__ KV,
    const float* __restrict__ inp, float* __restrict__ Out)
{
    extern __shared__ unsigned char smem[];
    const uint32_t sbase = smem_u32(smem);
    const int tid = threadIdx.x, lane = tid & 31, w = tid >> 5;
    const int qt = blockIdx.x, h = blockIdx.y, b = blockIdx.z;
    const int q0 = qt * 128;
    const int nt = 2 * qt + 2;                 // kv tiles (64 rows each)

    // ---- load Q tile (128 rows) ----
    {
        const size_t ro = (size_t)(b * CC + q0) * EE + (size_t)h * 64;
        #pragma unroll
        for (int i = 0; i < 4; i++) {
            const int idx = i * 256 + tid;
            const int r = idx >> 3, g = idx & 7;
            cpa16(sbase + (uint32_t)r * AR + g * 16u,
                  Q + ro + (size_t)r * EE + g * 8);
        }
    }
    CP_COMMIT();

    const size_t kvbase = (size_t)(b * CC) * KVS + (size_t)h * 64;
    auto load_kv = [&](int t, int s) {
        const uint32_t st = sbase + AQMAT + (uint32_t)s * ASTG;
        const size_t ro = kvbase + (size_t)(t * 64) * KVS;
        #pragma unroll
        for (int i = 0; i < 2; i++) {
            const int idx = i * 256 + tid;
            const int r = idx >> 3, g = idx & 7;
            const uint32_t d = st + (uint32_t)r * AR + g * 16u;
            const size_t so = ro + (size_t)r * KVS + g * 8;
            cpa16(d, KV + so);
            cpa16(d + AKMAT, KV + so + 1024);
        }
    };
    load_kv(0, 0); CP_COMMIT();

    float O[8][4];
    #pragma unroll
    for (int n = 0; n < 8; n++)
        #pragma unroll
        for (int j = 0; j < 4; j++) O[n][j] = 0.f;
    float m_lo = -1e30f, m_hi = -1e30f, l_lo = 0.f, l_hi = 0.f;
    uint32_t qF[4][4];

    const int rowl = w * 16 + (lane >> 2);     // local q row (lo); hi = +8
    const int c0 = (lane & 3) << 1;

    for (int t = 0; t < nt; t++) {
        if (t + 1 < nt) load_kv(t + 1, (t + 1) & 1);
        CP_COMMIT();
        asm volatile("cp.async.wait_group 1;" ::: "memory");
        __syncthreads();

        const uint32_t sK = sbase + AQMAT + (uint32_t)(t & 1) * ASTG;
        const uint32_t sV = sK + AKMAT;

        if (t == 0) {
            const uint32_t qa = sbase + (uint32_t)(w * 16 + (lane & 15)) * AR +
                                (((lane >> 4) << 3) << 1);
            #pragma unroll
            for (int ks = 0; ks < 4; ks++)
                ldsm4(qF[ks], qa + ks * 32);
        }

        // ---- S = Q @ K^T ----
        float S[8][4];
        #pragma unroll
        for (int n = 0; n < 8; n++)
            #pragma unroll
            for (int j = 0; j < 4; j++) S[n][j] = 0.f;

        #pragma unroll
        for (int ks = 0; ks < 4; ks++) {
            #pragma unroll
            for (int np = 0; np < 4; np += 2) {
                const uint32_t kb0 = sK +
                    (uint32_t)(np * 16 + ((lane >> 4) << 3) + (lane & 7)) * AR +
                    ((((lane >> 3) & 1) << 3) << 1) + ks * 32;
                const uint32_t kb1 = kb0 + 16 * AR;
                uint32_t bh0[4], bh1[4];
                ldsm4(bh0, kb0);
                ldsm4(bh1, kb1);
                #pragma unroll
                for (int h2 = 0; h2 < 2; h2++) {
                    mma16816h(S[np * 2 + h2],       qF[ks], &bh0[h2 * 2]);
                    mma16816h(S[(np + 1) * 2 + h2], qF[ks], &bh1[h2 * 2]);
                }
            }
        }

        // ---- causal mask (only tiles overlapping/above the diagonal) ----
        if (t >= 2 * qt) {
            const int colg0 = t * 64;
            const int rg_lo = q0 + rowl, rg_hi = rg_lo + 8;
            #pragma unroll
            for (int n = 0; n < 8; n++) {
                const int col = colg0 + n * 8 + c0;
                if (col > rg_lo)     S[n][0] = -1e30f;
                if (col + 1 > rg_lo) S[n][1] = -1e30f;
                if (col > rg_hi)     S[n][2] = -1e30f;
                if (col + 1 > rg_hi) S[n][3] = -1e30f;
            }
        }

        // ---- online softmax ----
        float mx0 = -1e30f, mx1 = -1e30f;
        #pragma unroll
        for (int n = 0; n < 8; n++) {
            mx0 = fmaxf(mx0, fmaxf(S[n][0], S[n][1]));
            mx1 = fmaxf(mx1, fmaxf(S[n][2], S[n][3]));
        }
        mx0 = fmaxf(mx0, __shfl_xor_sync(0xffffffffu, mx0, 1));
        mx0 = fmaxf(mx0, __shfl_xor_sync(0xffffffffu, mx0, 2));
        mx1 = fmaxf(mx1, __shfl_xor_sync(0xffffffffu, mx1, 1));
        mx1 = fmaxf(mx1, __shfl_xor_sync(0xffffffffu, mx1, 2));
        const float mn0 = fmaxf(m_lo, mx0), mn1 = fmaxf(m_hi, mx1);
        const float cr0 = __expf(m_lo - mn0), cr1 = __expf(m_hi - mn1);
        float s0 = 0.f, s1 = 0.f;
        #pragma unroll
        for (int n = 0; n < 8; n++) {
            S[n][0] = __expf(S[n][0] - mn0); s0 += S[n][0];
            S[n][1] = __expf(S[n][1] - mn0); s0 += S[n][1];
            S[n][2] = __expf(S[n][2] - mn1); s1 += S[n][2];
            S[n][3] = __expf(S[n][3] - mn1); s1 += S[n][3];
        }
        s0 += __shfl_xor_sync(0xffffffffu, s0, 1);
        s0 += __shfl_xor_sync(0xffffffffu, s0, 2);
        s1 += __shfl_xor_sync(0xffffffffu, s1, 1);
        s1 += __shfl_xor_sync(0xffffffffu, s1, 2);
        l_lo = l_lo * cr0 + s0; l_hi = l_hi * cr1 + s1;
        m_lo = mn0; m_hi = mn1;
        #pragma unroll
        for (int n = 0; n < 8; n++) {
            O[n][0] *= cr0; O[n][1] *= cr0;
            O[n][2] *= cr1; O[n][3] *= cr1;
        }

        // ---- P -> fp16 A-fragments (C-frag reuse) ----
        uint32_t pF[4][4];
        #pragma unroll
        for (int kk = 0; kk < 4; kk++) {
            pF[kk][0] = pack_h2(S[2 * kk][0],     S[2 * kk][1]);
            pF[kk][1] = pack_h2(S[2 * kk][2],     S[2 * kk][3]);
            pF[kk][2] = pack_h2(S[2 * kk + 1][0], S[2 * kk + 1][1]);
            pF[kk][3] = pack_h2(S[2 * kk + 1][2], S[2 * kk + 1][3]);
        }

        // ---- O += P @ V (ldmatrix.trans for V) ----
        #pragma unroll
        for (int kk = 0; kk < 4; kk++) {
            #pragma unroll
            for (int np = 0; np < 4; np += 2) {
                const uint32_t va0 = sV +
                    (uint32_t)(kk * 16 + ((lane >> 3) & 1) * 8 + (lane & 7)) * AR +
                    ((np * 16 + ((lane >> 4) << 3)) << 1);
                const uint32_t va1 = va0 + 32;
                uint32_t vh0[4], vh1[4];
                ldsm4t(vh0, va0);
                ldsm4t(vh1, va1);
                #pragma unroll
                for (int h2 = 0; h2 < 2; h2++) {
                    mma16816h(O[np * 2 + h2],       pF[kk], &vh0[h2 * 2]);
                    mma16816h(O[(np + 1) * 2 + h2], pF[kk], &vh1[h2 * 2]);
                }
            }
        }
        __syncthreads();
    }

    // ---- finalize: /l, add residual, store fp32 ----
    const float inv0 = 1.0f / l_lo, inv1 = 1.0f / l_hi;
    const int gr0 = b * CC + q0 + rowl;
    #pragma unroll
    for (int n = 0; n < 8; n++) {
        const int col = h * 64 + n * 8 + c0;
        const size_t o0 = (size_t)gr0 * EE + col;
        const size_t o1 = o0 + (size_t)8 * EE;
        const float2 i0 = *(const float2*)&inp[o0];
        const float2 i1 = *(const float2*)&inp[o1];
        *(float2*)&Out[o0] = make_float2(i0.x + O[n][0] * inv0,
                                         i0.y + O[n][1] * inv0);
        *(float2*)&Out[o1] = make_float2(i1.x + O[n][2] * inv1,
                                         i1.y + O[n][3] * inv1);
    }
}

// ---------------------------------------------------------------------------
// kernel_launch
// ---------------------------------------------------------------------------
extern "C" void kernel_launch(void* const* d_in, const int* in_sizes, int n_in,
                              void* d_out, int out_size)
{
    const float* inputs = (const float*)d_in[0];
    const float* Wq     = (const float*)d_in[1];
    const float* bq     = (const float*)d_in[2];
    const float* Wk     = (const float*)d_in[3];
    const float* bk     = (const float*)d_in[4];
    const float* Wv     = (const float*)d_in[5];
    const float* bv     = (const float*)d_in[6];
    const float* g1     = (const float*)d_in[7];
    const float* beta1  = (const float*)d_in[8];
    const float* g2     = (const float*)d_in[9];
    const float* beta2  = (const float*)d_in[10];
    const float* W1     = (const float*)d_in[11];
    const float* bm1    = (const float*)d_in[12];
    const float* W2     = (const float*)d_in[13];
    const float* bm2    = (const float*)d_in[14];
    float* out = (float*)d_out;

    unsigned char* base = nullptr;
    cudaGetSymbolAddress((void**)&base, g_scratch);
    __half* nf     = (__half*)(base + OFF_N);
    __half* hf     = (__half*)(base + OFF_H);
    __half* qf     = (__half*)(base + OFF_Q);
    __half* kvf    = (__half*)(base + OFF_KV);
    float* outbuf  = (float*)(base + OFF_OUTB);
    __half* m1     = (__half*)(base + OFF_M1);
    __half* WqT    = (__half*)(base + OFF_WQ);
    __half* WkvT   = (__half*)(base + OFF_WKV);
    __half* W1T    = (__half*)(base + OFF_W1);
    __half* W2T    = (__half*)(base + OFF_W2);

    cudaFuncSetAttribute(gemm_fp16_1p, cudaFuncAttributeMaxDynamicSharedMemorySize,
                         GSM1_BYTES);
    cudaFuncSetAttribute(attn_mma, cudaFuncAttributeMaxDynamicSharedMemorySize,
                         ATTN_SMEM);

    // Launch order keeps index 3 == gemm_fp16_1p (Q proj) for ncu capture.
    // 0: Wq prep
    t16_kernel<<<dim3(EE / 32, EE / 32), 256>>>(Wq, WqT, EE, EE);
    // 1: LN1 -> fp16
    ln16_kernel<<<MM, 256>>>(inputs, g1, beta1, nf);
    // 2: Wk prep (rows 0..1023 of fused)
    t16_kernel<<<dim3(EE / 32, EE / 32), 256>>>(Wk, WkvT, EE, EE);
    // 3: Q projection, oscale=1/8 (profiled)
    gemm_fp16_1p<<<dim3(EE / 128, MM / 128), 256, GSM1_BYTES>>>(
        nf, WqT, bq, nullptr, 0, nullptr, nullptr, qf, MM, EE, EE, 0, 0.125f);
    // 4: Wv prep (rows 1024..2047 of fused)
    t16_kernel<<<dim3(EE / 32, EE / 32), 256>>>(
        Wv, WkvT + (size_t)1024 * EE, EE, EE);
    // 5: fused K|V projection (N=2048)
    gemm_fp16_1p<<<dim3(KVS / 128, MM / 128), 256, GSM1_BYTES>>>(
        nf, WkvT, bk, bv, 1024, nullptr, nullptr, kvf, MM, KVS, EE, 0, 1.0f);
    // 6-7: MLP weight prep
    t16_kernel<<<dim3(FF / 32, EE / 32), 256>>>(W1, W1T, EE, FF);
    t16_kernel<<<dim3(EE / 32, FF / 32), 256>>>(W2, W2T, FF, EE);
    // 8: fp16 causal attention + residual
    attn_mma<<<dim3(CC / 128, HH, BB), 256, ATTN_SMEM>>>(
        qf, kvf, inputs, outbuf);
    // 9: LN2 -> fp16
    ln16_kernel<<<MM, 256>>>(outbuf, g2, beta2, hf);
    // 10: MLP1 (relu) -> fp16
    gemm_fp16_1p<<<dim3(FF / 128, MM / 128), 256, GSM1_BYTES>>>(
        hf, W1T, bm1, nullptr, 0, nullptr, nullptr, m1, MM, FF, EE, 1, 1.0f);
    // 11: MLP2 + residual -> out
    gemm_fp16_1p<<<dim3(EE / 128, MM / 128), 256, GSM1_BYTES>>>(
        m1, W2T, bm2, nullptr, 0, outbuf, out, nullptr, MM, EE, FF, 0, 1.0f);
}

// round 14
// speedup vs baseline: 2.7926x; 1.0022x over previous
#include <cuda_runtime.h>
#include <cuda_bf16.h>
#include <cuda_fp16.h>
#include <cstdint>

// ---------------------------------------------------------------------------
// Problem constants
// ---------------------------------------------------------------------------
#define BB 4
#define CC 2048
#define EE 1024
#define HH 16
#define DD 64
#define MM (BB * CC)          // 8192 rows
#define FF (4 * EE)           // 4096 mlp hidden
#define KVS 2048              // fused K|V row stride

// ---------------------------------------------------------------------------
// Scratch
// ---------------------------------------------------------------------------
#define MB (1ull << 20)
__device__ __align__(256) unsigned char g_scratch[364 * MB];

#define OFF_N     (0 * MB)      // normed fp16 [MM, EE]
#define OFF_H     (32 * MB)     // h fp16 [MM, EE]
#define OFF_Q     (64 * MB)     // q fp16 [MM, EE]
#define OFF_KV    (96 * MB)     // [MM, 2048] fp16: K cols 0-1023, V 1024-2047
#define OFF_OUTB  (160 * MB)
#define OFF_M1    (192 * MB)    // m1 fp16 [MM, FF]
#define OFF_WQ    (320 * MB)
#define OFF_WKV   (324 * MB)
#define OFF_W1    (332 * MB)
#define OFF_W2    (348 * MB)

// ---------------------------------------------------------------------------
// PTX helpers (baseline compute_103 only — no 'a' features)
// ---------------------------------------------------------------------------
__device__ __forceinline__ uint32_t smem_u32(const void* p) {
    uint32_t a;
    asm("{ .reg .u64 t; cvta.to.shared.u64 t, %1; cvt.u32.u64 %0, t; }"
        : "=r"(a) : "l"(p));
    return a;
}
__device__ __forceinline__ void cpa16(uint32_t d, const void* s) {
    asm volatile("cp.async.cg.shared.global [%0], [%1], 16;" :: "r"(d), "l"(s));
}
#define CP_COMMIT() asm volatile("cp.async.commit_group;" ::: "memory")

__device__ __forceinline__ void ldsm4(uint32_t* r, uint32_t addr) {
    asm volatile("ldmatrix.sync.aligned.m8n8.x4.shared.b16 {%0,%1,%2,%3}, [%4];"
                 : "=r"(r[0]), "=r"(r[1]), "=r"(r[2]), "=r"(r[3]) : "r"(addr));
}
__device__ __forceinline__ void ldsm4t(uint32_t* r, uint32_t addr) {
    asm volatile("ldmatrix.sync.aligned.m8n8.x4.trans.shared.b16 {%0,%1,%2,%3}, [%4];"
                 : "=r"(r[0]), "=r"(r[1]), "=r"(r[2]), "=r"(r[3]) : "r"(addr));
}
__device__ __forceinline__ void mma16816h(float* c, const uint32_t* a,
                                          const uint32_t* b) {
    asm volatile(
        "mma.sync.aligned.m16n8k16.row.col.f32.f16.f16.f32 "
        "{%0,%1,%2,%3}, {%4,%5,%6,%7}, {%8,%9}, {%0,%1,%2,%3};"
        : "+f"(c[0]), "+f"(c[1]), "+f"(c[2]), "+f"(c[3])
        : "r"(a[0]), "r"(a[1]), "r"(a[2]), "r"(a[3]), "r"(b[0]), "r"(b[1]));
}
__device__ __forceinline__ uint32_t pack_h2(float a, float b) {
    __half2 t = __floats2half2_rn(a, b);
    return *reinterpret_cast<uint32_t*>(&t);
}

// ---------------------------------------------------------------------------
// Weight transpose -> fp16:  W[K,N] fp32 -> T[N,K] fp16
// ---------------------------------------------------------------------------
__global__ __launch_bounds__(256) void t16_kernel(
    const float* __restrict__ W, __half* __restrict__ Th, int K, int N)
{
    __shared__ float t[32][33];
    const int n0 = blockIdx.x * 32, k0 = blockIdx.y * 32;
    const int tx = threadIdx.x & 31, ty = threadIdx.x >> 5;
    #pragma unroll
    for (int j = 0; j < 32; j += 8)
        t[ty + j][tx] = W[(size_t)(k0 + ty + j) * N + n0 + tx];
    __syncthreads();
    #pragma unroll
    for (int j = 0; j < 32; j += 8) {
        const float v = t[tx][ty + j];
        Th[(size_t)(n0 + ty + j) * K + k0 + tx] = __float2half_rn(v);
    }
}

// Dual-source variant: z=0 -> (W0 -> Th), z=1 -> (W1 -> Th + half), K x N each.
__global__ __launch_bounds__(256) void t16_dual_kernel(
    const float* __restrict__ W0, const float* __restrict__ W1,
    __half* __restrict__ Th, int K, int N)
{
    __shared__ float t[32][33];
    const float* W = blockIdx.z ? W1 : W0;
    __half* dst = Th + (size_t)blockIdx.z * N * K;
    const int n0 = blockIdx.x * 32, k0 = blockIdx.y * 32;
    const int tx = threadIdx.x & 31, ty = threadIdx.x >> 5;
    #pragma unroll
    for (int j = 0; j < 32; j += 8)
        t[ty + j][tx] = W[(size_t)(k0 + ty + j) * N + n0 + tx];
    __syncthreads();
    #pragma unroll
    for (int j = 0; j < 32; j += 8) {
        const float v = t[tx][ty + j];
        dst[(size_t)(n0 + ty + j) * K + k0 + tx] = __float2half_rn(v);
    }
}

// ---------------------------------------------------------------------------
// LayerNorm -> fp16 single
// ---------------------------------------------------------------------------
__global__ __launch_bounds__(256) void ln16_kernel(
    const float* __restrict__ x, const float* __restrict__ gamma,
    const float* __restrict__ beta, __half* __restrict__ y)
{
    const int row = blockIdx.x;
    const int t = threadIdx.x;
    const float4 v = ((const float4*)(x + (size_t)row * EE))[t];
    float s  = v.x + v.y + v.z + v.w;
    float s2 = fmaf(v.x, v.x, fmaf(v.y, v.y, fmaf(v.z, v.z, v.w * v.w)));
    #pragma unroll
    for (int o = 16; o > 0; o >>= 1) {
        s  += __shfl_xor_sync(0xffffffffu, s, o);
        s2 += __shfl_xor_sync(0xffffffffu, s2, o);
    }
    __shared__ float rs[8], rs2[8];
    __shared__ float sstat[2];
    if ((t & 31) == 0) { rs[t >> 5] = s; rs2[t >> 5] = s2; }
    __syncthreads();
    if (t == 0) {
        float S = 0.f, S2 = 0.f;
        #pragma unroll
        for (int w = 0; w < 8; w++) { S += rs[w]; S2 += rs2[w]; }
        const float mean = S * (1.0f / EE);
        const float var  = S2 * (1.0f / EE) - mean * mean;
        sstat[0] = mean;
        sstat[1] = rsqrtf(var + 1e-5f);
    }
    __syncthreads();
    const float mean = sstat[0], rstd = sstat[1];
    const float4 gv = ((const float4*)gamma)[t];
    const float4 bv = ((const float4*)beta)[t];
    const float o0 = (v.x - mean) * rstd * gv.x + bv.x;
    const float o1 = (v.y - mean) * rstd * gv.y + bv.y;
    const float o2 = (v.z - mean) * rstd * gv.z + bv.z;
    const float o3 = (v.w - mean) * rstd * gv.w + bv.w;
    uint32_t* p = (uint32_t*)(y + (size_t)row * EE + 4 * t);
    p[0] = pack_h2(o0, o1);
    p[1] = pack_h2(o2, o3);
}

// ---------------------------------------------------------------------------
// fp16 single-pass GEMM: D = A(fp16) @ B(fp16)^T.  128x128 tile,
// K-chunk 64, 3-stage cp.async, single __syncthreads per chunk, 2 CTAs/SM.
// ---------------------------------------------------------------------------
#define G64ROWB 144u               // 64 halfs + 8 pad = 144B per row
#define G64MAT  18432u             // 128 rows * 144B
#define G64STG  36864u             // A | B
#define GSM1_BYTES (3 * 36864)     // 110592

__global__ __launch_bounds__(256, 2) void gemm_fp16_1p(
    const __half* __restrict__ A, const __half* __restrict__ B,
    const float* __restrict__ bias, const float* __restrict__ bias2, int nsplit,
    const float* __restrict__ res, float* __restrict__ Cf,
    __half* __restrict__ Ch, int M, int N, int K, int relu, float oscale)
{
    extern __shared__ unsigned char smem[];
    const uint32_t sbase = smem_u32(smem);
    const int tid = threadIdx.x;
    const int lane = tid & 31, wid = tid >> 5;
    const int wm = wid >> 2, wn = wid & 3;
    const int row0 = blockIdx.y * 128, col0 = blockIdx.x * 128;

    const __half* gA = A + (size_t)row0 * K;
    const __half* gB = B + (size_t)col0 * K;
    const int nch = K >> 6;              // K-chunk 64

    float acc[4][4][4];
    #pragma unroll
    for (int a = 0; a < 4; a++)
        #pragma unroll
        for (int b = 0; b < 4; b++)
            #pragma unroll
            for (int c = 0; c < 4; c++) acc[a][b][c] = 0.f;

    const uint32_t a_base = (uint32_t)(wm * 64 + (lane & 15)) * G64ROWB +
                            (((lane >> 4) << 3) << 1);
    const uint32_t b_base = (uint32_t)(wn * 32 + ((lane >> 4) << 3) + (lane & 7)) * G64ROWB +
                            ((((lane >> 3) & 1) << 3) << 1);

    auto load_chunk = [&](int ch, int s) {
        const int k0 = ch << 6;
        const uint32_t st = sbase + (uint32_t)s * G64STG;
        #pragma unroll
        for (int i = 0; i < 4; i++) {
            const int idx = i * 256 + tid;
            const int r = idx >> 3, g = idx & 7;
            const uint32_t d = (uint32_t)r * G64ROWB + g * 16u;
            const size_t so = (size_t)r * K + k0 + g * 8;
            cpa16(st + d, gA + so);
            cpa16(st + G64MAT + d, gB + so);
        }
    };

    auto compute_chunk = [&](int s) {
        const uint32_t st = sbase + (uint32_t)s * G64STG;
        #pragma unroll
        for (int ks = 0; ks < 4; ks++) {            // 4 x k16 per chunk
            uint32_t aF[4][4], bF[2][4];
            const uint32_t ao = a_base + (ks << 5);  // ks * 32 bytes
            #pragma unroll
            for (int mi = 0; mi < 4; mi++)
                ldsm4(aF[mi], st + ao + (uint32_t)mi * 16 * G64ROWB);
            const uint32_t bo = b_base + (ks << 5);
            #pragma unroll
            for (int p = 0; p < 2; p++)
                ldsm4(bF[p], st + G64MAT + bo + (uint32_t)p * 16 * G64ROWB);
            #pragma unroll
            for (int mi = 0; mi < 4; mi++)
                #pragma unroll
                for (int p = 0; p < 2; p++)
                    #pragma unroll
                    for (int h = 0; h < 2; h++)
                        mma16816h(acc[mi][p * 2 + h], aF[mi], &bF[p][h * 2]);
        }
    };

    load_chunk(0, 0); CP_COMMIT();
    load_chunk(1, 1); CP_COMMIT();

    for (int ch = 0; ch < nch; ch++) {
        asm volatile("cp.async.wait_group 1;" ::: "memory");
        __syncthreads();
        if (ch + 2 < nch) {
            load_chunk(ch + 2, (ch + 2) % 3);
            CP_COMMIT();
        } else {
            CP_COMMIT();
        }
        compute_chunk(ch % 3);
    }
    asm volatile("cp.async.wait_group 0;" ::: "memory");

    // ---------------- epilogue ----------------
    const float* effb = (bias2 && col0 >= nsplit) ? (bias2 - nsplit) : bias;
    const int tr = lane >> 2, tc = (lane & 3) << 1;
    #pragma unroll
    for (int mi = 0; mi < 4; mi++) {
        #pragma unroll
        for (int ni = 0; ni < 4; ni++) {
            const int col = col0 + wn * 32 + ni * 8 + tc;
            const float2 bb = *(const float2*)&effb[col];
            #pragma unroll
            for (int hr = 0; hr < 2; hr++) {
                const int row = row0 + wm * 64 + mi * 16 + tr + hr * 8;
                float v0 = (acc[mi][ni][hr * 2 + 0] + bb.x) * oscale;
                float v1 = (acc[mi][ni][hr * 2 + 1] + bb.y) * oscale;
                if (relu) { v0 = fmaxf(v0, 0.f); v1 = fmaxf(v1, 0.f); }
                const size_t goff = (size_t)row * N + col;
                if (Cf) {
                    if (res) {
                        const float2 rv = *(const float2*)&res[goff];
                        v0 += rv.x; v1 += rv.y;
                    }
                    *(float2*)&Cf[goff] = make_float2(v0, v1);
                } else {
                    *(uint32_t*)&Ch[goff] = pack_h2(v0, v1);
                }
            }
        }
    }
}

// ---------------------------------------------------------------------------
// Tensor-core flash attention (causal), fp16 single-pass.
// BM=128, BN=64, 256 threads (8 warps, warp tile 16x64). Q pre-scaled 1/8.
// LPT scheduling: qt mapped DESCENDING from blockIdx.x so the longest CTAs
// (largest qt, most KV tiles) launch first and short ones backfill the tail.
// ---------------------------------------------------------------------------
#define AR 144u                   // bytes per smem row (64 fp16 + pad)
#define AQMAT 18432u              // 128 rows * 144B
#define AKMAT 9216u               // 64 rows * 144B
#define ASTG (2 * AKMAT)          // K, V per stage = 18432
#define ATTN_SMEM (AQMAT + 2 * ASTG)   // 55296

__global__ __launch_bounds__(256) void attn_mma(
    const __half* __restrict__ Q, const __half* __restrict__ KV,
    const float* __restrict__ inp, float* __restrict__ Out)
{
    extern __shared__ unsigned char smem[];
    const uint32_t sbase = smem_u32(smem);
    const int tid = threadIdx.x, lane = tid & 31, w = tid >> 5;
    const int qt = gridDim.x - 1 - blockIdx.x;   // longest-first scheduling
    const int h = blockIdx.y, b = blockIdx.z;
    const int q0 = qt * 128;
    const int nt = 2 * qt + 2;                 // kv tiles (64 rows each)

    // ---- load Q tile (128 rows) ----
    {
        const size_t ro = (size_t)(b * CC + q0) * EE + (size_t)h * 64;
        #pragma unroll
        for (int i = 0; i < 4; i++) {
            const int idx = i * 256 + tid;
            const int r = idx >> 3, g = idx & 7;
            cpa16(sbase + (uint32_t)r * AR + g * 16u,
                  Q + ro + (size_t)r * EE + g * 8);
        }
    }
    CP_COMMIT();

    const size_t kvbase = (size_t)(b * CC) * KVS + (size_t)h * 64;
    auto load_kv = [&](int t, int s) {
        const uint32_t st = sbase + AQMAT + (uint32_t)s * ASTG;
        const size_t ro = kvbase + (size_t)(t * 64) * KVS;
        #pragma unroll
        for (int i = 0; i < 2; i++) {
            const int idx = i * 256 + tid;
            const int r = idx >> 3, g = idx & 7;
            const uint32_t d = st + (uint32_t)r * AR + g * 16u;
            const size_t so = ro + (size_t)r * KVS + g * 8;
            cpa16(d, KV + so);
            cpa16(d + AKMAT, KV + so + 1024);
        }
    };
    load_kv(0, 0); CP_COMMIT();

    float O[8][4];
    #pragma unroll
    for (int n = 0; n < 8; n++)
        #pragma unroll
        for (int j = 0; j < 4; j++) O[n][j] = 0.f;
    float m_lo = -1e30f, m_hi = -1e30f, l_lo = 0.f, l_hi = 0.f;
    uint32_t qF[4][4];

    const int rowl = w * 16 + (lane >> 2);     // local q row (lo); hi = +8
    const int c0 = (lane & 3) << 1;

    for (int t = 0; t < nt; t++) {
        if (t + 1 < nt) load_kv(t + 1, (t + 1) & 1);
        CP_COMMIT();
        asm volatile("cp.async.wait_group 1;" ::: "memory");
        __syncthreads();

        const uint32_t sK = sbase + AQMAT + (uint32_t)(t & 1) * ASTG;
        const uint32_t sV = sK + AKMAT;

        if (t == 0) {
            const uint32_t qa = sbase + (uint32_t)(w * 16 + (lane & 15)) * AR +
                                (((lane >> 4) << 3) << 1);
            #pragma unroll
            for (int ks = 0; ks < 4; ks++)
                ldsm4(qF[ks], qa + ks * 32);
        }

        // ---- S = Q @ K^T ----
        float S[8][4];
        #pragma unroll
        for (int n = 0; n < 8; n++)
            #pragma unroll
            for (int j = 0; j < 4; j++) S[n][j] = 0.f;

        #pragma unroll
        for (int ks = 0; ks < 4; ks++) {
            #pragma unroll
            for (int np = 0; np < 4; np += 2) {
                const uint32_t kb0 = sK +
                    (uint32_t)(np * 16 + ((lane >> 4) << 3) + (lane & 7)) * AR +
                    ((((lane >> 3) & 1) << 3) << 1) + ks * 32;
                const uint32_t kb1 = kb0 + 16 * AR;
                uint32_t bh0[4], bh1[4];
                ldsm4(bh0, kb0);
                ldsm4(bh1, kb1);
                #pragma unroll
                for (int h2 = 0; h2 < 2; h2++) {
                    mma16816h(S[np * 2 + h2],       qF[ks], &bh0[h2 * 2]);
                    mma16816h(S[(np + 1) * 2 + h2], qF[ks], &bh1[h2 * 2]);
                }
            }
        }

        // ---- causal mask (only tiles overlapping/above the diagonal) ----
        if (t >= 2 * qt) {
            const int colg0 = t * 64;
            const int rg_lo = q0 + rowl, rg_hi = rg_lo + 8;
            #pragma unroll
            for (int n = 0; n < 8; n++) {
                const int col = colg0 + n * 8 + c0;
                if (col > rg_lo)     S[n][0] = -1e30f;
                if (col + 1 > rg_lo) S[n][1] = -1e30f;
                if (col > rg_hi)     S[n][2] = -1e30f;
                if (col + 1 > rg_hi) S[n][3] = -1e30f;
            }
        }

        // ---- online softmax ----
        float mx0 = -1e30f, mx1 = -1e30f;
        #pragma unroll
        for (int n = 0; n < 8; n++) {
            mx0 = fmaxf(mx0, fmaxf(S[n][0], S[n][1]));
            mx1 = fmaxf(mx1, fmaxf(S[n][2], S[n][3]));
        }
        mx0 = fmaxf(mx0, __shfl_xor_sync(0xffffffffu, mx0, 1));
        mx0 = fmaxf(mx0, __shfl_xor_sync(0xffffffffu, mx0, 2));
        mx1 = fmaxf(mx1, __shfl_xor_sync(0xffffffffu, mx1, 1));
        mx1 = fmaxf(mx1, __shfl_xor_sync(0xffffffffu, mx1, 2));
        const float mn0 = fmaxf(m_lo, mx0), mn1 = fmaxf(m_hi, mx1);
        const float cr0 = __expf(m_lo - mn0), cr1 = __expf(m_hi - mn1);
        float s0 = 0.f, s1 = 0.f;
        #pragma unroll
        for (int n = 0; n < 8; n++) {
            S[n][0] = __expf(S[n][0] - mn0); s0 += S[n][0];
            S[n][1] = __expf(S[n][1] - mn0); s0 += S[n][1];
            S[n][2] = __expf(S[n][2] - mn1); s1 += S[n][2];
            S[n][3] = __expf(S[n][3] - mn1); s1 += S[n][3];
        }
        s0 += __shfl_xor_sync(0xffffffffu, s0, 1);
        s0 += __shfl_xor_sync(0xffffffffu, s0, 2);
        s1 += __shfl_xor_sync(0xffffffffu, s1, 1);
        s1 += __shfl_xor_sync(0xffffffffu, s1, 2);
        l_lo = l_lo * cr0 + s0; l_hi = l_hi * cr1 + s1;
        m_lo = mn0; m_hi = mn1;
        #pragma unroll
        for (int n = 0; n < 8; n++) {
            O[n][0] *= cr0; O[n][1] *= cr0;
            O[n][2] *= cr1; O[n][3] *= cr1;
        }

        // ---- P -> fp16 A-fragments (C-frag reuse) ----
        uint32_t pF[4][4];
        #pragma unroll
        for (int kk = 0; kk < 4; kk++) {
            pF[kk][0] = pack_h2(S[2 * kk][0],     S[2 * kk][1]);
            pF[kk][1] = pack_h2(S[2 * kk][2],     S[2 * kk][3]);
            pF[kk][2] = pack_h2(S[2 * kk + 1][0], S[2 * kk + 1][1]);
            pF[kk][3] = pack_h2(S[2 * kk + 1][2], S[2 * kk + 1][3]);
        }

        // ---- O += P @ V (ldmatrix.trans for V) ----
        #pragma unroll
        for (int kk = 0; kk < 4; kk++) {
            #pragma unroll
            for (int np = 0; np < 4; np += 2) {
                const uint32_t va0 = sV +
                    (uint32_t)(kk * 16 + ((lane >> 3) & 1) * 8 + (lane & 7)) * AR +
                    ((np * 16 + ((lane >> 4) << 3)) << 1);
                const uint32_t va1 = va0 + 32;
                uint32_t vh0[4], vh1[4];
                ldsm4t(vh0, va0);
                ldsm4t(vh1, va1);
                #pragma unroll
                for (int h2 = 0; h2 < 2; h2++) {
                    mma16816h(O[np * 2 + h2],       pF[kk], &vh0[h2 * 2]);
                    mma16816h(O[(np + 1) * 2 + h2], pF[kk], &vh1[h2 * 2]);
                }
            }
        }
        __syncthreads();
    }

    // ---- finalize: /l, add residual, store fp32 ----
    const float inv0 = 1.0f / l_lo, inv1 = 1.0f / l_hi;
    const int gr0 = b * CC + q0 + rowl;
    #pragma unroll
    for (int n = 0; n < 8; n++) {
        const int col = h * 64 + n * 8 + c0;
        const size_t o0 = (size_t)gr0 * EE + col;
        const size_t o1 = o0 + (size_t)8 * EE;
        const float2 i0 = *(const float2*)&inp[o0];
        const float2 i1 = *(const float2*)&inp[o1];
        *(float2*)&Out[o0] = make_float2(i0.x + O[n][0] * inv0,
                                         i0.y + O[n][1] * inv0);
        *(float2*)&Out[o1] = make_float2(i1.x + O[n][2] * inv1,
                                         i1.y + O[n][3] * inv1);
    }
}

// ---------------------------------------------------------------------------
// kernel_launch
// ---------------------------------------------------------------------------
extern "C" void kernel_launch(void* const* d_in, const int* in_sizes, int n_in,
                              void* d_out, int out_size)
{
    const float* inputs = (const float*)d_in[0];
    const float* Wq     = (const float*)d_in[1];
    const float* bq     = (const float*)d_in[2];
    const float* Wk     = (const float*)d_in[3];
    const float* bk     = (const float*)d_in[4];
    const float* Wv     = (const float*)d_in[5];
    const float* bv     = (const float*)d_in[6];
    const float* g1     = (const float*)d_in[7];
    const float* beta1  = (const float*)d_in[8];
    const float* g2     = (const float*)d_in[9];
    const float* beta2  = (const float*)d_in[10];
    const float* W1     = (const float*)d_in[11];
    const float* bm1    = (const float*)d_in[12];
    const float* W2     = (const float*)d_in[13];
    const float* bm2    = (const float*)d_in[14];
    float* out = (float*)d_out;

    unsigned char* base = nullptr;
    cudaGetSymbolAddress((void**)&base, g_scratch);
    __half* nf     = (__half*)(base + OFF_N);
    __half* hf     = (__half*)(base + OFF_H);
    __half* qf     = (__half*)(base + OFF_Q);
    __half* kvf    = (__half*)(base + OFF_KV);
    float* outbuf  = (float*)(base + OFF_OUTB);
    __half* m1     = (__half*)(base + OFF_M1);
    __half* WqT    = (__half*)(base + OFF_WQ);
    __half* WkvT   = (__half*)(base + OFF_WKV);
    __half* W1T    = (__half*)(base + OFF_W1);
    __half* W2T    = (__half*)(base + OFF_W2);

    cudaFuncSetAttribute(gemm_fp16_1p, cudaFuncAttributeMaxDynamicSharedMemorySize,
                         GSM1_BYTES);
    cudaFuncSetAttribute(attn_mma, cudaFuncAttributeMaxDynamicSharedMemorySize,
                         ATTN_SMEM);

    // Launch order keeps index 3 == gemm_fp16_1p (Q proj) for ncu capture.
    // 0: Wq prep
    t16_kernel<<<dim3(EE / 32, EE / 32), 256>>>(Wq, WqT, EE, EE);
    // 1: LN1 -> fp16
    ln16_kernel<<<MM, 256>>>(inputs, g1, beta1, nf);
    // 2: Wk + Wv prep (both halves of fused WkvT in one launch)
    t16_dual_kernel<<<dim3(EE / 32, EE / 32, 2), 256>>>(Wk, Wv, WkvT, EE, EE);
    // 3: Q projection, oscale=1/8 (profiled)
    gemm_fp16_1p<<<dim3(EE / 128, MM / 128), 256, GSM1_BYTES>>>(
        nf, WqT, bq, nullptr, 0, nullptr, nullptr, qf, MM, EE, EE, 0, 0.125f);
    // 4: fused K|V projection (N=2048)
    gemm_fp16_1p<<<dim3(KVS / 128, MM / 128), 256, GSM1_BYTES>>>(
        nf, WkvT, bk, bv, 1024, nullptr, nullptr, kvf, MM, KVS, EE, 0, 1.0f);
    // 5-6: MLP weight prep
    t16_kernel<<<dim3(FF / 32, EE / 32), 256>>>(W1, W1T, EE, FF);
    t16_kernel<<<dim3(EE / 32, FF / 32), 256>>>(W2, W2T, FF, EE);
    // 7: fp16 causal attention + residual (longest-first qt order)
    attn_mma<<<dim3(CC / 128, HH, BB), 256, ATTN_SMEM>>>(
        qf, kvf, inputs, outbuf);
    // 8: LN2 -> fp16
    ln16_kernel<<<MM, 256>>>(outbuf, g2, beta2, hf);
    // 9: MLP1 (relu) -> fp16
    gemm_fp16_1p<<<dim3(FF / 128, MM / 128), 256, GSM1_BYTES>>>(
        hf, W1T, bm1, nullptr, 0, nullptr, nullptr, m1, MM, FF, EE, 1, 1.0f);
    // 10: MLP2 + residual -> out
    gemm_fp16_1p<<<dim3(EE / 128, MM / 128), 256, GSM1_BYTES>>>(
        m1, W2T, bm2, nullptr, 0, outbuf, out, nullptr, MM, EE, FF, 0, 1.0f);
}

// round 15
// speedup vs baseline: 2.8371x; 1.0159x over previous
#include <cuda_runtime.h>
#include <cuda_bf16.h>
#include <cuda_fp16.h>
#include <cstdint>

// ---------------------------------------------------------------------------
// Problem constants
// ---------------------------------------------------------------------------
#define BB 4
#define CC 2048
#define EE 1024
#define HH 16
#define DD 64
#define MM (BB * CC)          // 8192 rows
#define FF (4 * EE)           // 4096 mlp hidden
#define QKVS 3072             // fused Q|K|V row stride

// Q scale: 1/sqrt(D) * log2(e) folded in, so softmax can use exp2 directly.
#define QSCALE 0.18033688011112042f   // 0.125 * 1.4426950408889634

// ---------------------------------------------------------------------------
// Scratch
// ---------------------------------------------------------------------------
#define MB (1ull << 20)
__device__ __align__(256) unsigned char g_scratch[364 * MB];

#define OFF_N     (0 * MB)      // normed fp16 [MM, EE]
#define OFF_H     (32 * MB)     // h fp16 [MM, EE]
#define OFF_QKV   (64 * MB)     // [MM, 3072] fp16: Q 0-1023, K 1024-2047, V 2048-3071
#define OFF_OUTB  (160 * MB)
#define OFF_M1    (192 * MB)    // m1 fp16 [MM, FF]
#define OFF_WQKV  (320 * MB)    // [3072, 1024] fp16 (6MB)
#define OFF_W1    (332 * MB)
#define OFF_W2    (348 * MB)

// ---------------------------------------------------------------------------
// PTX helpers (baseline compute_103 only — no 'a' features)
// ---------------------------------------------------------------------------
__device__ __forceinline__ uint32_t smem_u32(const void* p) {
    uint32_t a;
    asm("{ .reg .u64 t; cvta.to.shared.u64 t, %1; cvt.u32.u64 %0, t; }"
        : "=r"(a) : "l"(p));
    return a;
}
__device__ __forceinline__ void cpa16(uint32_t d, const void* s) {
    asm volatile("cp.async.cg.shared.global [%0], [%1], 16;" :: "r"(d), "l"(s));
}
#define CP_COMMIT() asm volatile("cp.async.commit_group;" ::: "memory")

__device__ __forceinline__ void ldsm4(uint32_t* r, uint32_t addr) {
    asm volatile("ldmatrix.sync.aligned.m8n8.x4.shared.b16 {%0,%1,%2,%3}, [%4];"
                 : "=r"(r[0]), "=r"(r[1]), "=r"(r[2]), "=r"(r[3]) : "r"(addr));
}
__device__ __forceinline__ void ldsm4t(uint32_t* r, uint32_t addr) {
    asm volatile("ldmatrix.sync.aligned.m8n8.x4.trans.shared.b16 {%0,%1,%2,%3}, [%4];"
                 : "=r"(r[0]), "=r"(r[1]), "=r"(r[2]), "=r"(r[3]) : "r"(addr));
}
__device__ __forceinline__ void mma16816h(float* c, const uint32_t* a,
                                          const uint32_t* b) {
    asm volatile(
        "mma.sync.aligned.m16n8k16.row.col.f32.f16.f16.f32 "
        "{%0,%1,%2,%3}, {%4,%5,%6,%7}, {%8,%9}, {%0,%1,%2,%3};"
        : "+f"(c[0]), "+f"(c[1]), "+f"(c[2]), "+f"(c[3])
        : "r"(a[0]), "r"(a[1]), "r"(a[2]), "r"(a[3]), "r"(b[0]), "r"(b[1]));
}
__device__ __forceinline__ uint32_t pack_h2(float a, float b) {
    __half2 t = __floats2half2_rn(a, b);
    return *reinterpret_cast<uint32_t*>(&t);
}

// ---------------------------------------------------------------------------
// Weight transpose -> fp16:  W[K,N] fp32 -> T[N,K] fp16
// ---------------------------------------------------------------------------
__global__ __launch_bounds__(256) void t16_kernel(
    const float* __restrict__ W, __half* __restrict__ Th, int K, int N)
{
    __shared__ float t[32][33];
    const int n0 = blockIdx.x * 32, k0 = blockIdx.y * 32;
    const int tx = threadIdx.x & 31, ty = threadIdx.x >> 5;
    #pragma unroll
    for (int j = 0; j < 32; j += 8)
        t[ty + j][tx] = W[(size_t)(k0 + ty + j) * N + n0 + tx];
    __syncthreads();
    #pragma unroll
    for (int j = 0; j < 32; j += 8) {
        const float v = t[tx][ty + j];
        Th[(size_t)(n0 + ty + j) * K + k0 + tx] = __float2half_rn(v);
    }
}

// Triple-source: z in {0,1,2} -> (Wz -> Th + z*N*K).  Each W is K x N.
__global__ __launch_bounds__(256) void t16_tri_kernel(
    const float* __restrict__ W0, const float* __restrict__ W1,
    const float* __restrict__ W2, __half* __restrict__ Th, int K, int N)
{
    __shared__ float t[32][33];
    const float* W = (blockIdx.z == 0) ? W0 : (blockIdx.z == 1) ? W1 : W2;
    __half* dst = Th + (size_t)blockIdx.z * N * K;
    const int n0 = blockIdx.x * 32, k0 = blockIdx.y * 32;
    const int tx = threadIdx.x & 31, ty = threadIdx.x >> 5;
    #pragma unroll
    for (int j = 0; j < 32; j += 8)
        t[ty + j][tx] = W[(size_t)(k0 + ty + j) * N + n0 + tx];
    __syncthreads();
    #pragma unroll
    for (int j = 0; j < 32; j += 8) {
        const float v = t[tx][ty + j];
        dst[(size_t)(n0 + ty + j) * K + k0 + tx] = __float2half_rn(v);
    }
}

// ---------------------------------------------------------------------------
// LayerNorm -> fp16, warp-per-row (8 rows/CTA, no __syncthreads)
// ---------------------------------------------------------------------------
__global__ __launch_bounds__(256) void ln16w_kernel(
    const float* __restrict__ x, const float* __restrict__ gamma,
    const float* __restrict__ beta, __half* __restrict__ y)
{
    const int w = threadIdx.x >> 5, lane = threadIdx.x & 31;
    const int row = blockIdx.x * 8 + w;
    const float4* xr = (const float4*)(x + (size_t)row * EE);
    float4 v[8];
    float s = 0.f, s2 = 0.f;
    #pragma unroll
    for (int i = 0; i < 8; i++) {
        v[i] = xr[i * 32 + lane];
        s  += v[i].x + v[i].y + v[i].z + v[i].w;
        s2 += fmaf(v[i].x, v[i].x, fmaf(v[i].y, v[i].y,
              fmaf(v[i].z, v[i].z, v[i].w * v[i].w)));
    }
    #pragma unroll
    for (int o = 16; o > 0; o >>= 1) {
        s  += __shfl_xor_sync(0xffffffffu, s, o);
        s2 += __shfl_xor_sync(0xffffffffu, s2, o);
    }
    const float mean = s * (1.0f / EE);
    const float var  = s2 * (1.0f / EE) - mean * mean;
    const float rstd = rsqrtf(var + 1e-5f);
    uint2* yr = (uint2*)(y + (size_t)row * EE);
    #pragma unroll
    for (int i = 0; i < 8; i++) {
        const int c4 = i * 32 + lane;
        const float4 gv = ((const float4*)gamma)[c4];
        const float4 bv = ((const float4*)beta)[c4];
        const float o0 = (v[i].x - mean) * rstd * gv.x + bv.x;
        const float o1 = (v[i].y - mean) * rstd * gv.y + bv.y;
        const float o2 = (v[i].z - mean) * rstd * gv.z + bv.z;
        const float o3 = (v[i].w - mean) * rstd * gv.w + bv.w;
        yr[c4] = make_uint2(pack_h2(o0, o1), pack_h2(o2, o3));
    }
}

// ---------------------------------------------------------------------------
// fp16 single-pass GEMM: D = A(fp16) @ B(fp16)^T.  128x128 tile,
// K-chunk 64, 3-stage cp.async, single __syncthreads per chunk, 2 CTAs/SM.
// qkv mode (biasK != null): col segment 0 -> bias,oscale; 1 -> biasK; 2 -> biasV
// (segments get oscale=1).
// ---------------------------------------------------------------------------
#define G64ROWB 144u               // 64 halfs + 8 pad = 144B per row
#define G64MAT  18432u             // 128 rows * 144B
#define G64STG  36864u             // A | B
#define GSM1_BYTES (3 * 36864)     // 110592

__global__ __launch_bounds__(256, 2) void gemm_fp16_1p(
    const __half* __restrict__ A, const __half* __restrict__ B,
    const float* __restrict__ bias, const float* __restrict__ biasK,
    const float* __restrict__ biasV,
    const float* __restrict__ res, float* __restrict__ Cf,
    __half* __restrict__ Ch, int M, int N, int K, int relu, float oscale)
{
    extern __shared__ unsigned char smem[];
    const uint32_t sbase = smem_u32(smem);
    const int tid = threadIdx.x;
    const int lane = tid & 31, wid = tid >> 5;
    const int wm = wid >> 2, wn = wid & 3;
    const int row0 = blockIdx.y * 128, col0 = blockIdx.x * 128;

    const __half* gA = A + (size_t)row0 * K;
    const __half* gB = B + (size_t)col0 * K;
    const int nch = K >> 6;              // K-chunk 64

    float acc[4][4][4];
    #pragma unroll
    for (int a = 0; a < 4; a++)
        #pragma unroll
        for (int b = 0; b < 4; b++)
            #pragma unroll
            for (int c = 0; c < 4; c++) acc[a][b][c] = 0.f;

    const uint32_t a_base = (uint32_t)(wm * 64 + (lane & 15)) * G64ROWB +
                            (((lane >> 4) << 3) << 1);
    const uint32_t b_base = (uint32_t)(wn * 32 + ((lane >> 4) << 3) + (lane & 7)) * G64ROWB +
                            ((((lane >> 3) & 1) << 3) << 1);

    auto load_chunk = [&](int ch, int s) {
        const int k0 = ch << 6;
        const uint32_t st = sbase + (uint32_t)s * G64STG;
        #pragma unroll
        for (int i = 0; i < 4; i++) {
            const int idx = i * 256 + tid;
            const int r = idx >> 3, g = idx & 7;
            const uint32_t d = (uint32_t)r * G64ROWB + g * 16u;
            const size_t so = (size_t)r * K + k0 + g * 8;
            cpa16(st + d, gA + so);
            cpa16(st + G64MAT + d, gB + so);
        }
    };

    auto compute_chunk = [&](int s) {
        const uint32_t st = sbase + (uint32_t)s * G64STG;
        #pragma unroll
        for (int ks = 0; ks < 4; ks++) {            // 4 x k16 per chunk
            uint32_t aF[4][4], bF[2][4];
            const uint32_t ao = a_base + (ks << 5);
            #pragma unroll
            for (int mi = 0; mi < 4; mi++)
                ldsm4(aF[mi], st + ao + (uint32_t)mi * 16 * G64ROWB);
            const uint32_t bo = b_base + (ks << 5);
            #pragma unroll
            for (int p = 0; p < 2; p++)
                ldsm4(bF[p], st + G64MAT + bo + (uint32_t)p * 16 * G64ROWB);
            #pragma unroll
            for (int mi = 0; mi < 4; mi++)
                #pragma unroll
                for (int p = 0; p < 2; p++)
                    #pragma unroll
                    for (int h = 0; h < 2; h++)
                        mma16816h(acc[mi][p * 2 + h], aF[mi], &bF[p][h * 2]);
        }
    };

    load_chunk(0, 0); CP_COMMIT();
    load_chunk(1, 1); CP_COMMIT();

    for (int ch = 0; ch < nch; ch++) {
        asm volatile("cp.async.wait_group 1;" ::: "memory");
        __syncthreads();
        if (ch + 2 < nch) {
            load_chunk(ch + 2, (ch + 2) % 3);
            CP_COMMIT();
        } else {
            CP_COMMIT();
        }
        compute_chunk(ch % 3);
    }
    asm volatile("cp.async.wait_group 0;" ::: "memory");

    // ---------------- epilogue ----------------
    const float* effb = bias;
    float osc = oscale;
    if (biasK) {                          // fused QKV mode
        if (col0 >= 2048)      { effb = biasV - 2048; osc = 1.0f; }
        else if (col0 >= 1024) { effb = biasK - 1024; osc = 1.0f; }
    }
    const int tr = lane >> 2, tc = (lane & 3) << 1;
    #pragma unroll
    for (int mi = 0; mi < 4; mi++) {
        #pragma unroll
        for (int ni = 0; ni < 4; ni++) {
            const int col = col0 + wn * 32 + ni * 8 + tc;
            const float2 bb = *(const float2*)&effb[col];
            #pragma unroll
            for (int hr = 0; hr < 2; hr++) {
                const int row = row0 + wm * 64 + mi * 16 + tr + hr * 8;
                float v0 = (acc[mi][ni][hr * 2 + 0] + bb.x) * osc;
                float v1 = (acc[mi][ni][hr * 2 + 1] + bb.y) * osc;
                if (relu) { v0 = fmaxf(v0, 0.f); v1 = fmaxf(v1, 0.f); }
                const size_t goff = (size_t)row * N + col;
                if (Cf) {
                    if (res) {
                        const float2 rv = *(const float2*)&res[goff];
                        v0 += rv.x; v1 += rv.y;
                    }
                    *(float2*)&Cf[goff] = make_float2(v0, v1);
                } else {
                    *(uint32_t*)&Ch[goff] = pack_h2(v0, v1);
                }
            }
        }
    }
}

// ---------------------------------------------------------------------------
// Tensor-core flash attention (causal), fp16 single-pass, exp2 softmax.
// BM=128, BN=64, 256 threads (8 warps, warp tile 16x64), 2 CTAs/SM.
// QKV fused fp16 [M][3072]: Q at h*64 (pre-scaled by QSCALE), K at 1024+h*64,
// V at 2048+h*64. Out = inp + softmax(QK^T)V (fp32).
// ---------------------------------------------------------------------------
#define AR 144u                   // bytes per smem row (64 fp16 + pad)
#define AQMAT 18432u              // 128 rows * 144B
#define AKMAT 9216u               // 64 rows * 144B
#define ASTG (2 * AKMAT)          // K, V per stage = 18432
#define ATTN_SMEM (AQMAT + 2 * ASTG)   // 55296

__global__ __launch_bounds__(256, 2) void attn_mma(
    const __half* __restrict__ QKV, const float* __restrict__ inp,
    float* __restrict__ Out)
{
    extern __shared__ unsigned char smem[];
    const uint32_t sbase = smem_u32(smem);
    const int tid = threadIdx.x, lane = tid & 31, w = tid >> 5;
    const int qt = gridDim.x - 1 - blockIdx.x;   // longest-first
    const int h = blockIdx.y, b = blockIdx.z;
    const int q0 = qt * 128;
    const int nt = 2 * qt + 2;                 // kv tiles (64 rows each)

    // ---- load Q tile (128 rows) ----
    {
        const size_t ro = (size_t)(b * CC + q0) * QKVS + (size_t)h * 64;
        #pragma unroll
        for (int i = 0; i < 4; i++) {
            const int idx = i * 256 + tid;
            const int r = idx >> 3, g = idx & 7;
            cpa16(sbase + (uint32_t)r * AR + g * 16u,
                  QKV + ro + (size_t)r * QKVS + g * 8);
        }
    }
    CP_COMMIT();

    const size_t kvbase = (size_t)(b * CC) * QKVS + 1024 + (size_t)h * 64;
    auto load_kv = [&](int t, int s) {
        const uint32_t st = sbase + AQMAT + (uint32_t)s * ASTG;
        const size_t ro = kvbase + (size_t)(t * 64) * QKVS;
        #pragma unroll
        for (int i = 0; i < 2; i++) {
            const int idx = i * 256 + tid;
            const int r = idx >> 3, g = idx & 7;
            const uint32_t d = st + (uint32_t)r * AR + g * 16u;
            const size_t so = ro + (size_t)r * QKVS + g * 8;
            cpa16(d, QKV + so);                 // K
            cpa16(d + AKMAT, QKV + so + 1024);  // V
        }
    };
    load_kv(0, 0); CP_COMMIT();

    float O[8][4];
    #pragma unroll
    for (int n = 0; n < 8; n++)
        #pragma unroll
        for (int j = 0; j < 4; j++) O[n][j] = 0.f;
    float m_lo = -1e30f, m_hi = -1e30f, l_lo = 0.f, l_hi = 0.f;
    uint32_t qF[4][4];

    const int rowl = w * 16 + (lane >> 2);     // local q row (lo); hi = +8
    const int c0 = (lane & 3) << 1;

    for (int t = 0; t < nt; t++) {
        if (t + 1 < nt) load_kv(t + 1, (t + 1) & 1);
        CP_COMMIT();
        asm volatile("cp.async.wait_group 1;" ::: "memory");
        __syncthreads();

        const uint32_t sK = sbase + AQMAT + (uint32_t)(t & 1) * ASTG;
        const uint32_t sV = sK + AKMAT;

        if (t == 0) {
            const uint32_t qa = sbase + (uint32_t)(w * 16 + (lane & 15)) * AR +
                                (((lane >> 4) << 3) << 1);
            #pragma unroll
            for (int ks = 0; ks < 4; ks++)
                ldsm4(qF[ks], qa + ks * 32);
        }

        // ---- S = Q @ K^T (scores already in log2 units via QSCALE) ----
        float S[8][4];
        #pragma unroll
        for (int n = 0; n < 8; n++)
            #pragma unroll
            for (int j = 0; j < 4; j++) S[n][j] = 0.f;

        #pragma unroll
        for (int ks = 0; ks < 4; ks++) {
            #pragma unroll
            for (int np = 0; np < 4; np += 2) {
                const uint32_t kb0 = sK +
                    (uint32_t)(np * 16 + ((lane >> 4) << 3) + (lane & 7)) * AR +
                    ((((lane >> 3) & 1) << 3) << 1) + ks * 32;
                const uint32_t kb1 = kb0 + 16 * AR;
                uint32_t bh0[4], bh1[4];
                ldsm4(bh0, kb0);
                ldsm4(bh1, kb1);
                #pragma unroll
                for (int h2 = 0; h2 < 2; h2++) {
                    mma16816h(S[np * 2 + h2],       qF[ks], &bh0[h2 * 2]);
                    mma16816h(S[(np + 1) * 2 + h2], qF[ks], &bh1[h2 * 2]);
                }
            }
        }

        // ---- causal mask ----
        if (t >= 2 * qt) {
            const int colg0 = t * 64;
            const int rg_lo = q0 + rowl, rg_hi = rg_lo + 8;
            #pragma unroll
            for (int n = 0; n < 8; n++) {
                const int col = colg0 + n * 8 + c0;
                if (col > rg_lo)     S[n][0] = -1e30f;
                if (col + 1 > rg_lo) S[n][1] = -1e30f;
                if (col > rg_hi)     S[n][2] = -1e30f;
                if (col + 1 > rg_hi) S[n][3] = -1e30f;
            }
        }

        // ---- online softmax (base-2) ----
        float mx0 = -1e30f, mx1 = -1e30f;
        #pragma unroll
        for (int n = 0; n < 8; n++) {
            mx0 = fmaxf(mx0, fmaxf(S[n][0], S[n][1]));
            mx1 = fmaxf(mx1, fmaxf(S[n][2], S[n][3]));
        }
        mx0 = fmaxf(mx0, __shfl_xor_sync(0xffffffffu, mx0, 1));
        mx0 = fmaxf(mx0, __shfl_xor_sync(0xffffffffu, mx0, 2));
        mx1 = fmaxf(mx1, __shfl_xor_sync(0xffffffffu, mx1, 1));
        mx1 = fmaxf(mx1, __shfl_xor_sync(0xffffffffu, mx1, 2));
        const float mn0 = fmaxf(m_lo, mx0), mn1 = fmaxf(m_hi, mx1);
        const float cr0 = exp2f(m_lo - mn0), cr1 = exp2f(m_hi - mn1);
        float s0 = 0.f, s1 = 0.f;
        #pragma unroll
        for (int n = 0; n < 8; n++) {
            S[n][0] = exp2f(S[n][0] - mn0); s0 += S[n][0];
            S[n][1] = exp2f(S[n][1] - mn0); s0 += S[n][1];
            S[n][2] = exp2f(S[n][2] - mn1); s1 += S[n][2];
            S[n][3] = exp2f(S[n][3] - mn1); s1 += S[n][3];
        }
        s0 += __shfl_xor_sync(0xffffffffu, s0, 1);
        s0 += __shfl_xor_sync(0xffffffffu, s0, 2);
        s1 += __shfl_xor_sync(0xffffffffu, s1, 1);
        s1 += __shfl_xor_sync(0xffffffffu, s1, 2);
        l_lo = l_lo * cr0 + s0; l_hi = l_hi * cr1 + s1;
        m_lo = mn0; m_hi = mn1;
        #pragma unroll
        for (int n = 0; n < 8; n++) {
            O[n][0] *= cr0; O[n][1] *= cr0;
            O[n][2] *= cr1; O[n][3] *= cr1;
        }

        // ---- P -> fp16 A-fragments ----
        uint32_t pF[4][4];
        #pragma unroll
        for (int kk = 0; kk < 4; kk++) {
            pF[kk][0] = pack_h2(S[2 * kk][0],     S[2 * kk][1]);
            pF[kk][1] = pack_h2(S[2 * kk][2],     S[2 * kk][3]);
            pF[kk][2] = pack_h2(S[2 * kk + 1][0], S[2 * kk + 1][1]);
            pF[kk][3] = pack_h2(S[2 * kk + 1][2], S[2 * kk + 1][3]);
        }

        // ---- O += P @ V ----
        #pragma unroll
        for (int kk = 0; kk < 4; kk++) {
            #pragma unroll
            for (int np = 0; np < 4; np += 2) {
                const uint32_t va0 = sV +
                    (uint32_t)(kk * 16 + ((lane >> 3) & 1) * 8 + (lane & 7)) * AR +
                    ((np * 16 + ((lane >> 4) << 3)) << 1);
                const uint32_t va1 = va0 + 32;
                uint32_t vh0[4], vh1[4];
                ldsm4t(vh0, va0);
                ldsm4t(vh1, va1);
                #pragma unroll
                for (int h2 = 0; h2 < 2; h2++) {
                    mma16816h(O[np * 2 + h2],       pF[kk], &vh0[h2 * 2]);
                    mma16816h(O[(np + 1) * 2 + h2], pF[kk], &vh1[h2 * 2]);
                }
            }
        }
        __syncthreads();
    }

    // ---- finalize ----
    const float inv0 = 1.0f / l_lo, inv1 = 1.0f / l_hi;
    const int gr0 = b * CC + q0 + rowl;
    #pragma unroll
    for (int n = 0; n < 8; n++) {
        const int col = h * 64 + n * 8 + c0;
        const size_t o0 = (size_t)gr0 * EE + col;
        const size_t o1 = o0 + (size_t)8 * EE;
        const float2 i0 = *(const float2*)&inp[o0];
        const float2 i1 = *(const float2*)&inp[o1];
        *(float2*)&Out[o0] = make_float2(i0.x + O[n][0] * inv0,
                                         i0.y + O[n][1] * inv0);
        *(float2*)&Out[o1] = make_float2(i1.x + O[n][2] * inv1,
                                         i1.y + O[n][3] * inv1);
    }
}

// ---------------------------------------------------------------------------
// kernel_launch
// ---------------------------------------------------------------------------
extern "C" void kernel_launch(void* const* d_in, const int* in_sizes, int n_in,
                              void* d_out, int out_size)
{
    const float* inputs = (const float*)d_in[0];
    const float* Wq     = (const float*)d_in[1];
    const float* bq     = (const float*)d_in[2];
    const float* Wk     = (const float*)d_in[3];
    const float* bk     = (const float*)d_in[4];
    const float* Wv     = (const float*)d_in[5];
    const float* bv     = (const float*)d_in[6];
    const float* g1     = (const float*)d_in[7];
    const float* beta1  = (const float*)d_in[8];
    const float* g2     = (const float*)d_in[9];
    const float* beta2  = (const float*)d_in[10];
    const float* W1     = (const float*)d_in[11];
    const float* bm1    = (const float*)d_in[12];
    const float* W2     = (const float*)d_in[13];
    const float* bm2    = (const float*)d_in[14];
    float* out = (float*)d_out;

    unsigned char* base = nullptr;
    cudaGetSymbolAddress((void**)&base, g_scratch);
    __half* nf     = (__half*)(base + OFF_N);
    __half* hf     = (__half*)(base + OFF_H);
    __half* qkvf   = (__half*)(base + OFF_QKV);
    float* outbuf  = (float*)(base + OFF_OUTB);
    __half* m1     = (__half*)(base + OFF_M1);
    __half* WqkvT  = (__half*)(base + OFF_WQKV);
    __half* W1T    = (__half*)(base + OFF_W1);
    __half* W2T    = (__half*)(base + OFF_W2);

    cudaFuncSetAttribute(gemm_fp16_1p, cudaFuncAttributeMaxDynamicSharedMemorySize,
                         GSM1_BYTES);
    cudaFuncSetAttribute(attn_mma, cudaFuncAttributeMaxDynamicSharedMemorySize,
                         ATTN_SMEM);

    // Launch order keeps index 3 == gemm_fp16_1p (fused QKV) for ncu capture.
    // 0: Wq|Wk|Wv prep into fused [3072,1024]
    t16_tri_kernel<<<dim3(EE / 32, EE / 32, 3), 256>>>(Wq, Wk, Wv, WqkvT, EE, EE);
    // 1: LN1 -> fp16 (warp-per-row)
    ln16w_kernel<<<MM / 8, 256>>>(inputs, g1, beta1, nf);
    // 2: W1 prep
    t16_kernel<<<dim3(FF / 32, EE / 32), 256>>>(W1, W1T, EE, FF);
    // 3: fused QKV projection, N=3072, Q scaled by QSCALE (profiled)
    gemm_fp16_1p<<<dim3(QKVS / 128, MM / 128), 256, GSM1_BYTES>>>(
        nf, WqkvT, bq, bk, bv, nullptr, nullptr, qkvf, MM, QKVS, EE, 0, QSCALE);
    // 4: W2 prep
    t16_kernel<<<dim3(EE / 32, FF / 32), 256>>>(W2, W2T, FF, EE);
    // 5: fp16 causal attention + residual (exp2 softmax, 2 CTA/SM)
    attn_mma<<<dim3(CC / 128, HH, BB), 256, ATTN_SMEM>>>(qkvf, inputs, outbuf);
    // 6: LN2 -> fp16
    ln16w_kernel<<<MM / 8, 256>>>(outbuf, g2, beta2, hf);
    // 7: MLP1 (relu) -> fp16
    gemm_fp16_1p<<<dim3(FF / 128, MM / 128), 256, GSM1_BYTES>>>(
        hf, W1T, bm1, nullptr, nullptr, nullptr, nullptr, m1, MM, FF, EE, 1, 1.0f);
    // 8: MLP2 + residual -> out
    gemm_fp16_1p<<<dim3(EE / 128, MM / 128), 256, GSM1_BYTES>>>(
        m1, W2T, bm2, nullptr, nullptr, outbuf, out, nullptr, MM, EE, FF, 0, 1.0f);
}